// round 2
// baseline (speedup 1.0000x reference)
#include <cuda_runtime.h>
#include <cstdint>

#define D 128
#define NPAD 50048          // 391 * 128, padded node count
#define BM 128
#define BN 128

// ---------------- device scratch (static, no runtime alloc) ----------------
__device__ float g_S[(size_t)NPAD * 256];     // [n][0:128]=x, [128:256]=x2
__device__ float g_Agg[(size_t)NPAD * 256];   // [n][0:128]=Zx, [128:256]=Z2
__device__ float g_TgtX[(size_t)NPAD * D];
__device__ float g_TgtY[(size_t)NPAD * D];
__device__ float g_Hx[(size_t)NPAD * D];
__device__ float g_Hy[(size_t)NPAD * D];
__device__ float g_Wc[D * D];
__device__ float g_bc[D];
__device__ float g_colsum[2][D];
__device__ float g_colsq[2][D];
__device__ float g_bnScale[2][D];
__device__ float g_bnShift[2][D];
__device__ double g_lossSum;

// ---------------- helpers ----------------
__device__ __forceinline__ void red4(float4* p, float a, float b, float c, float d) {
    asm volatile("red.global.add.v4.f32 [%0], {%1,%2,%3,%4};"
                 :: "l"(p), "f"(a), "f"(b), "f"(c), "f"(d) : "memory");
}
__device__ __forceinline__ unsigned long long pack2(float lo, float hi) {
    unsigned long long r;
    asm("mov.b64 %0, {%1, %2};" : "=l"(r) : "f"(lo), "f"(hi));
    return r;
}
__device__ __forceinline__ void unpack2(unsigned long long v, float& lo, float& hi) {
    asm("mov.b64 {%0, %1}, %2;" : "=f"(lo), "=f"(hi) : "l"(v));
}
__device__ __forceinline__ unsigned long long fma2(unsigned long long a,
                                                   unsigned long long b,
                                                   unsigned long long c) {
    unsigned long long d;
    asm("fma.rn.f32x2 %0, %1, %2, %3;" : "=l"(d) : "l"(a), "l"(b), "l"(c));
    return d;
}

// ---------------- kernels ----------------
__global__ void k_zero() {
    int t = threadIdx.x;
    if (t < D) {
        g_colsum[0][t] = 0.f; g_colsum[1][t] = 0.f;
        g_colsq[0][t]  = 0.f; g_colsq[1][t]  = 0.f;
    }
    if (t == 0) g_lossSum = 0.0;
}

// x2 = x + perb ; build S = [x | x2] ; zero Agg
__global__ void k_prep(const float* __restrict__ x, const float* __restrict__ perb, int N) {
    int idx = blockIdx.x * 256 + threadIdx.x;   // float4 slot index
    if (idx >= NPAD * 64) return;
    int n = idx >> 6, k = idx & 63;
    float4 v = make_float4(0.f, 0.f, 0.f, 0.f);
    if (n < N) {
        if (k < 32) {
            v = ((const float4*)x)[(size_t)n * 32 + k];
        } else {
            float4 a = ((const float4*)x)[(size_t)n * 32 + (k - 32)];
            float4 p = ((const float4*)perb)[(size_t)n * 32 + (k - 32)];
            v = make_float4(a.x + p.x, a.y + p.y, a.z + p.z, a.w + p.w);
        }
    }
    ((float4*)g_S)[idx] = v;
    ((float4*)g_Agg)[idx] = make_float4(0.f, 0.f, 0.f, 0.f);
}

// Wc = W_on @ W1 ; bc = b_on @ W1 + b1
__global__ void k_combine(const float* __restrict__ Won, const float* __restrict__ bon,
                          const float* __restrict__ W1,  const float* __restrict__ b1) {
    __shared__ float row[D];
    int j = threadIdx.x;
    int i = blockIdx.x;
    if (i < D) {
        row[j] = Won[i * D + j];
        __syncthreads();
        float acc = 0.f;
        #pragma unroll 8
        for (int k = 0; k < D; k++) acc = fmaf(row[k], W1[k * D + j], acc);
        g_Wc[i * D + j] = acc;
    } else {
        row[j] = bon[j];
        __syncthreads();
        float acc = b1[j];
        #pragma unroll 8
        for (int k = 0; k < D; k++) acc = fmaf(row[k], W1[k * D + j], acc);
        g_bc[j] = acc;
    }
}

// sparse aggregation over edges: Agg[row] += w * S[col]  (256 floats per node)
__global__ void k_agg(const int* __restrict__ erow, const int* __restrict__ ecol,
                      const float* __restrict__ ew, int E) {
    int e = blockIdx.x * 8 + (threadIdx.x >> 5);
    if (e >= E) return;
    int lane = threadIdx.x & 31;
    int r = __ldg(erow + e);
    int c = __ldg(ecol + e);
    float w = __ldg(ew + e);
    const float4* src = (const float4*)g_S + (size_t)c * 64;
    float4* dst = (float4*)g_Agg + (size_t)r * 64;
    float4 v = src[lane];
    red4(dst + lane, w * v.x, w * v.y, w * v.z, w * v.w);
    float4 u = src[lane + 32];
    red4(dst + lane + 32, w * u.x, w * u.y, w * u.z, w * u.w);
}

// fused stage-1 GEMM: 5 groups over (Zx, Z2) x (W_tg, Wc, W_on)
// g0: TgtY = Zx@Wtg+btg   g1: Hx = Zx@Wc+bc (stats 0)
// g2: embed = x2 + Z2@Won+bon -> d_out
// g3: TgtX = Z2@Wtg+btg   g4: Hy = Z2@Wc+bc (stats 1)
__global__ __launch_bounds__(256) void k_gemm1(
    const float* __restrict__ Won, const float* __restrict__ bon,
    const float* __restrict__ Wtg, const float* __restrict__ btg,
    float* __restrict__ dout, int N)
{
    extern __shared__ float sm[];
    float* As = sm;              // [128][128]
    float* Bs = sm + BM * D;     // [128][128]
    int g = blockIdx.y;
    int row0 = blockIdx.x * BM;
    int aoff4 = (g <= 1) ? 0 : 32;   // Zx vs Z2 (float4 offset within 64-f4 row)
    const float* B; const float* bias; float* out; int mode; int sidx = 0;
    switch (g) {
        case 0:  B = Wtg;  bias = btg;  out = g_TgtY; mode = 0; break;
        case 1:  B = g_Wc; bias = g_bc; out = g_Hx;   mode = 1; sidx = 0; break;
        case 2:  B = Won;  bias = bon;  out = dout;   mode = 2; break;
        case 3:  B = Wtg;  bias = btg;  out = g_TgtX; mode = 0; break;
        default: B = g_Wc; bias = g_bc; out = g_Hy;   mode = 1; sidx = 1; break;
    }
    int tid = threadIdx.x;
    const float4* A4 = (const float4*)g_Agg;
    #pragma unroll
    for (int i = 0; i < 16; i++) {
        int idx = tid + i * 256;
        int m = idx >> 5, kq = idx & 31;
        ((float4*)As)[idx] = A4[(size_t)(row0 + m) * 64 + aoff4 + kq];
    }
    const float4* B4 = (const float4*)B;
    #pragma unroll
    for (int i = 0; i < 16; i++) {
        ((float4*)Bs)[tid + i * 256] = B4[tid + i * 256];
    }
    __syncthreads();

    int cg = tid & 15, rg = tid >> 4;        // 16 col-groups x 16 row-groups
    const float* Arow = As + rg * 8 * D;     // this thread's 8 rows
    unsigned long long acc[8][4];
    #pragma unroll
    for (int r = 0; r < 8; r++)
        #pragma unroll
        for (int c = 0; c < 4; c++) acc[r][c] = 0ull;

    #pragma unroll 8
    for (int k = 0; k < D; k++) {
        const unsigned long long* bsp = (const unsigned long long*)(Bs + k * D + cg * 8);
        unsigned long long bp0 = bsp[0], bp1 = bsp[1], bp2 = bsp[2], bp3 = bsp[3];
        #pragma unroll
        for (int r = 0; r < 8; r++) {
            float av = Arow[r * D + k];
            unsigned long long ap = pack2(av, av);
            acc[r][0] = fma2(ap, bp0, acc[r][0]);
            acc[r][1] = fma2(ap, bp1, acc[r][1]);
            acc[r][2] = fma2(ap, bp2, acc[r][2]);
            acc[r][3] = fma2(ap, bp3, acc[r][3]);
        }
    }

    float bias8[8];
    #pragma unroll
    for (int i = 0; i < 8; i++) bias8[i] = bias[cg * 8 + i];

    float lsum[8], lsq[8];
    #pragma unroll
    for (int i = 0; i < 8; i++) { lsum[i] = 0.f; lsq[i] = 0.f; }

    #pragma unroll
    for (int r = 0; r < 8; r++) {
        int n = row0 + rg * 8 + r;
        float v[8];
        #pragma unroll
        for (int c = 0; c < 4; c++) unpack2(acc[r][c], v[2 * c], v[2 * c + 1]);
        #pragma unroll
        for (int i = 0; i < 8; i++) v[i] += bias8[i];
        if (mode == 2) {
            if (n < N) {
                const float4* s2 = (const float4*)g_S + (size_t)n * 64 + 32 + cg * 2;
                float4 a0 = s2[0], a1 = s2[1];
                v[0] += a0.x; v[1] += a0.y; v[2] += a0.z; v[3] += a0.w;
                v[4] += a1.x; v[5] += a1.y; v[6] += a1.z; v[7] += a1.w;
                float4* o = (float4*)(dout + (size_t)n * D + cg * 8);
                o[0] = make_float4(v[0], v[1], v[2], v[3]);
                o[1] = make_float4(v[4], v[5], v[6], v[7]);
            }
        } else {
            float4* o = (float4*)(out + (size_t)n * D + cg * 8);
            o[0] = make_float4(v[0], v[1], v[2], v[3]);
            o[1] = make_float4(v[4], v[5], v[6], v[7]);
            if (mode == 1 && n < N) {
                #pragma unroll
                for (int i = 0; i < 8; i++) { lsum[i] += v[i]; lsq[i] += v[i] * v[i]; }
            }
        }
    }
    if (mode == 1) {
        #pragma unroll
        for (int i = 0; i < 8; i++) {
            atomicAdd(&g_colsum[sidx][cg * 8 + i], lsum[i]);
            atomicAdd(&g_colsq[sidx][cg * 8 + i], lsq[i]);
        }
    }
}

__global__ void k_stats(const float* __restrict__ bng, const float* __restrict__ bnb, int N) {
    int t = threadIdx.x;           // 256 threads: 2 sets x 128 cols
    int s = t >> 7, c = t & 127;
    float inv = 1.f / (float)N;
    float mu  = g_colsum[s][c] * inv;
    float var = g_colsq[s][c] * inv - mu * mu;
    float istd = rsqrtf(var + 1e-5f);
    float sc = bng[c] * istd;
    g_bnScale[s][c] = sc;
    g_bnShift[s][c] = bnb[c] - mu * sc;
}

// stage-2: p = PReLU(BN(H)) @ W2 + b2 ; loss += 2 - 2*cos(p, Tgt)
__global__ __launch_bounds__(256) void k_pred(
    const float* __restrict__ W2, const float* __restrict__ b2,
    const float* __restrict__ prelu_a, int N)
{
    extern __shared__ float sm[];
    float* As = sm;
    float* Bs = sm + BM * D;
    int tag = blockIdx.y;
    const float* H = tag ? g_Hy : g_Hx;
    const float* T = tag ? g_TgtY : g_TgtX;
    float slope = prelu_a[0];
    int row0 = blockIdx.x * BM;
    int tid = threadIdx.x;

    #pragma unroll
    for (int i = 0; i < 16; i++) {
        int idx = tid + i * 256;
        int m = idx >> 5, kq = idx & 31;
        float4 h  = ((const float4*)H)[(size_t)(row0 + m) * 32 + kq];
        float4 sc = ((const float4*)g_bnScale[tag])[kq];
        float4 sh = ((const float4*)g_bnShift[tag])[kq];
        h.x = fmaf(h.x, sc.x, sh.x); h.y = fmaf(h.y, sc.y, sh.y);
        h.z = fmaf(h.z, sc.z, sh.z); h.w = fmaf(h.w, sc.w, sh.w);
        h.x = h.x > 0.f ? h.x : slope * h.x;
        h.y = h.y > 0.f ? h.y : slope * h.y;
        h.z = h.z > 0.f ? h.z : slope * h.z;
        h.w = h.w > 0.f ? h.w : slope * h.w;
        ((float4*)As)[idx] = h;
    }
    const float4* B4 = (const float4*)W2;
    #pragma unroll
    for (int i = 0; i < 16; i++) ((float4*)Bs)[tid + i * 256] = B4[tid + i * 256];
    __syncthreads();

    int cg = tid & 15, rg = tid >> 4;
    const float* Arow = As + rg * 8 * D;
    unsigned long long acc[8][4];
    #pragma unroll
    for (int r = 0; r < 8; r++)
        #pragma unroll
        for (int c = 0; c < 4; c++) acc[r][c] = 0ull;

    #pragma unroll 8
    for (int k = 0; k < D; k++) {
        const unsigned long long* bsp = (const unsigned long long*)(Bs + k * D + cg * 8);
        unsigned long long bp0 = bsp[0], bp1 = bsp[1], bp2 = bsp[2], bp3 = bsp[3];
        #pragma unroll
        for (int r = 0; r < 8; r++) {
            float av = Arow[r * D + k];
            unsigned long long ap = pack2(av, av);
            acc[r][0] = fma2(ap, bp0, acc[r][0]);
            acc[r][1] = fma2(ap, bp1, acc[r][1]);
            acc[r][2] = fma2(ap, bp2, acc[r][2]);
            acc[r][3] = fma2(ap, bp3, acc[r][3]);
        }
    }

    float bias8[8];
    #pragma unroll
    for (int i = 0; i < 8; i++) bias8[i] = b2[cg * 8 + i];

    float lacc = 0.f;
    #pragma unroll
    for (int r = 0; r < 8; r++) {
        int n = row0 + rg * 8 + r;
        float v[8];
        #pragma unroll
        for (int c = 0; c < 4; c++) unpack2(acc[r][c], v[2 * c], v[2 * c + 1]);
        #pragma unroll
        for (int i = 0; i < 8; i++) v[i] += bias8[i];

        float4 t0 = ((const float4*)T)[(size_t)n * 32 + cg * 2];
        float4 t1 = ((const float4*)T)[(size_t)n * 32 + cg * 2 + 1];
        float tv[8] = {t0.x, t0.y, t0.z, t0.w, t1.x, t1.y, t1.z, t1.w};

        float psq = 0.f, dot = 0.f, tsq = 0.f;
        #pragma unroll
        for (int i = 0; i < 8; i++) {
            psq = fmaf(v[i], v[i], psq);
            dot = fmaf(v[i], tv[i], dot);
            tsq = fmaf(tv[i], tv[i], tsq);
        }
        // half-warp (16-lane) reduction — cg is the low 4 bits of the lane
        #pragma unroll
        for (int o = 1; o < 16; o <<= 1) {
            psq += __shfl_xor_sync(0xffffffffu, psq, o);
            dot += __shfl_xor_sync(0xffffffffu, dot, o);
            tsq += __shfl_xor_sync(0xffffffffu, tsq, o);
        }
        if (cg == 0 && n < N) {
            float np = sqrtf(psq), nt = sqrtf(tsq);
            float denom = fmaxf(np, 1e-12f) * fmaxf(nt, 1e-12f);
            lacc += 2.f - 2.f * dot / denom;
        }
    }
    if (cg == 0) atomicAdd(&g_lossSum, (double)lacc);
}

__global__ void k_final(float* __restrict__ dout, int N) {
    dout[(size_t)N * D] = (float)(g_lossSum / (double)N);
}

// ---------------- launch ----------------
extern "C" void kernel_launch(void* const* d_in, const int* in_sizes, int n_in,
                              void* d_out, int out_size) {
    const float* x    = (const float*)d_in[0];
    const float* perb = (const float*)d_in[1];
    const int*   erow = (const int*)d_in[2];
    const int*   ecol = (const int*)d_in[3];
    const float* ew   = (const float*)d_in[4];
    const float* Won  = (const float*)d_in[5];
    const float* bon  = (const float*)d_in[6];
    const float* Wtg  = (const float*)d_in[7];
    const float* btg  = (const float*)d_in[8];
    const float* W1   = (const float*)d_in[9];
    const float* b1   = (const float*)d_in[10];
    const float* bng  = (const float*)d_in[11];
    const float* bnb  = (const float*)d_in[12];
    const float* pa   = (const float*)d_in[13];
    const float* W2   = (const float*)d_in[14];
    const float* b2   = (const float*)d_in[15];
    float* out = (float*)d_out;

    int N = in_sizes[0] / D;
    int E = in_sizes[2];
    if (N > NPAD) N = NPAD;

    cudaFuncSetAttribute(k_gemm1, cudaFuncAttributeMaxDynamicSharedMemorySize, 2 * BM * D * 4);
    cudaFuncSetAttribute(k_pred,  cudaFuncAttributeMaxDynamicSharedMemorySize, 2 * BM * D * 4);

    k_zero<<<1, 256>>>();
    k_prep<<<(NPAD * 64 + 255) / 256, 256>>>(x, perb, N);
    k_combine<<<D + 1, D>>>(Won, bon, W1, b1);
    k_agg<<<(E + 7) / 8, 256>>>(erow, ecol, ew, E);
    dim3 g1(NPAD / BM, 5);
    k_gemm1<<<g1, 256, 2 * BM * D * 4>>>(Won, bon, Wtg, btg, out, N);
    k_stats<<<1, 256>>>(bng, bnb, N);
    dim3 g2(NPAD / BM, 2);
    k_pred<<<g2, 256, 2 * BM * D * 4>>>(W2, b2, pa, N);
    k_final<<<1, 1>>>(out, N);
}

// round 4
// speedup vs baseline: 1.9529x; 1.9529x over previous
#include <cuda_runtime.h>
#include <cuda_bf16.h>
#include <cstdint>

#define D 128
#define NPAD 50048          // 391 * 128
#define NBLK 391
#define PA 68               // packed (bf16x2) row pitch in u32: 64 data + 4 pad

// ---------------- device scratch ----------------
__device__ float g_S[(size_t)NPAD * 256];     // [n][0:128]=x, [128:256]=x2
__device__ float g_Agg[(size_t)NPAD * 256];   // [n][0:128]=Zx, [128:256]=Z2
__device__ float g_TgtX[(size_t)NPAD * D];
__device__ float g_TgtY[(size_t)NPAD * D];
__device__ float g_Hx[(size_t)NPAD * D];
__device__ float g_Hy[(size_t)NPAD * D];
__device__ float g_Wc[D * D];
__device__ float g_bc[D];
__device__ __align__(16) uint32_t g_Bh[4][D * PA];  // Wtg, Wc, Won, W2 (hi, transposed+packed)
__device__ __align__(16) uint32_t g_Bl[4][D * PA];  // lo residual
__device__ float g_colsum[2][D];
__device__ float g_colsq[2][D];
__device__ float g_bnScale[2][D];
__device__ float g_bnShift[2][D];
__device__ double g_lossSum;

// ---------------- helpers ----------------
__device__ __forceinline__ void red4(float4* p, float a, float b, float c, float d) {
    asm volatile("red.global.add.v4.f32 [%0], {%1,%2,%3,%4};"
                 :: "l"(p), "f"(a), "f"(b), "f"(c), "f"(d) : "memory");
}

// split fp32 pair -> packed bf16 hi pair + bf16 lo (residual) pair
__device__ __forceinline__ void bsplit(float x, float y, uint32_t& h, uint32_t& l) {
    __nv_bfloat162 hb = __floats2bfloat162_rn(x, y);
    float2 hf = __bfloat1622float2(hb);
    __nv_bfloat162 lb = __floats2bfloat162_rn(x - hf.x, y - hf.y);
    h = *reinterpret_cast<uint32_t*>(&hb);
    l = *reinterpret_cast<uint32_t*>(&lb);
}

// bf16 HMMA, fp32 accumulate (sm_80+ PTX; valid at compute_103)
#define MMA(cc, a, b) \
    asm("mma.sync.aligned.m16n8k16.row.col.f32.bf16.bf16.f32 " \
        "{%0,%1,%2,%3},{%4,%5,%6,%7},{%8,%9},{%0,%1,%2,%3};" \
        : "+f"((cc)[0]), "+f"((cc)[1]), "+f"((cc)[2]), "+f"((cc)[3]) \
        : "r"((a)[0]), "r"((a)[1]), "r"((a)[2]), "r"((a)[3]), \
          "r"((b)[0]), "r"((b)[1]))

// smem layout (u32 offsets)
#define SM_AH 0
#define SM_AL (D * PA)
#define SM_BH (2 * D * PA)
#define SM_BL (3 * D * PA)
#define SM_BIAS (4 * D * PA)
#define SM_RED (SM_BIAS + 128)
#define DYN_SMEM ((SM_RED + 3 * 128) * 4)

// ---------------- small kernels ----------------
__global__ void k_zero() {
    int t = threadIdx.x;
    if (t < D) {
        g_colsum[0][t] = 0.f; g_colsum[1][t] = 0.f;
        g_colsq[0][t]  = 0.f; g_colsq[1][t]  = 0.f;
    }
    if (t == 0) g_lossSum = 0.0;
}

__global__ void k_prep(const float* __restrict__ x, const float* __restrict__ perb, int N) {
    int idx = blockIdx.x * 256 + threadIdx.x;
    if (idx >= NPAD * 64) return;
    int n = idx >> 6, k = idx & 63;
    float4 v = make_float4(0.f, 0.f, 0.f, 0.f);
    if (n < N) {
        if (k < 32) {
            v = ((const float4*)x)[(size_t)n * 32 + k];
        } else {
            float4 a = ((const float4*)x)[(size_t)n * 32 + (k - 32)];
            float4 p = ((const float4*)perb)[(size_t)n * 32 + (k - 32)];
            v = make_float4(a.x + p.x, a.y + p.y, a.z + p.z, a.w + p.w);
        }
    }
    ((float4*)g_S)[idx] = v;
    ((float4*)g_Agg)[idx] = make_float4(0.f, 0.f, 0.f, 0.f);
}

__global__ void k_combine(const float* __restrict__ Won, const float* __restrict__ bon,
                          const float* __restrict__ W1,  const float* __restrict__ b1) {
    __shared__ float row[D];
    int j = threadIdx.x;
    int i = blockIdx.x;
    if (i < D) {
        row[j] = Won[i * D + j];
        __syncthreads();
        float acc = 0.f;
        #pragma unroll 8
        for (int k = 0; k < D; k++) acc = fmaf(row[k], W1[k * D + j], acc);
        g_Wc[i * D + j] = acc;
    } else {
        row[j] = bon[j];
        __syncthreads();
        float acc = b1[j];
        #pragma unroll 8
        for (int k = 0; k < D; k++) acc = fmaf(row[k], W1[k * D + j], acc);
        g_bc[j] = acc;
    }
}

// weight -> transposed Bt[n][k], bf16 hi/lo, packed pairs, pitch PA
__global__ void k_wprep(const float* __restrict__ Wtg, const float* __restrict__ Won,
                        const float* __restrict__ W2) {
    int w = blockIdx.x;
    const float* W = (w == 0) ? Wtg : (w == 1) ? g_Wc : (w == 2) ? Won : W2;
    int t = threadIdx.x;
    int n = t >> 1, half = t & 1;
    #pragma unroll
    for (int j = 0; j < 32; j++) {
        int k = half * 64 + 2 * j;
        float v0 = W[(size_t)k * D + n];
        float v1 = W[(size_t)(k + 1) * D + n];
        uint32_t h, l;
        bsplit(v0, v1, h, l);
        g_Bh[w][n * PA + half * 32 + j] = h;
        g_Bl[w][n * PA + half * 32 + j] = l;
    }
}

__global__ void k_agg(const int* __restrict__ erow, const int* __restrict__ ecol,
                      const float* __restrict__ ew, int E) {
    int e = blockIdx.x * 8 + (threadIdx.x >> 5);
    if (e >= E) return;
    int lane = threadIdx.x & 31;
    int r = __ldg(erow + e);
    int c = __ldg(ecol + e);
    float w = __ldg(ew + e);
    const float4* src = (const float4*)g_S + (size_t)c * 64;
    float4* dst = (float4*)g_Agg + (size_t)r * 64;
    float4 v = src[lane];
    red4(dst + lane, w * v.x, w * v.y, w * v.z, w * v.w);
    float4 u = src[lane + 32];
    red4(dst + lane + 32, w * u.x, w * u.y, w * u.z, w * u.w);
}

// ---------------- shared MMA core (computes c = A_tile @ B_tile) ----------------
// Warp grid: warpM = wid&1 (64 rows), warpN = wid>>1 (32 cols).
// Fragment mapping: g = lane>>2, tg = lane&3 (PTX m16n8k16 layout).
__device__ __forceinline__ void mma_core(const uint32_t* __restrict__ sm,
                                         int warpM, int warpN, int g, int tg,
                                         float c[4][4][4]) {
    const uint32_t* Ah = sm + SM_AH;
    const uint32_t* Al = sm + SM_AL;
    const uint32_t* Bh = sm + SM_BH;
    const uint32_t* Bl = sm + SM_BL;
    #pragma unroll
    for (int mf = 0; mf < 4; mf++)
        #pragma unroll
        for (int nf = 0; nf < 4; nf++)
            #pragma unroll
            for (int q = 0; q < 4; q++) c[mf][nf][q] = 0.f;

    #pragma unroll
    for (int ks = 0; ks < 8; ks++) {
        int ko = ks * 8 + tg;
        uint32_t ah[4][4], al[4][4], bh[4][2], bl[4][2];
        #pragma unroll
        for (int mf = 0; mf < 4; mf++) {
            int base = (warpM * 64 + mf * 16 + g) * PA + ko;
            ah[mf][0] = Ah[base];
            ah[mf][1] = Ah[base + 8 * PA];
            ah[mf][2] = Ah[base + 4];
            ah[mf][3] = Ah[base + 8 * PA + 4];
            al[mf][0] = Al[base];
            al[mf][1] = Al[base + 8 * PA];
            al[mf][2] = Al[base + 4];
            al[mf][3] = Al[base + 8 * PA + 4];
        }
        #pragma unroll
        for (int nf = 0; nf < 4; nf++) {
            int nb = (warpN * 32 + nf * 8 + g) * PA + ko;
            bh[nf][0] = Bh[nb];
            bh[nf][1] = Bh[nb + 4];
            bl[nf][0] = Bl[nb];
            bl[nf][1] = Bl[nb + 4];
        }
        #pragma unroll
        for (int mf = 0; mf < 4; mf++)
            #pragma unroll
            for (int nf = 0; nf < 4; nf++) MMA(c[mf][nf], ah[mf], bh[nf]);
        #pragma unroll
        for (int mf = 0; mf < 4; mf++)
            #pragma unroll
            for (int nf = 0; nf < 4; nf++) MMA(c[mf][nf], ah[mf], bl[nf]);
        #pragma unroll
        for (int mf = 0; mf < 4; mf++)
            #pragma unroll
            for (int nf = 0; nf < 4; nf++) MMA(c[mf][nf], al[mf], bh[nf]);
    }
}

// ---------------- stage-1: 5 fused GEMMs ----------------
// g0: TgtY=Zx@Wtg+btg  g1: Hx=Zx@Wc+bc (stats 0)  g2: embed=x2+Z2@Won+bon -> dout
// g3: TgtX=Z2@Wtg+btg  g4: Hy=Z2@Wc+bc (stats 1)
__global__ __launch_bounds__(256, 1) void k_gemm_s1(
    const float* __restrict__ bon, const float* __restrict__ btg,
    float* __restrict__ dout, int N)
{
    extern __shared__ uint32_t sm[];
    float* bias_s = (float*)(sm + SM_BIAS);

    int gq = blockIdx.y;
    int row0 = blockIdx.x * 128;
    int tid = threadIdx.x;
    int wid = tid >> 5, lane = tid & 31;
    int g = lane >> 2, tg = lane & 3;
    int warpM = wid & 1, warpN = wid >> 1;

    int widx, mode; const float* bias; float* out;
    switch (gq) {
        case 0:  widx = 0; bias = btg;  out = g_TgtY; mode = 0; break;
        case 1:  widx = 1; bias = g_bc; out = g_Hx;   mode = 1; break;
        case 2:  widx = 2; bias = bon;  out = dout;   mode = 2; break;
        case 3:  widx = 0; bias = btg;  out = g_TgtX; mode = 0; break;
        default: widx = 1; bias = g_bc; out = g_Hy;   mode = 1; break;
    }
    int sidx = (gq == 1) ? 0 : 1;
    int aoff = (gq <= 1) ? 0 : 128;

    // fill A (split fp32 -> bf16 hi/lo packed)
    {
        int m = tid >> 1, half = tid & 1;
        const float4* arow = (const float4*)(g_Agg + (size_t)(row0 + m) * 256 + aoff + half * 64);
        uint32_t* dH = sm + SM_AH + m * PA + half * 32;
        uint32_t* dL = sm + SM_AL + m * PA + half * 32;
        #pragma unroll
        for (int j = 0; j < 16; j++) {
            float4 a = arow[j];
            uint32_t h0, l0, h1, l1;
            bsplit(a.x, a.y, h0, l0);
            bsplit(a.z, a.w, h1, l1);
            dH[2 * j] = h0; dH[2 * j + 1] = h1;
            dL[2 * j] = l0; dL[2 * j + 1] = l1;
        }
    }
    // fill B (pre-split image copy)
    {
        const uint4* sH = (const uint4*)g_Bh[widx];
        const uint4* sL = (const uint4*)g_Bl[widx];
        uint4* dH = (uint4*)(sm + SM_BH);
        uint4* dL = (uint4*)(sm + SM_BL);
        for (int i = tid; i < D * PA / 4; i += 256) { dH[i] = sH[i]; dL[i] = sL[i]; }
    }
    if (tid < 128) bias_s[tid] = bias[tid];
    __syncthreads();

    float c[4][4][4];
    mma_core(sm, warpM, warpN, g, tg, c);

    // epilogue
    float ls[8], lq[8];
    #pragma unroll
    for (int i = 0; i < 8; i++) { ls[i] = 0.f; lq[i] = 0.f; }

    #pragma unroll
    for (int mf = 0; mf < 4; mf++) {
        #pragma unroll
        for (int part = 0; part < 2; part++) {
            int n = row0 + warpM * 64 + mf * 16 + g + part * 8;
            #pragma unroll
            for (int nf = 0; nf < 4; nf++) {
                int col = warpN * 32 + nf * 8 + 2 * tg;
                float v0 = c[mf][nf][part * 2]     + bias_s[col];
                float v1 = c[mf][nf][part * 2 + 1] + bias_s[col + 1];
                if (mode == 2) {
                    if (n < N) {
                        float2 s2 = *(const float2*)(g_S + (size_t)n * 256 + 128 + col);
                        *(float2*)(dout + (size_t)n * D + col) =
                            make_float2(v0 + s2.x, v1 + s2.y);
                    }
                } else {
                    *(float2*)(out + (size_t)n * D + col) = make_float2(v0, v1);
                    if (mode == 1 && n < N) {
                        ls[nf * 2]     += v0; lq[nf * 2]     += v0 * v0;
                        ls[nf * 2 + 1] += v1; lq[nf * 2 + 1] += v1 * v1;
                    }
                }
            }
        }
    }
    if (mode == 1) {
        #pragma unroll
        for (int i = 0; i < 8; i++) {
            #pragma unroll
            for (int off = 4; off < 32; off <<= 1) {
                ls[i] += __shfl_xor_sync(0xffffffffu, ls[i], off);
                lq[i] += __shfl_xor_sync(0xffffffffu, lq[i], off);
            }
        }
        if (g == 0) {
            #pragma unroll
            for (int nf = 0; nf < 4; nf++) {
                #pragma unroll
                for (int j = 0; j < 2; j++) {
                    int col = warpN * 32 + nf * 8 + 2 * tg + j;
                    atomicAdd(&g_colsum[sidx][col], ls[nf * 2 + j]);
                    atomicAdd(&g_colsq[sidx][col],  lq[nf * 2 + j]);
                }
            }
        }
    }
}

__global__ void k_stats(const float* __restrict__ bng, const float* __restrict__ bnb, int N) {
    int t = threadIdx.x;
    int s = t >> 7, c = t & 127;
    float inv = 1.f / (float)N;
    float mu  = g_colsum[s][c] * inv;
    float var = g_colsq[s][c] * inv - mu * mu;
    float istd = rsqrtf(var + 1e-5f);
    float sc = bng[c] * istd;
    g_bnScale[s][c] = sc;
    g_bnShift[s][c] = bnb[c] - mu * sc;
}

// ---------------- stage-2: predictor + cosine loss ----------------
__global__ __launch_bounds__(256, 1) void k_pred_s2(
    const float* __restrict__ b2, const float* __restrict__ prelu_a, int N)
{
    extern __shared__ uint32_t sm[];
    float* bias_s = (float*)(sm + SM_BIAS);
    float* sred   = (float*)(sm + SM_RED);   // psq[128], dot[128], tsq[128]

    int tag = blockIdx.y;
    int row0 = blockIdx.x * 128;
    int tid = threadIdx.x;
    int wid = tid >> 5, lane = tid & 31;
    int g = lane >> 2, tg = lane & 3;
    int warpM = wid & 1, warpN = wid >> 1;
    const float* H = tag ? g_Hy : g_Hx;
    const float* T = tag ? g_TgtY : g_TgtX;
    float slope = prelu_a[0];

    // fill A = PReLU(BN(H)) split
    {
        int m = tid >> 1, half = tid & 1;
        const float4* hrow = (const float4*)(H + (size_t)(row0 + m) * D + half * 64);
        const float4* scp = (const float4*)(g_bnScale[tag] + half * 64);
        const float4* shp = (const float4*)(g_bnShift[tag] + half * 64);
        uint32_t* dH = sm + SM_AH + m * PA + half * 32;
        uint32_t* dL = sm + SM_AL + m * PA + half * 32;
        #pragma unroll
        for (int j = 0; j < 16; j++) {
            float4 h  = hrow[j];
            float4 sc = scp[j];
            float4 sh = shp[j];
            float a0 = fmaf(h.x, sc.x, sh.x);
            float a1 = fmaf(h.y, sc.y, sh.y);
            float a2 = fmaf(h.z, sc.z, sh.z);
            float a3 = fmaf(h.w, sc.w, sh.w);
            a0 = a0 > 0.f ? a0 : slope * a0;
            a1 = a1 > 0.f ? a1 : slope * a1;
            a2 = a2 > 0.f ? a2 : slope * a2;
            a3 = a3 > 0.f ? a3 : slope * a3;
            uint32_t h0, l0, h1, l1;
            bsplit(a0, a1, h0, l0);
            bsplit(a2, a3, h1, l1);
            dH[2 * j] = h0; dH[2 * j + 1] = h1;
            dL[2 * j] = l0; dL[2 * j + 1] = l1;
        }
    }
    {
        const uint4* sH = (const uint4*)g_Bh[3];
        const uint4* sL = (const uint4*)g_Bl[3];
        uint4* dH = (uint4*)(sm + SM_BH);
        uint4* dL = (uint4*)(sm + SM_BL);
        for (int i = tid; i < D * PA / 4; i += 256) { dH[i] = sH[i]; dL[i] = sL[i]; }
    }
    if (tid < 128) {
        bias_s[tid] = b2[tid];
        sred[tid] = 0.f; sred[128 + tid] = 0.f; sred[256 + tid] = 0.f;
    }
    __syncthreads();

    float c[4][4][4];
    mma_core(sm, warpM, warpN, g, tg, c);

    #pragma unroll
    for (int mf = 0; mf < 4; mf++) {
        #pragma unroll
        for (int part = 0; part < 2; part++) {
            int r = warpM * 64 + mf * 16 + g + part * 8;
            int n = row0 + r;
            float psq = 0.f, dot = 0.f, tsq = 0.f;
            #pragma unroll
            for (int nf = 0; nf < 4; nf++) {
                int col = warpN * 32 + nf * 8 + 2 * tg;
                float v0 = c[mf][nf][part * 2]     + bias_s[col];
                float v1 = c[mf][nf][part * 2 + 1] + bias_s[col + 1];
                float2 t2 = *(const float2*)(T + (size_t)n * D + col);
                psq = fmaf(v0, v0, fmaf(v1, v1, psq));
                dot = fmaf(v0, t2.x, fmaf(v1, t2.y, dot));
                tsq = fmaf(t2.x, t2.x, fmaf(t2.y, t2.y, tsq));
            }
            atomicAdd(&sred[r], psq);
            atomicAdd(&sred[128 + r], dot);
            atomicAdd(&sred[256 + r], tsq);
        }
    }
    __syncthreads();

    if (tid < 128) {
        int n = row0 + tid;
        float lossv = 0.f;
        if (n < N) {
            float denom = fmaxf(sqrtf(sred[tid]), 1e-12f) *
                          fmaxf(sqrtf(sred[256 + tid]), 1e-12f);
            lossv = 2.f - 2.f * sred[128 + tid] / denom;
        }
        #pragma unroll
        for (int o = 16; o; o >>= 1) lossv += __shfl_xor_sync(0xffffffffu, lossv, o);
        if (lane == 0) atomicAdd(&g_lossSum, (double)lossv);
    }
}

__global__ void k_final(float* __restrict__ dout, int N) {
    dout[(size_t)N * D] = (float)(g_lossSum / (double)N);
}

// ---------------- launch ----------------
extern "C" void kernel_launch(void* const* d_in, const int* in_sizes, int n_in,
                              void* d_out, int out_size) {
    const float* x    = (const float*)d_in[0];
    const float* perb = (const float*)d_in[1];
    const int*   erow = (const int*)d_in[2];
    const int*   ecol = (const int*)d_in[3];
    const float* ew   = (const float*)d_in[4];
    const float* Won  = (const float*)d_in[5];
    const float* bon  = (const float*)d_in[6];
    const float* Wtg  = (const float*)d_in[7];
    const float* btg  = (const float*)d_in[8];
    const float* W1   = (const float*)d_in[9];
    const float* b1   = (const float*)d_in[10];
    const float* bng  = (const float*)d_in[11];
    const float* bnb  = (const float*)d_in[12];
    const float* pa   = (const float*)d_in[13];
    const float* W2   = (const float*)d_in[14];
    const float* b2   = (const float*)d_in[15];
    float* out = (float*)d_out;

    int N = in_sizes[0] / D;
    int E = in_sizes[2];
    if (N > NPAD) N = NPAD;

    cudaFuncSetAttribute(k_gemm_s1, cudaFuncAttributeMaxDynamicSharedMemorySize, DYN_SMEM);
    cudaFuncSetAttribute(k_pred_s2, cudaFuncAttributeMaxDynamicSharedMemorySize, DYN_SMEM);

    k_zero<<<1, 256>>>();
    k_prep<<<(NPAD * 64 + 255) / 256, 256>>>(x, perb, N);
    k_combine<<<D + 1, D>>>(Won, bon, W1, b1);
    k_wprep<<<4, 256>>>(Wtg, Won, W2);
    k_agg<<<(E + 7) / 8, 256>>>(erow, ecol, ew, E);
    dim3 g1(NBLK, 5);
    k_gemm_s1<<<g1, 256, DYN_SMEM>>>(bon, btg, out, N);
    k_stats<<<1, 256>>>(bng, bnb, N);
    dim3 g2(NBLK, 2);
    k_pred_s2<<<g2, 256, DYN_SMEM>>>(b2, pa, N);
    k_final<<<1, 1>>>(out, N);
}

// round 5
// speedup vs baseline: 2.0624x; 1.0561x over previous
#include <cuda_runtime.h>
#include <cuda_bf16.h>
#include <cstdint>

#define D 128
#define NPAD 50048          // 391 * 128
#define NBLK 391
#define PA 68               // packed (bf16x2) row pitch in u32: 64 data + 4 pad

// ---------------- device scratch ----------------
__device__ float g_S[(size_t)NPAD * 256];     // [n][0:128]=x, [128:256]=x2
__device__ float g_Agg[(size_t)NPAD * 256];   // [n][0:128]=Zx, [128:256]=Z2
__device__ float g_TgtX[(size_t)NPAD * D];
__device__ float g_TgtY[(size_t)NPAD * D];
__device__ float g_Hx[(size_t)NPAD * D];
__device__ float g_Hy[(size_t)NPAD * D];
__device__ float g_Wc[D * D];
__device__ float g_bc[D];
__device__ __align__(16) uint32_t g_Bh[4][D * PA];  // Wtg, Wc, Won, W2 (hi, transposed+packed)
__device__ __align__(16) uint32_t g_Bl[4][D * PA];  // lo residual
__device__ float g_colsum[2][D];
__device__ float g_colsq[2][D];
__device__ float g_bnScale[2][D];
__device__ float g_bnShift[2][D];
__device__ double g_lossSum;

// ---------------- helpers ----------------
__device__ __forceinline__ uint32_t smem_u32(const void* p) {
    uint32_t a;
    asm("{ .reg .u64 t; cvta.to.shared.u64 t, %1; cvt.u32.u64 %0, t; }" : "=r"(a) : "l"(p));
    return a;
}
__device__ __forceinline__ void red4(float4* p, float a, float b, float c, float d) {
    asm volatile("red.global.add.v4.f32 [%0], {%1,%2,%3,%4};"
                 :: "l"(p), "f"(a), "f"(b), "f"(c), "f"(d) : "memory");
}

// split fp32 pair -> packed bf16 hi pair + bf16 lo (residual) pair
__device__ __forceinline__ void bsplit(float x, float y, uint32_t& h, uint32_t& l) {
    __nv_bfloat162 hb = __floats2bfloat162_rn(x, y);
    float2 hf = __bfloat1622float2(hb);
    __nv_bfloat162 lb = __floats2bfloat162_rn(x - hf.x, y - hf.y);
    h = *reinterpret_cast<uint32_t*>(&hb);
    l = *reinterpret_cast<uint32_t*>(&lb);
}

// bf16 HMMA, fp32 accumulate (sm_80+ PTX; valid at compute_103)
#define MMA(cc, a, b0v, b1v) \
    asm("mma.sync.aligned.m16n8k16.row.col.f32.bf16.bf16.f32 " \
        "{%0,%1,%2,%3},{%4,%5,%6,%7},{%8,%9},{%0,%1,%2,%3};" \
        : "+f"((cc)[0]), "+f"((cc)[1]), "+f"((cc)[2]), "+f"((cc)[3]) \
        : "r"((a)[0]), "r"((a)[1]), "r"((a)[2]), "r"((a)[3]), \
          "r"(b0v), "r"(b1v))

#define LDSM4(r, addr) \
    asm volatile("ldmatrix.sync.aligned.m8n8.x4.shared.b16 {%0,%1,%2,%3}, [%4];" \
        : "=r"((r)[0]), "=r"((r)[1]), "=r"((r)[2]), "=r"((r)[3]) : "r"(addr))

// smem layout (u32 offsets)
#define SM_AH 0
#define SM_AL (D * PA)
#define SM_BH (2 * D * PA)
#define SM_BL (3 * D * PA)
#define SM_BIAS (4 * D * PA)
#define SM_RED (SM_BIAS + 128)
#define DYN_SMEM ((SM_RED + 3 * 128) * 4)

// ---------------- small kernels ----------------
__global__ void k_prep(const float* __restrict__ x, const float* __restrict__ perb, int N) {
    int idx = blockIdx.x * 256 + threadIdx.x;
    if (idx >= NPAD * 64) return;
    int n = idx >> 6, k = idx & 63;
    float4 v = make_float4(0.f, 0.f, 0.f, 0.f);
    if (n < N) {
        if (k < 32) {
            v = ((const float4*)x)[(size_t)n * 32 + k];
        } else {
            float4 a = ((const float4*)x)[(size_t)n * 32 + (k - 32)];
            float4 p = ((const float4*)perb)[(size_t)n * 32 + (k - 32)];
            v = make_float4(a.x + p.x, a.y + p.y, a.z + p.z, a.w + p.w);
        }
    }
    ((float4*)g_S)[idx] = v;
    ((float4*)g_Agg)[idx] = make_float4(0.f, 0.f, 0.f, 0.f);
}

__global__ void k_combine(const float* __restrict__ Won, const float* __restrict__ bon,
                          const float* __restrict__ W1,  const float* __restrict__ b1) {
    __shared__ float row[D];
    int j = threadIdx.x;
    int i = blockIdx.x;
    if (i < D) {
        row[j] = Won[i * D + j];
        __syncthreads();
        float acc = 0.f;
        #pragma unroll 8
        for (int k = 0; k < D; k++) acc = fmaf(row[k], W1[k * D + j], acc);
        g_Wc[i * D + j] = acc;
    } else {
        row[j] = bon[j];
        __syncthreads();
        float acc = b1[j];
        #pragma unroll 8
        for (int k = 0; k < D; k++) acc = fmaf(row[k], W1[k * D + j], acc);
        g_bc[j] = acc;
    }
}

// weight -> transposed Bt[n][k], bf16 hi/lo, packed pairs, pitch PA (+ zero accumulators)
__global__ void k_wprep(const float* __restrict__ Wtg, const float* __restrict__ Won,
                        const float* __restrict__ W2) {
    int w = blockIdx.x;
    int t = threadIdx.x;
    if (w == 0) {
        if (t < 128) {
            g_colsum[0][t] = 0.f; g_colsum[1][t] = 0.f;
            g_colsq[0][t]  = 0.f; g_colsq[1][t]  = 0.f;
        }
        if (t == 0) g_lossSum = 0.0;
    }
    const float* W = (w == 0) ? Wtg : (w == 1) ? g_Wc : (w == 2) ? Won : W2;
    int n = t >> 1, half = t & 1;
    #pragma unroll
    for (int j = 0; j < 32; j++) {
        int k = half * 64 + 2 * j;
        float v0 = W[(size_t)k * D + n];
        float v1 = W[(size_t)(k + 1) * D + n];
        uint32_t h, l;
        bsplit(v0, v1, h, l);
        g_Bh[w][n * PA + half * 32 + j] = h;
        g_Bl[w][n * PA + half * 32 + j] = l;
    }
}

__global__ void k_agg(const int* __restrict__ erow, const int* __restrict__ ecol,
                      const float* __restrict__ ew, int E) {
    int e = blockIdx.x * 8 + (threadIdx.x >> 5);
    if (e >= E) return;
    int lane = threadIdx.x & 31;
    int r = __ldg(erow + e);
    int c = __ldg(ecol + e);
    float w = __ldg(ew + e);
    const float4* src = (const float4*)g_S + (size_t)c * 64;
    float4* dst = (float4*)g_Agg + (size_t)r * 64;
    float4 v = src[lane];
    red4(dst + lane, w * v.x, w * v.y, w * v.z, w * v.w);
    float4 u = src[lane + 32];
    red4(dst + lane + 32, w * u.x, w * u.y, w * u.z, w * u.w);
}

// ---------------- MMA core via ldmatrix ----------------
// Warp grid: warpM = wid&1 (64 rows), warpN = wid>>1 (32 cols).
__device__ __forceinline__ void mma_core(uint32_t sb, int wid, int lane, float c[4][4][4]) {
    int warpM = wid & 1, warpN = wid >> 1;
    #pragma unroll
    for (int mf = 0; mf < 4; mf++)
        #pragma unroll
        for (int nf = 0; nf < 4; nf++)
            #pragma unroll
            for (int q = 0; q < 4; q++) c[mf][nf][q] = 0.f;

    int arow = warpM * 64 + (lane & 15);
    uint32_t aA = sb + (uint32_t)(arow * PA + (lane >> 4) * 4) * 4;
    int brow = warpN * 32 + (lane & 7) + ((lane >> 4) & 1) * 8;
    uint32_t aB = sb + (uint32_t)(brow * PA + ((lane >> 3) & 1) * 4) * 4
                + (uint32_t)SM_BH * 4;

    #pragma unroll
    for (int ks = 0; ks < 8; ks++) {
        uint32_t ah[4][4], al[4][4], bh[2][4], bl[2][4];
        #pragma unroll
        for (int mf = 0; mf < 4; mf++) {
            uint32_t ad = aA + (uint32_t)(mf * 16 * PA) * 4 + ks * 32;
            LDSM4(ah[mf], ad);
            LDSM4(al[mf], ad + (uint32_t)SM_AL * 4);
        }
        #pragma unroll
        for (int p = 0; p < 2; p++) {
            uint32_t bd = aB + (uint32_t)(p * 16 * PA) * 4 + ks * 32;
            LDSM4(bh[p], bd);
            LDSM4(bl[p], bd + (uint32_t)(SM_BL - SM_BH) * 4);
        }
        #pragma unroll
        for (int mf = 0; mf < 4; mf++)
            #pragma unroll
            for (int p = 0; p < 2; p++) {
                MMA(c[mf][p * 2 + 0], ah[mf], bh[p][0], bh[p][1]);
                MMA(c[mf][p * 2 + 1], ah[mf], bh[p][2], bh[p][3]);
            }
        #pragma unroll
        for (int mf = 0; mf < 4; mf++)
            #pragma unroll
            for (int p = 0; p < 2; p++) {
                MMA(c[mf][p * 2 + 0], ah[mf], bl[p][0], bl[p][1]);
                MMA(c[mf][p * 2 + 1], ah[mf], bl[p][2], bl[p][3]);
                MMA(c[mf][p * 2 + 0], al[mf], bh[p][0], bh[p][1]);
                MMA(c[mf][p * 2 + 1], al[mf], bh[p][2], bh[p][3]);
            }
    }
}

// ---------------- stage-1: A-reused fused GEMMs ----------------
// gy=0: A=Zx -> s0: TgtY=Zx@Wtg+btg, s1: Hx=Zx@Wc+bc (stats 0)
// gy=1: A=Z2 -> s0: TgtX=Z2@Wtg+btg, s1: Hy=Z2@Wc+bc (stats 1), s2: embed=x2+Z2@Won+bon
__global__ __launch_bounds__(256, 1) void k_gemm_s1(
    const float* __restrict__ bon, const float* __restrict__ btg,
    float* __restrict__ dout, int N)
{
    extern __shared__ uint32_t sm[];
    float* bias_s = (float*)(sm + SM_BIAS);
    uint32_t sb = smem_u32(sm);

    int gy = blockIdx.y;
    int row0 = blockIdx.x * 128;
    int tid = threadIdx.x;
    int wid = tid >> 5, lane = tid & 31;
    int g = lane >> 2, tg = lane & 3;
    int warpM = wid & 1, warpN = wid >> 1;
    int aoff = gy ? 128 : 0;

    // fill A (split fp32 -> bf16 hi/lo packed), once per CTA
    {
        int m = tid >> 1, half = tid & 1;
        const float4* arow = (const float4*)(g_Agg + (size_t)(row0 + m) * 256 + aoff + half * 64);
        uint32_t* dH = sm + SM_AH + m * PA + half * 32;
        uint32_t* dL = sm + SM_AL + m * PA + half * 32;
        #pragma unroll
        for (int j = 0; j < 16; j++) {
            float4 a = arow[j];
            uint32_t h0, l0, h1, l1;
            bsplit(a.x, a.y, h0, l0);
            bsplit(a.z, a.w, h1, l1);
            dH[2 * j] = h0; dH[2 * j + 1] = h1;
            dL[2 * j] = l0; dL[2 * j + 1] = l1;
        }
    }

    int nsub = gy ? 3 : 2;
    for (int s = 0; s < nsub; s++) {
        int widx, mode, sidx = 0;
        const float* bias;
        float* out;
        if (s == 0)      { widx = 0; bias = btg;  out = gy ? g_TgtX : g_TgtY; mode = 0; }
        else if (s == 1) { widx = 1; bias = g_bc; out = gy ? g_Hy   : g_Hx;   mode = 1; sidx = gy; }
        else             { widx = 2; bias = bon;  out = dout;                 mode = 2; }

        __syncthreads();   // previous sub done reading B
        {
            const uint4* sH = (const uint4*)g_Bh[widx];
            const uint4* sL = (const uint4*)g_Bl[widx];
            uint4* dH = (uint4*)(sm + SM_BH);
            uint4* dL = (uint4*)(sm + SM_BL);
            for (int i = tid; i < D * PA / 4; i += 256) { dH[i] = sH[i]; dL[i] = sL[i]; }
        }
        if (tid < 128) bias_s[tid] = bias[tid];
        __syncthreads();

        float c[4][4][4];
        mma_core(sb, wid, lane, c);

        // epilogue
        float ls[8], lq[8];
        #pragma unroll
        for (int i = 0; i < 8; i++) { ls[i] = 0.f; lq[i] = 0.f; }

        #pragma unroll
        for (int mf = 0; mf < 4; mf++) {
            #pragma unroll
            for (int part = 0; part < 2; part++) {
                int n = row0 + warpM * 64 + mf * 16 + g + part * 8;
                #pragma unroll
                for (int nf = 0; nf < 4; nf++) {
                    int col = warpN * 32 + nf * 8 + 2 * tg;
                    float v0 = c[mf][nf][part * 2]     + bias_s[col];
                    float v1 = c[mf][nf][part * 2 + 1] + bias_s[col + 1];
                    if (mode == 2) {
                        if (n < N) {
                            float2 s2 = *(const float2*)(g_S + (size_t)n * 256 + 128 + col);
                            *(float2*)(dout + (size_t)n * D + col) =
                                make_float2(v0 + s2.x, v1 + s2.y);
                        }
                    } else {
                        *(float2*)(out + (size_t)n * D + col) = make_float2(v0, v1);
                        if (mode == 1 && n < N) {
                            ls[nf * 2]     += v0; lq[nf * 2]     += v0 * v0;
                            ls[nf * 2 + 1] += v1; lq[nf * 2 + 1] += v1 * v1;
                        }
                    }
                }
            }
        }
        if (mode == 1) {
            #pragma unroll
            for (int i = 0; i < 8; i++) {
                #pragma unroll
                for (int off = 4; off < 32; off <<= 1) {
                    ls[i] += __shfl_xor_sync(0xffffffffu, ls[i], off);
                    lq[i] += __shfl_xor_sync(0xffffffffu, lq[i], off);
                }
            }
            if (g == 0) {
                #pragma unroll
                for (int nf = 0; nf < 4; nf++) {
                    #pragma unroll
                    for (int j = 0; j < 2; j++) {
                        int col = warpN * 32 + nf * 8 + 2 * tg + j;
                        atomicAdd(&g_colsum[sidx][col], ls[nf * 2 + j]);
                        atomicAdd(&g_colsq[sidx][col],  lq[nf * 2 + j]);
                    }
                }
            }
        }
    }
}

__global__ void k_stats(const float* __restrict__ bng, const float* __restrict__ bnb, int N) {
    int t = threadIdx.x;
    int s = t >> 7, c = t & 127;
    float inv = 1.f / (float)N;
    float mu  = g_colsum[s][c] * inv;
    float var = g_colsq[s][c] * inv - mu * mu;
    float istd = rsqrtf(var + 1e-5f);
    float sc = bng[c] * istd;
    g_bnScale[s][c] = sc;
    g_bnShift[s][c] = bnb[c] - mu * sc;
}

// ---------------- stage-2: predictor + cosine loss ----------------
__global__ __launch_bounds__(256, 1) void k_pred_s2(
    const float* __restrict__ b2, const float* __restrict__ prelu_a, int N)
{
    extern __shared__ uint32_t sm[];
    float* bias_s = (float*)(sm + SM_BIAS);
    float* sred   = (float*)(sm + SM_RED);   // psq[128], dot[128], tsq[128]
    uint32_t sb = smem_u32(sm);

    int tag = blockIdx.y;
    int row0 = blockIdx.x * 128;
    int tid = threadIdx.x;
    int wid = tid >> 5, lane = tid & 31;
    int g = lane >> 2, tg = lane & 3;
    int warpM = wid & 1, warpN = wid >> 1;
    const float* H = tag ? g_Hy : g_Hx;
    const float* T = tag ? g_TgtY : g_TgtX;
    float slope = prelu_a[0];

    // fill A = PReLU(BN(H)) split
    {
        int m = tid >> 1, half = tid & 1;
        const float4* hrow = (const float4*)(H + (size_t)(row0 + m) * D + half * 64);
        const float4* scp = (const float4*)(g_bnScale[tag] + half * 64);
        const float4* shp = (const float4*)(g_bnShift[tag] + half * 64);
        uint32_t* dH = sm + SM_AH + m * PA + half * 32;
        uint32_t* dL = sm + SM_AL + m * PA + half * 32;
        #pragma unroll
        for (int j = 0; j < 16; j++) {
            float4 h  = hrow[j];
            float4 sc = scp[j];
            float4 sh = shp[j];
            float a0 = fmaf(h.x, sc.x, sh.x);
            float a1 = fmaf(h.y, sc.y, sh.y);
            float a2 = fmaf(h.z, sc.z, sh.z);
            float a3 = fmaf(h.w, sc.w, sh.w);
            a0 = a0 > 0.f ? a0 : slope * a0;
            a1 = a1 > 0.f ? a1 : slope * a1;
            a2 = a2 > 0.f ? a2 : slope * a2;
            a3 = a3 > 0.f ? a3 : slope * a3;
            uint32_t h0, l0, h1, l1;
            bsplit(a0, a1, h0, l0);
            bsplit(a2, a3, h1, l1);
            dH[2 * j] = h0; dH[2 * j + 1] = h1;
            dL[2 * j] = l0; dL[2 * j + 1] = l1;
        }
    }
    {
        const uint4* sH = (const uint4*)g_Bh[3];
        const uint4* sL = (const uint4*)g_Bl[3];
        uint4* dH = (uint4*)(sm + SM_BH);
        uint4* dL = (uint4*)(sm + SM_BL);
        for (int i = tid; i < D * PA / 4; i += 256) { dH[i] = sH[i]; dL[i] = sL[i]; }
    }
    if (tid < 128) {
        bias_s[tid] = b2[tid];
        sred[tid] = 0.f; sred[128 + tid] = 0.f; sred[256 + tid] = 0.f;
    }
    __syncthreads();

    float c[4][4][4];
    mma_core(sb, wid, lane, c);

    #pragma unroll
    for (int mf = 0; mf < 4; mf++) {
        #pragma unroll
        for (int part = 0; part < 2; part++) {
            int r = warpM * 64 + mf * 16 + g + part * 8;
            int n = row0 + r;
            float psq = 0.f, dot = 0.f, tsq = 0.f;
            #pragma unroll
            for (int nf = 0; nf < 4; nf++) {
                int col = warpN * 32 + nf * 8 + 2 * tg;
                float v0 = c[mf][nf][part * 2]     + bias_s[col];
                float v1 = c[mf][nf][part * 2 + 1] + bias_s[col + 1];
                float2 t2 = *(const float2*)(T + (size_t)n * D + col);
                psq = fmaf(v0, v0, fmaf(v1, v1, psq));
                dot = fmaf(v0, t2.x, fmaf(v1, t2.y, dot));
                tsq = fmaf(t2.x, t2.x, fmaf(t2.y, t2.y, tsq));
            }
            atomicAdd(&sred[r], psq);
            atomicAdd(&sred[128 + r], dot);
            atomicAdd(&sred[256 + r], tsq);
        }
    }
    __syncthreads();

    if (tid < 128) {
        int n = row0 + tid;
        float lossv = 0.f;
        if (n < N) {
            float denom = fmaxf(sqrtf(sred[tid]), 1e-12f) *
                          fmaxf(sqrtf(sred[256 + tid]), 1e-12f);
            lossv = 2.f - 2.f * sred[128 + tid] / denom;
        }
        #pragma unroll
        for (int o = 16; o; o >>= 1) lossv += __shfl_xor_sync(0xffffffffu, lossv, o);
        if (lane == 0) atomicAdd(&g_lossSum, (double)lossv);
    }
}

__global__ void k_final(float* __restrict__ dout, int N) {
    dout[(size_t)N * D] = (float)(g_lossSum / (double)N);
}

// ---------------- launch ----------------
extern "C" void kernel_launch(void* const* d_in, const int* in_sizes, int n_in,
                              void* d_out, int out_size) {
    const float* x    = (const float*)d_in[0];
    const float* perb = (const float*)d_in[1];
    const int*   erow = (const int*)d_in[2];
    const int*   ecol = (const int*)d_in[3];
    const float* ew   = (const float*)d_in[4];
    const float* Won  = (const float*)d_in[5];
    const float* bon  = (const float*)d_in[6];
    const float* Wtg  = (const float*)d_in[7];
    const float* btg  = (const float*)d_in[8];
    const float* W1   = (const float*)d_in[9];
    const float* b1   = (const float*)d_in[10];
    const float* bng  = (const float*)d_in[11];
    const float* bnb  = (const float*)d_in[12];
    const float* pa   = (const float*)d_in[13];
    const float* W2   = (const float*)d_in[14];
    const float* b2   = (const float*)d_in[15];
    float* out = (float*)d_out;

    int N = in_sizes[0] / D;
    int E = in_sizes[2];
    if (N > NPAD) N = NPAD;

    cudaFuncSetAttribute(k_gemm_s1, cudaFuncAttributeMaxDynamicSharedMemorySize, DYN_SMEM);
    cudaFuncSetAttribute(k_pred_s2, cudaFuncAttributeMaxDynamicSharedMemorySize, DYN_SMEM);

    k_prep<<<(NPAD * 64 + 255) / 256, 256>>>(x, perb, N);
    k_combine<<<D + 1, D>>>(Won, bon, W1, b1);
    k_wprep<<<4, 256>>>(Wtg, Won, W2);
    k_agg<<<(E + 7) / 8, 256>>>(erow, ecol, ew, E);
    dim3 g1(NBLK, 2);
    k_gemm_s1<<<g1, 256, DYN_SMEM>>>(bon, btg, out, N);
    k_stats<<<1, 256>>>(bng, bnb, N);
    dim3 g2(NBLK, 2);
    k_pred_s2<<<g2, 256, DYN_SMEM>>>(b2, pa, N);
    k_final<<<1, 1>>>(out, N);
}

// round 6
// speedup vs baseline: 2.1532x; 1.0440x over previous
#include <cuda_runtime.h>
#include <cuda_bf16.h>
#include <cstdint>

#define D 128
#define NPAD 50048          // 391 * 128
#define NBLK 391
#define PA 68               // packed (bf16x2) row pitch in u32: 64 data + 4 pad
#define EMAX 1000000

// ---------------- device scratch ----------------
__device__ float g_S[(size_t)NPAD * 256];     // [n][0:128]=x, [128:256]=x2
__device__ float g_Agg[(size_t)NPAD * 256];   // [n][0:128]=Zx, [128:256]=Z2
__device__ float g_TgtX[(size_t)NPAD * D];
__device__ float g_TgtY[(size_t)NPAD * D];
__device__ float g_Hx[(size_t)NPAD * D];
__device__ float g_Hy[(size_t)NPAD * D];
__device__ float g_Wc[D * D];
__device__ float g_bc[D];
__device__ __align__(16) uint32_t g_Bh[4][D * PA];  // Wtg, Wc, Won, W2 (hi)
__device__ __align__(16) uint32_t g_Bl[4][D * PA];  // lo residual
__device__ float g_colsum[2][D];
__device__ float g_colsq[2][D];
__device__ float g_bnScale[2][D];
__device__ float g_bnShift[2][D];
__device__ double g_lossSum;
// CSR
__device__ int   g_off[NPAD + 1];
__device__ int   g_cur[NPAD];
__device__ int   g_ecol2[EMAX];
__device__ float g_ew2[EMAX];

// ---------------- helpers ----------------
__device__ __forceinline__ uint32_t smem_u32(const void* p) {
    uint32_t a;
    asm("{ .reg .u64 t; cvta.to.shared.u64 t, %1; cvt.u32.u64 %0, t; }" : "=r"(a) : "l"(p));
    return a;
}
__device__ __forceinline__ void cpa16(uint32_t s, const void* g) {
    asm volatile("cp.async.ca.shared.global [%0], [%1], 16;" :: "r"(s), "l"(g));
}
#define CP_WAIT() \
    asm volatile("cp.async.commit_group;\n\tcp.async.wait_group 0;" ::: "memory")

// split fp32 pair -> packed bf16 hi pair + bf16 lo (residual) pair
__device__ __forceinline__ void bsplit(float x, float y, uint32_t& h, uint32_t& l) {
    __nv_bfloat162 hb = __floats2bfloat162_rn(x, y);
    float2 hf = __bfloat1622float2(hb);
    __nv_bfloat162 lb = __floats2bfloat162_rn(x - hf.x, y - hf.y);
    h = *reinterpret_cast<uint32_t*>(&hb);
    l = *reinterpret_cast<uint32_t*>(&lb);
}

#define MMA(cc, a, b0v, b1v) \
    asm("mma.sync.aligned.m16n8k16.row.col.f32.bf16.bf16.f32 " \
        "{%0,%1,%2,%3},{%4,%5,%6,%7},{%8,%9},{%0,%1,%2,%3};" \
        : "+f"((cc)[0]), "+f"((cc)[1]), "+f"((cc)[2]), "+f"((cc)[3]) \
        : "r"((a)[0]), "r"((a)[1]), "r"((a)[2]), "r"((a)[3]), \
          "r"(b0v), "r"(b1v))

#define LDSM4(r, addr) \
    asm volatile("ldmatrix.sync.aligned.m8n8.x4.shared.b16 {%0,%1,%2,%3}, [%4];" \
        : "=r"((r)[0]), "=r"((r)[1]), "=r"((r)[2]), "=r"((r)[3]) : "r"(addr))

// smem layout (u32 offsets): Ah, Al, single B, bias, reduction
#define SM_AH 0
#define SM_AL (D * PA)
#define SM_B  (2 * D * PA)
#define SM_BIAS (3 * D * PA)
#define SM_RED (SM_BIAS + 128)
#define DYN_SMEM ((SM_RED + 3 * 128) * 4)   // 106496 B -> 2 CTAs/SM

// ---------------- small kernels ----------------
__global__ void k_prep(const float* __restrict__ x, const float* __restrict__ perb, int N) {
    int idx = blockIdx.x * 256 + threadIdx.x;
    if (idx >= NPAD * 64) return;
    if (idx < NPAD) g_cur[idx] = 0;
    int n = idx >> 6, k = idx & 63;
    float4 v = make_float4(0.f, 0.f, 0.f, 0.f);
    if (n < N) {
        if (k < 32) {
            v = ((const float4*)x)[(size_t)n * 32 + k];
        } else {
            float4 a = ((const float4*)x)[(size_t)n * 32 + (k - 32)];
            float4 p = ((const float4*)perb)[(size_t)n * 32 + (k - 32)];
            v = make_float4(a.x + p.x, a.y + p.y, a.z + p.z, a.w + p.w);
        }
    }
    ((float4*)g_S)[idx] = v;
}

__global__ void k_count(const int* __restrict__ erow, int E) {
    int e = blockIdx.x * 256 + threadIdx.x;
    if (e < E) atomicAdd(&g_cur[__ldg(erow + e)], 1);
}

// single-block exclusive scan over g_cur -> g_off, reset g_cur
__global__ void k_scan() {
    __shared__ int part[1024];
    const int CH = (NPAD + 1023) / 1024;   // 49
    int t = threadIdx.x;
    int base = t * CH;
    int s = 0;
    for (int i = 0; i < CH; i++) {
        int idx = base + i;
        if (idx < NPAD) s += g_cur[idx];
    }
    part[t] = s;
    __syncthreads();
    for (int off = 1; off < 1024; off <<= 1) {
        int u = (t >= off) ? part[t - off] : 0;
        __syncthreads();
        part[t] += u;
        __syncthreads();
    }
    int run = part[t] - s;   // exclusive start for this chunk
    for (int i = 0; i < CH; i++) {
        int idx = base + i;
        if (idx < NPAD) {
            g_off[idx] = run;
            run += g_cur[idx];
            g_cur[idx] = 0;
        }
    }
    if (t == 1023) g_off[NPAD] = part[1023];
}

__global__ void k_scatter(const int* __restrict__ erow, const int* __restrict__ ecol,
                          const float* __restrict__ ew, int E) {
    int e = blockIdx.x * 256 + threadIdx.x;
    if (e >= E) return;
    int r = __ldg(erow + e);
    int pos = g_off[r] + atomicAdd(&g_cur[r], 1);
    g_ecol2[pos] = __ldg(ecol + e);
    g_ew2[pos]   = __ldg(ew + e);
}

// CSR aggregation: one warp per node, register accumulation, single write
__global__ __launch_bounds__(256) void k_agg_csr() {
    int wid = threadIdx.x >> 5, lane = threadIdx.x & 31;
    int n = blockIdx.x * 8 + wid;
    int start = g_off[n];
    int deg = g_off[n + 1] - start;
    float4 a0 = make_float4(0.f, 0.f, 0.f, 0.f), a1 = a0;
    for (int base = 0; base < deg; base += 32) {
        int j = base + lane;
        int cc = 0; float ww = 0.f;
        if (j < deg) { cc = g_ecol2[start + j]; ww = g_ew2[start + j]; }
        int cnt = min(32, deg - base);
        for (int i = 0; i < cnt; i++) {
            int cs = __shfl_sync(0xffffffffu, cc, i);
            float ws = __shfl_sync(0xffffffffu, ww, i);
            const float4* src = (const float4*)g_S + (size_t)cs * 64 + lane * 2;
            float4 v = __ldg(src);
            float4 u = __ldg(src + 1);
            a0.x = fmaf(ws, v.x, a0.x); a0.y = fmaf(ws, v.y, a0.y);
            a0.z = fmaf(ws, v.z, a0.z); a0.w = fmaf(ws, v.w, a0.w);
            a1.x = fmaf(ws, u.x, a1.x); a1.y = fmaf(ws, u.y, a1.y);
            a1.z = fmaf(ws, u.z, a1.z); a1.w = fmaf(ws, u.w, a1.w);
        }
    }
    float4* dst = (float4*)g_Agg + (size_t)n * 64 + lane * 2;
    dst[0] = a0;
    dst[1] = a1;
}

__global__ void k_combine(const float* __restrict__ Won, const float* __restrict__ bon,
                          const float* __restrict__ W1,  const float* __restrict__ b1) {
    __shared__ float row[D];
    int j = threadIdx.x;
    int i = blockIdx.x;
    if (i < D) {
        row[j] = Won[i * D + j];
        __syncthreads();
        float acc = 0.f;
        #pragma unroll 8
        for (int k = 0; k < D; k++) acc = fmaf(row[k], W1[k * D + j], acc);
        g_Wc[i * D + j] = acc;
    } else {
        row[j] = bon[j];
        __syncthreads();
        float acc = b1[j];
        #pragma unroll 8
        for (int k = 0; k < D; k++) acc = fmaf(row[k], W1[k * D + j], acc);
        g_bc[j] = acc;
    }
}

__global__ void k_wprep(const float* __restrict__ Wtg, const float* __restrict__ Won,
                        const float* __restrict__ W2) {
    int w = blockIdx.x;
    int t = threadIdx.x;
    if (w == 0) {
        if (t < 128) {
            g_colsum[0][t] = 0.f; g_colsum[1][t] = 0.f;
            g_colsq[0][t]  = 0.f; g_colsq[1][t]  = 0.f;
        }
        if (t == 0) g_lossSum = 0.0;
    }
    const float* W = (w == 0) ? Wtg : (w == 1) ? g_Wc : (w == 2) ? Won : W2;
    int n = t >> 1, half = t & 1;
    #pragma unroll
    for (int j = 0; j < 32; j++) {
        int k = half * 64 + 2 * j;
        float v0 = W[(size_t)k * D + n];
        float v1 = W[(size_t)(k + 1) * D + n];
        uint32_t h, l;
        bsplit(v0, v1, h, l);
        g_Bh[w][n * PA + half * 32 + j] = h;
        g_Bl[w][n * PA + half * 32 + j] = l;
    }
}

// ---------------- MMA pass via ldmatrix (B tile shared between hi/lo passes) ----
__device__ __forceinline__ void mma_pass(uint32_t sb, int wid, int lane,
                                         float c[4][4][4], bool hipass) {
    int warpM = wid & 1, warpN = wid >> 1;
    int arow = warpM * 64 + (lane & 15);
    uint32_t aA = sb + (uint32_t)(arow * PA + (lane >> 4) * 4) * 4;
    int brow = warpN * 32 + (lane & 7) + ((lane >> 4) & 1) * 8;
    uint32_t aB = sb + (uint32_t)(brow * PA + ((lane >> 3) & 1) * 4) * 4
                + (uint32_t)SM_B * 4;

    #pragma unroll
    for (int ks = 0; ks < 8; ks++) {
        uint32_t ah[4][4], b[2][4];
        #pragma unroll
        for (int mf = 0; mf < 4; mf++)
            LDSM4(ah[mf], aA + (uint32_t)(mf * 16 * PA) * 4 + ks * 32);
        #pragma unroll
        for (int p = 0; p < 2; p++)
            LDSM4(b[p], aB + (uint32_t)(p * 16 * PA) * 4 + ks * 32);
        #pragma unroll
        for (int mf = 0; mf < 4; mf++)
            #pragma unroll
            for (int p = 0; p < 2; p++) {
                MMA(c[mf][p * 2 + 0], ah[mf], b[p][0], b[p][1]);
                MMA(c[mf][p * 2 + 1], ah[mf], b[p][2], b[p][3]);
            }
        if (hipass) {
            uint32_t al[4][4];
            #pragma unroll
            for (int mf = 0; mf < 4; mf++)
                LDSM4(al[mf], aA + (uint32_t)SM_AL * 4
                              + (uint32_t)(mf * 16 * PA) * 4 + ks * 32);
            #pragma unroll
            for (int mf = 0; mf < 4; mf++)
                #pragma unroll
                for (int p = 0; p < 2; p++) {
                    MMA(c[mf][p * 2 + 0], al[mf], b[p][0], b[p][1]);
                    MMA(c[mf][p * 2 + 1], al[mf], b[p][2], b[p][3]);
                }
        }
    }
}

// ---------------- stage-1: A-reused fused GEMMs (2 CTAs/SM) ----------------
__global__ __launch_bounds__(256, 2) void k_gemm_s1(
    const float* __restrict__ bon, const float* __restrict__ btg,
    float* __restrict__ dout, int N)
{
    extern __shared__ uint32_t sm[];
    float* bias_s = (float*)(sm + SM_BIAS);
    uint32_t sb = smem_u32(sm);

    int gy = blockIdx.y;
    int row0 = blockIdx.x * 128;
    int tid = threadIdx.x;
    int wid = tid >> 5, lane = tid & 31;
    int g = lane >> 2, tg = lane & 3;
    int warpM = wid & 1, warpN = wid >> 1;
    int aoff = gy ? 128 : 0;

    // fill A (split fp32 -> bf16 hi/lo packed), once per CTA
    {
        int m = tid >> 1, half = tid & 1;
        const float4* arow = (const float4*)(g_Agg + (size_t)(row0 + m) * 256 + aoff + half * 64);
        uint32_t* dH = sm + SM_AH + m * PA + half * 32;
        uint32_t* dL = sm + SM_AL + m * PA + half * 32;
        #pragma unroll
        for (int j = 0; j < 16; j++) {
            float4 a = arow[j];
            uint32_t h0, l0, h1, l1;
            bsplit(a.x, a.y, h0, l0);
            bsplit(a.z, a.w, h1, l1);
            dH[2 * j] = h0; dH[2 * j + 1] = h1;
            dL[2 * j] = l0; dL[2 * j + 1] = l1;
        }
    }

    int nsub = gy ? 3 : 2;
    for (int s = 0; s < nsub; s++) {
        int widx, mode, sidx = 0;
        const float* bias;
        float* out;
        if (s == 0)      { widx = 0; bias = btg;  out = gy ? g_TgtX : g_TgtY; mode = 0; }
        else if (s == 1) { widx = 1; bias = g_bc; out = gy ? g_Hy   : g_Hx;   mode = 1; sidx = gy; }
        else             { widx = 2; bias = bon;  out = dout;                 mode = 2; }

        __syncthreads();   // previous sub done reading B/bias
        {
            const uint4* src = (const uint4*)g_Bh[widx];
            uint32_t bdst = sb + (uint32_t)SM_B * 4;
            for (int i = tid; i < D * PA / 4; i += 256) cpa16(bdst + i * 16, src + i);
            CP_WAIT();
        }
        if (tid < 128) bias_s[tid] = bias[tid];
        __syncthreads();

        float c[4][4][4];
        #pragma unroll
        for (int mf = 0; mf < 4; mf++)
            #pragma unroll
            for (int nf = 0; nf < 4; nf++)
                #pragma unroll
                for (int q = 0; q < 4; q++) c[mf][nf][q] = 0.f;

        mma_pass(sb, wid, lane, c, true);    // Ah*Bh + Al*Bh
        __syncthreads();
        {
            const uint4* src = (const uint4*)g_Bl[widx];
            uint32_t bdst = sb + (uint32_t)SM_B * 4;
            for (int i = tid; i < D * PA / 4; i += 256) cpa16(bdst + i * 16, src + i);
            CP_WAIT();
        }
        __syncthreads();
        mma_pass(sb, wid, lane, c, false);   // Ah*Bl

        // epilogue
        float ls[8], lq[8];
        #pragma unroll
        for (int i = 0; i < 8; i++) { ls[i] = 0.f; lq[i] = 0.f; }

        #pragma unroll
        for (int mf = 0; mf < 4; mf++) {
            #pragma unroll
            for (int part = 0; part < 2; part++) {
                int n = row0 + warpM * 64 + mf * 16 + g + part * 8;
                #pragma unroll
                for (int nf = 0; nf < 4; nf++) {
                    int col = warpN * 32 + nf * 8 + 2 * tg;
                    float v0 = c[mf][nf][part * 2]     + bias_s[col];
                    float v1 = c[mf][nf][part * 2 + 1] + bias_s[col + 1];
                    if (mode == 2) {
                        if (n < N) {
                            float2 s2 = *(const float2*)(g_S + (size_t)n * 256 + 128 + col);
                            *(float2*)(dout + (size_t)n * D + col) =
                                make_float2(v0 + s2.x, v1 + s2.y);
                        }
                    } else {
                        *(float2*)(out + (size_t)n * D + col) = make_float2(v0, v1);
                        if (mode == 1 && n < N) {
                            ls[nf * 2]     += v0; lq[nf * 2]     += v0 * v0;
                            ls[nf * 2 + 1] += v1; lq[nf * 2 + 1] += v1 * v1;
                        }
                    }
                }
            }
        }
        if (mode == 1) {
            #pragma unroll
            for (int i = 0; i < 8; i++) {
                #pragma unroll
                for (int off = 4; off < 32; off <<= 1) {
                    ls[i] += __shfl_xor_sync(0xffffffffu, ls[i], off);
                    lq[i] += __shfl_xor_sync(0xffffffffu, lq[i], off);
                }
            }
            if (g == 0) {
                #pragma unroll
                for (int nf = 0; nf < 4; nf++) {
                    #pragma unroll
                    for (int j = 0; j < 2; j++) {
                        int col = warpN * 32 + nf * 8 + 2 * tg + j;
                        atomicAdd(&g_colsum[sidx][col], ls[nf * 2 + j]);
                        atomicAdd(&g_colsq[sidx][col],  lq[nf * 2 + j]);
                    }
                }
            }
        }
    }
}

__global__ void k_stats(const float* __restrict__ bng, const float* __restrict__ bnb, int N) {
    int t = threadIdx.x;
    int s = t >> 7, c = t & 127;
    float inv = 1.f / (float)N;
    float mu  = g_colsum[s][c] * inv;
    float var = g_colsq[s][c] * inv - mu * mu;
    float istd = rsqrtf(var + 1e-5f);
    float sc = bng[c] * istd;
    g_bnScale[s][c] = sc;
    g_bnShift[s][c] = bnb[c] - mu * sc;
}

// ---------------- stage-2: predictor + cosine loss (2 CTAs/SM) ----------------
__global__ __launch_bounds__(256, 2) void k_pred_s2(
    const float* __restrict__ b2, const float* __restrict__ prelu_a, int N)
{
    extern __shared__ uint32_t sm[];
    float* bias_s = (float*)(sm + SM_BIAS);
    float* sred   = (float*)(sm + SM_RED);   // psq[128], dot[128], tsq[128]
    uint32_t sb = smem_u32(sm);

    int tag = blockIdx.y;
    int row0 = blockIdx.x * 128;
    int tid = threadIdx.x;
    int wid = tid >> 5, lane = tid & 31;
    int g = lane >> 2, tg = lane & 3;
    int warpM = wid & 1, warpN = wid >> 1;
    const float* H = tag ? g_Hy : g_Hx;
    const float* T = tag ? g_TgtY : g_TgtX;
    float slope = prelu_a[0];

    // fill A = PReLU(BN(H)) split
    {
        int m = tid >> 1, half = tid & 1;
        const float4* hrow = (const float4*)(H + (size_t)(row0 + m) * D + half * 64);
        const float4* scp = (const float4*)(g_bnScale[tag] + half * 64);
        const float4* shp = (const float4*)(g_bnShift[tag] + half * 64);
        uint32_t* dH = sm + SM_AH + m * PA + half * 32;
        uint32_t* dL = sm + SM_AL + m * PA + half * 32;
        #pragma unroll
        for (int j = 0; j < 16; j++) {
            float4 h  = hrow[j];
            float4 sc = scp[j];
            float4 sh = shp[j];
            float a0 = fmaf(h.x, sc.x, sh.x);
            float a1 = fmaf(h.y, sc.y, sh.y);
            float a2 = fmaf(h.z, sc.z, sh.z);
            float a3 = fmaf(h.w, sc.w, sh.w);
            a0 = a0 > 0.f ? a0 : slope * a0;
            a1 = a1 > 0.f ? a1 : slope * a1;
            a2 = a2 > 0.f ? a2 : slope * a2;
            a3 = a3 > 0.f ? a3 : slope * a3;
            uint32_t h0, l0, h1, l1;
            bsplit(a0, a1, h0, l0);
            bsplit(a2, a3, h1, l1);
            dH[2 * j] = h0; dH[2 * j + 1] = h1;
            dL[2 * j] = l0; dL[2 * j + 1] = l1;
        }
    }
    {
        const uint4* src = (const uint4*)g_Bh[3];
        uint32_t bdst = sb + (uint32_t)SM_B * 4;
        for (int i = tid; i < D * PA / 4; i += 256) cpa16(bdst + i * 16, src + i);
        CP_WAIT();
    }
    if (tid < 128) {
        bias_s[tid] = b2[tid];
        sred[tid] = 0.f; sred[128 + tid] = 0.f; sred[256 + tid] = 0.f;
    }
    __syncthreads();

    float c[4][4][4];
    #pragma unroll
    for (int mf = 0; mf < 4; mf++)
        #pragma unroll
        for (int nf = 0; nf < 4; nf++)
            #pragma unroll
            for (int q = 0; q < 4; q++) c[mf][nf][q] = 0.f;

    mma_pass(sb, wid, lane, c, true);
    __syncthreads();
    {
        const uint4* src = (const uint4*)g_Bl[3];
        uint32_t bdst = sb + (uint32_t)SM_B * 4;
        for (int i = tid; i < D * PA / 4; i += 256) cpa16(bdst + i * 16, src + i);
        CP_WAIT();
    }
    __syncthreads();
    mma_pass(sb, wid, lane, c, false);

    #pragma unroll
    for (int mf = 0; mf < 4; mf++) {
        #pragma unroll
        for (int part = 0; part < 2; part++) {
            int r = warpM * 64 + mf * 16 + g + part * 8;
            int n = row0 + r;
            float psq = 0.f, dot = 0.f, tsq = 0.f;
            #pragma unroll
            for (int nf = 0; nf < 4; nf++) {
                int col = warpN * 32 + nf * 8 + 2 * tg;
                float v0 = c[mf][nf][part * 2]     + bias_s[col];
                float v1 = c[mf][nf][part * 2 + 1] + bias_s[col + 1];
                float2 t2 = *(const float2*)(T + (size_t)n * D + col);
                psq = fmaf(v0, v0, fmaf(v1, v1, psq));
                dot = fmaf(v0, t2.x, fmaf(v1, t2.y, dot));
                tsq = fmaf(t2.x, t2.x, fmaf(t2.y, t2.y, tsq));
            }
            atomicAdd(&sred[r], psq);
            atomicAdd(&sred[128 + r], dot);
            atomicAdd(&sred[256 + r], tsq);
        }
    }
    __syncthreads();

    if (tid < 128) {
        int n = row0 + tid;
        float lossv = 0.f;
        if (n < N) {
            float denom = fmaxf(sqrtf(sred[tid]), 1e-12f) *
                          fmaxf(sqrtf(sred[256 + tid]), 1e-12f);
            lossv = 2.f - 2.f * sred[128 + tid] / denom;
        }
        #pragma unroll
        for (int o = 16; o; o >>= 1) lossv += __shfl_xor_sync(0xffffffffu, lossv, o);
        if (lane == 0) atomicAdd(&g_lossSum, (double)lossv);
    }
}

__global__ void k_final(float* __restrict__ dout, int N) {
    dout[(size_t)N * D] = (float)(g_lossSum / (double)N);
}

// ---------------- launch ----------------
extern "C" void kernel_launch(void* const* d_in, const int* in_sizes, int n_in,
                              void* d_out, int out_size) {
    const float* x    = (const float*)d_in[0];
    const float* perb = (const float*)d_in[1];
    const int*   erow = (const int*)d_in[2];
    const int*   ecol = (const int*)d_in[3];
    const float* ew   = (const float*)d_in[4];
    const float* Won  = (const float*)d_in[5];
    const float* bon  = (const float*)d_in[6];
    const float* Wtg  = (const float*)d_in[7];
    const float* btg  = (const float*)d_in[8];
    const float* W1   = (const float*)d_in[9];
    const float* b1   = (const float*)d_in[10];
    const float* bng  = (const float*)d_in[11];
    const float* bnb  = (const float*)d_in[12];
    const float* pa   = (const float*)d_in[13];
    const float* W2   = (const float*)d_in[14];
    const float* b2   = (const float*)d_in[15];
    float* out = (float*)d_out;

    int N = in_sizes[0] / D;
    int E = in_sizes[2];
    if (N > NPAD) N = NPAD;
    if (E > EMAX) E = EMAX;

    cudaFuncSetAttribute(k_gemm_s1, cudaFuncAttributeMaxDynamicSharedMemorySize, DYN_SMEM);
    cudaFuncSetAttribute(k_pred_s2, cudaFuncAttributeMaxDynamicSharedMemorySize, DYN_SMEM);

    k_prep<<<(NPAD * 64 + 255) / 256, 256>>>(x, perb, N);
    k_count<<<(E + 255) / 256, 256>>>(erow, E);
    k_scan<<<1, 1024>>>();
    k_scatter<<<(E + 255) / 256, 256>>>(erow, ecol, ew, E);
    k_combine<<<D + 1, D>>>(Won, bon, W1, b1);
    k_wprep<<<4, 256>>>(Wtg, Won, W2);
    k_agg_csr<<<NPAD / 8, 256>>>();
    dim3 g1(NBLK, 2);
    k_gemm_s1<<<g1, 256, DYN_SMEM>>>(bon, btg, out, N);
    k_stats<<<1, 256>>>(bng, bnb, N);
    dim3 g2(NBLK, 2);
    k_pred_s2<<<g2, 256, DYN_SMEM>>>(b2, pa, N);
    k_final<<<1, 1>>>(out, N);
}

// round 7
// speedup vs baseline: 2.3560x; 1.0942x over previous
#include <cuda_runtime.h>
#include <cuda_bf16.h>
#include <cstdint>

#define D 128
#define NPAD 50048          // 391 * 128
#define NBLK 391
#define PA 68               // packed (bf16x2) row pitch in u32: 64 data + 4 pad
#define EMAX 1000000

// ---------------- device scratch ----------------
__device__ float g_S[(size_t)NPAD * 256];     // [n][0:128]=x, [128:256]=x2
__device__ float g_Agg[(size_t)NPAD * 256];   // [n][0:128]=Zx, [128:256]=Z2
__device__ float g_TgtX[(size_t)NPAD * D];
__device__ float g_TgtY[(size_t)NPAD * D];
__device__ float g_Hx[(size_t)NPAD * D];
__device__ float g_Hy[(size_t)NPAD * D];
__device__ float g_Wc[D * D];
__device__ float g_bc[D];
__device__ __align__(16) uint32_t g_Bh[4][D * PA];  // Wtg, Wc, Won, W2 (hi)
__device__ __align__(16) uint32_t g_Bl[4][D * PA];  // lo residual
__device__ float g_colsum[2][D];
__device__ float g_colsq[2][D];
__device__ float g_bnScale[2][D];
__device__ float g_bnShift[2][D];
__device__ double g_lossSum;
// CSR (g_cur zero at load; every launch restores it to zero)
__device__ int   g_off[NPAD + 1];
__device__ int   g_cur[NPAD];
__device__ int   g_ecol2[EMAX];
__device__ float g_ew2[EMAX];

// ---------------- helpers ----------------
__device__ __forceinline__ uint32_t smem_u32(const void* p) {
    uint32_t a;
    asm("{ .reg .u64 t; cvta.to.shared.u64 t, %1; cvt.u32.u64 %0, t; }" : "=r"(a) : "l"(p));
    return a;
}
__device__ __forceinline__ void cpa16(uint32_t s, const void* g) {
    asm volatile("cp.async.ca.shared.global [%0], [%1], 16;" :: "r"(s), "l"(g));
}
#define CP_WAIT() \
    asm volatile("cp.async.commit_group;\n\tcp.async.wait_group 0;" ::: "memory")

__device__ __forceinline__ void bsplit(float x, float y, uint32_t& h, uint32_t& l) {
    __nv_bfloat162 hb = __floats2bfloat162_rn(x, y);
    float2 hf = __bfloat1622float2(hb);
    __nv_bfloat162 lb = __floats2bfloat162_rn(x - hf.x, y - hf.y);
    h = *reinterpret_cast<uint32_t*>(&hb);
    l = *reinterpret_cast<uint32_t*>(&lb);
}

#define MMA(cc, a, b0v, b1v) \
    asm("mma.sync.aligned.m16n8k16.row.col.f32.bf16.bf16.f32 " \
        "{%0,%1,%2,%3},{%4,%5,%6,%7},{%8,%9},{%0,%1,%2,%3};" \
        : "+f"((cc)[0]), "+f"((cc)[1]), "+f"((cc)[2]), "+f"((cc)[3]) \
        : "r"((a)[0]), "r"((a)[1]), "r"((a)[2]), "r"((a)[3]), \
          "r"(b0v), "r"(b1v))

#define LDSM4(r, addr) \
    asm volatile("ldmatrix.sync.aligned.m8n8.x4.shared.b16 {%0,%1,%2,%3}, [%4];" \
        : "=r"((r)[0]), "=r"((r)[1]), "=r"((r)[2]), "=r"((r)[3]) : "r"(addr))

// smem layout (u32 offsets): Ah, Al, single B, bias, reduction
#define SM_AH 0
#define SM_AL (D * PA)
#define SM_B  (2 * D * PA)
#define SM_BIAS (3 * D * PA)
#define SM_RED (SM_BIAS + 128)
#define DYN_SMEM ((SM_RED + 3 * 128) * 4)   // ~104.5KB -> 2 CTAs/SM

// ---------------- fused: prep || count ----------------
__global__ void k_prep_count(const float* __restrict__ x, const float* __restrict__ perb,
                             const int* __restrict__ erow, int N, int E, int PREPB) {
    int b = blockIdx.x;
    int t = threadIdx.x;
    if (b < PREPB) {
        int idx = b * 256 + t;
        if (idx >= NPAD * 64) return;
        int n = idx >> 6, k = idx & 63;
        float4 v = make_float4(0.f, 0.f, 0.f, 0.f);
        if (n < N) {
            if (k < 32) {
                v = ((const float4*)x)[(size_t)n * 32 + k];
            } else {
                float4 a = ((const float4*)x)[(size_t)n * 32 + (k - 32)];
                float4 p = ((const float4*)perb)[(size_t)n * 32 + (k - 32)];
                v = make_float4(a.x + p.x, a.y + p.y, a.z + p.z, a.w + p.w);
            }
        }
        ((float4*)g_S)[idx] = v;
    } else {
        int e = (b - PREPB) * 256 + t;
        if (e < E) atomicAdd(&g_cur[__ldg(erow + e)], 1);
    }
}

// single-block exclusive scan over g_cur -> g_off; reset g_cur for scatter
__global__ void k_scan() {
    __shared__ int part[1024];
    const int CH = (NPAD + 1023) / 1024;   // 49
    int t = threadIdx.x;
    int base = t * CH;
    int s = 0;
    for (int i = 0; i < CH; i++) {
        int idx = base + i;
        if (idx < NPAD) s += g_cur[idx];
    }
    part[t] = s;
    __syncthreads();
    for (int off = 1; off < 1024; off <<= 1) {
        int u = (t >= off) ? part[t - off] : 0;
        __syncthreads();
        part[t] += u;
        __syncthreads();
    }
    int run = part[t] - s;
    for (int i = 0; i < CH; i++) {
        int idx = base + i;
        if (idx < NPAD) {
            g_off[idx] = run;
            run += g_cur[idx];
            g_cur[idx] = 0;
        }
    }
    if (t == 1023) g_off[NPAD] = part[1023];
}

// ---------------- fused: scatter || combine (Wc = Won@W1, bc = bon@W1+b1) ------
__global__ void k_scatter_combine(
    const int* __restrict__ erow, const int* __restrict__ ecol,
    const float* __restrict__ ew,
    const float* __restrict__ Won, const float* __restrict__ bon,
    const float* __restrict__ W1,  const float* __restrict__ b1,
    int E, int SCATB)
{
    int b = blockIdx.x;
    int t = threadIdx.x;
    if (b < SCATB) {
        int e = b * 256 + t;
        if (e >= E) return;
        int r = __ldg(erow + e);
        int pos = g_off[r] + atomicAdd(&g_cur[r], 1);
        g_ecol2[pos] = __ldg(ecol + e);
        g_ew2[pos]   = __ldg(ew + e);
    } else {
        __shared__ float row[D];
        int i = b - SCATB;           // 0..128
        int j = t;
        if (j < D) row[j] = (i < D) ? Won[i * D + j] : bon[j];
        __syncthreads();
        if (j < D) {
            float acc = (i < D) ? 0.f : b1[j];
            #pragma unroll 8
            for (int k = 0; k < D; k++) acc = fmaf(row[k], W1[k * D + j], acc);
            if (i < D) g_Wc[i * D + j] = acc;
            else       g_bc[j] = acc;
        }
    }
}

// ---------------- fused: wprep (16 blocks) || CSR aggregation ----------------
__global__ __launch_bounds__(256) void k_agg_wprep(
    const float* __restrict__ Wtg, const float* __restrict__ Won,
    const float* __restrict__ W2) {
    int b = blockIdx.x;
    int t = threadIdx.x;
    if (b < 16) {
        // weight split/transpose; block b covers w = b>>2, n in [quad*32, quad*32+32)
        if (b == 0) {
            if (t >= 128) {
                int c = t - 128;
                g_colsum[0][c] = 0.f; g_colsum[1][c] = 0.f;
                g_colsq[0][c]  = 0.f; g_colsq[1][c]  = 0.f;
                if (c == 0) g_lossSum = 0.0;
            }
        }
        int w = b >> 2, quad = b & 3;
        if (t < 64) {
            const float* W = (w == 0) ? Wtg : (w == 1) ? g_Wc : (w == 2) ? Won : W2;
            int n = quad * 32 + (t >> 1), half = t & 1;
            #pragma unroll
            for (int j = 0; j < 32; j++) {
                int k = half * 64 + 2 * j;
                float v0 = W[(size_t)k * D + n];
                float v1 = W[(size_t)(k + 1) * D + n];
                uint32_t h, l;
                bsplit(v0, v1, h, l);
                g_Bh[w][n * PA + half * 32 + j] = h;
                g_Bl[w][n * PA + half * 32 + j] = l;
            }
        }
        return;
    }
    // aggregation: one warp per node, 4 edges in flight
    int wid = t >> 5, lane = t & 31;
    int n = (b - 16) * 8 + wid;
    int start = g_off[n];
    int deg = g_off[n + 1] - start;
    if (lane == 0) g_cur[n] = 0;          // restore invariant for next launch
    float4 a0 = make_float4(0.f, 0.f, 0.f, 0.f), a1 = a0;
    const float4* S4 = (const float4*)g_S;
    for (int base = 0; base < deg; base += 32) {
        int j = base + lane;
        int cc = 0; float ww = 0.f;
        if (j < deg) { cc = g_ecol2[start + j]; ww = g_ew2[start + j]; }
        int cnt = min(32, deg - base);
        int i = 0;
        for (; i + 4 <= cnt; i += 4) {
            int   c0 = __shfl_sync(0xffffffffu, cc, i);
            int   c1 = __shfl_sync(0xffffffffu, cc, i + 1);
            int   c2 = __shfl_sync(0xffffffffu, cc, i + 2);
            int   c3 = __shfl_sync(0xffffffffu, cc, i + 3);
            float w0 = __shfl_sync(0xffffffffu, ww, i);
            float w1 = __shfl_sync(0xffffffffu, ww, i + 1);
            float w2 = __shfl_sync(0xffffffffu, ww, i + 2);
            float w3 = __shfl_sync(0xffffffffu, ww, i + 3);
            const float4* p0 = S4 + (size_t)c0 * 64 + lane * 2;
            const float4* p1 = S4 + (size_t)c1 * 64 + lane * 2;
            const float4* p2 = S4 + (size_t)c2 * 64 + lane * 2;
            const float4* p3 = S4 + (size_t)c3 * 64 + lane * 2;
            float4 v00 = __ldg(p0), v01 = __ldg(p0 + 1);
            float4 v10 = __ldg(p1), v11 = __ldg(p1 + 1);
            float4 v20 = __ldg(p2), v21 = __ldg(p2 + 1);
            float4 v30 = __ldg(p3), v31 = __ldg(p3 + 1);
            a0.x = fmaf(w0, v00.x, a0.x); a0.y = fmaf(w0, v00.y, a0.y);
            a0.z = fmaf(w0, v00.z, a0.z); a0.w = fmaf(w0, v00.w, a0.w);
            a1.x = fmaf(w0, v01.x, a1.x); a1.y = fmaf(w0, v01.y, a1.y);
            a1.z = fmaf(w0, v01.z, a1.z); a1.w = fmaf(w0, v01.w, a1.w);
            a0.x = fmaf(w1, v10.x, a0.x); a0.y = fmaf(w1, v10.y, a0.y);
            a0.z = fmaf(w1, v10.z, a0.z); a0.w = fmaf(w1, v10.w, a0.w);
            a1.x = fmaf(w1, v11.x, a1.x); a1.y = fmaf(w1, v11.y, a1.y);
            a1.z = fmaf(w1, v11.z, a1.z); a1.w = fmaf(w1, v11.w, a1.w);
            a0.x = fmaf(w2, v20.x, a0.x); a0.y = fmaf(w2, v20.y, a0.y);
            a0.z = fmaf(w2, v20.z, a0.z); a0.w = fmaf(w2, v20.w, a0.w);
            a1.x = fmaf(w2, v21.x, a1.x); a1.y = fmaf(w2, v21.y, a1.y);
            a1.z = fmaf(w2, v21.z, a1.z); a1.w = fmaf(w2, v21.w, a1.w);
            a0.x = fmaf(w3, v30.x, a0.x); a0.y = fmaf(w3, v30.y, a0.y);
            a0.z = fmaf(w3, v30.z, a0.z); a0.w = fmaf(w3, v30.w, a0.w);
            a1.x = fmaf(w3, v31.x, a1.x); a1.y = fmaf(w3, v31.y, a1.y);
            a1.z = fmaf(w3, v31.z, a1.z); a1.w = fmaf(w3, v31.w, a1.w);
        }
        for (; i < cnt; i++) {
            int cs = __shfl_sync(0xffffffffu, cc, i);
            float ws = __shfl_sync(0xffffffffu, ww, i);
            const float4* src = S4 + (size_t)cs * 64 + lane * 2;
            float4 v = __ldg(src);
            float4 u = __ldg(src + 1);
            a0.x = fmaf(ws, v.x, a0.x); a0.y = fmaf(ws, v.y, a0.y);
            a0.z = fmaf(ws, v.z, a0.z); a0.w = fmaf(ws, v.w, a0.w);
            a1.x = fmaf(ws, u.x, a1.x); a1.y = fmaf(ws, u.y, a1.y);
            a1.z = fmaf(ws, u.z, a1.z); a1.w = fmaf(ws, u.w, a1.w);
        }
    }
    float4* dst = (float4*)g_Agg + (size_t)n * 64 + lane * 2;
    dst[0] = a0;
    dst[1] = a1;
}

// ---------------- MMA pass via ldmatrix ----------------
__device__ __forceinline__ void mma_pass(uint32_t sb, int wid, int lane,
                                         float c[4][4][4], bool hipass) {
    int warpM = wid & 1, warpN = wid >> 1;
    int arow = warpM * 64 + (lane & 15);
    uint32_t aA = sb + (uint32_t)(arow * PA + (lane >> 4) * 4) * 4;
    int brow = warpN * 32 + (lane & 7) + ((lane >> 4) & 1) * 8;
    uint32_t aB = sb + (uint32_t)(brow * PA + ((lane >> 3) & 1) * 4) * 4
                + (uint32_t)SM_B * 4;

    #pragma unroll
    for (int ks = 0; ks < 8; ks++) {
        uint32_t ah[4][4], b[2][4];
        #pragma unroll
        for (int mf = 0; mf < 4; mf++)
            LDSM4(ah[mf], aA + (uint32_t)(mf * 16 * PA) * 4 + ks * 32);
        #pragma unroll
        for (int p = 0; p < 2; p++)
            LDSM4(b[p], aB + (uint32_t)(p * 16 * PA) * 4 + ks * 32);
        #pragma unroll
        for (int mf = 0; mf < 4; mf++)
            #pragma unroll
            for (int p = 0; p < 2; p++) {
                MMA(c[mf][p * 2 + 0], ah[mf], b[p][0], b[p][1]);
                MMA(c[mf][p * 2 + 1], ah[mf], b[p][2], b[p][3]);
            }
        if (hipass) {
            uint32_t al[4][4];
            #pragma unroll
            for (int mf = 0; mf < 4; mf++)
                LDSM4(al[mf], aA + (uint32_t)SM_AL * 4
                              + (uint32_t)(mf * 16 * PA) * 4 + ks * 32);
            #pragma unroll
            for (int mf = 0; mf < 4; mf++)
                #pragma unroll
                for (int p = 0; p < 2; p++) {
                    MMA(c[mf][p * 2 + 0], al[mf], b[p][0], b[p][1]);
                    MMA(c[mf][p * 2 + 1], al[mf], b[p][2], b[p][3]);
                }
        }
    }
}

// ---------------- stage-1: A-reused fused GEMMs (2 CTAs/SM) ----------------
// Tgt/H sub-GEMMs use 2-term A@Bh (normalized consumers); embed keeps 3 terms.
__global__ __launch_bounds__(256, 2) void k_gemm_s1(
    const float* __restrict__ bon, const float* __restrict__ btg,
    float* __restrict__ dout, int N)
{
    extern __shared__ uint32_t sm[];
    float* bias_s = (float*)(sm + SM_BIAS);
    uint32_t sb = smem_u32(sm);

    int gy = blockIdx.y;
    int row0 = blockIdx.x * 128;
    int tid = threadIdx.x;
    int wid = tid >> 5, lane = tid & 31;
    int g = lane >> 2, tg = lane & 3;
    int warpM = wid & 1, warpN = wid >> 1;
    int aoff = gy ? 128 : 0;

    // fill A (split fp32 -> bf16 hi/lo packed), once per CTA
    {
        int m = tid >> 1, half = tid & 1;
        const float4* arow = (const float4*)(g_Agg + (size_t)(row0 + m) * 256 + aoff + half * 64);
        uint32_t* dH = sm + SM_AH + m * PA + half * 32;
        uint32_t* dL = sm + SM_AL + m * PA + half * 32;
        #pragma unroll
        for (int j = 0; j < 16; j++) {
            float4 a = arow[j];
            uint32_t h0, l0, h1, l1;
            bsplit(a.x, a.y, h0, l0);
            bsplit(a.z, a.w, h1, l1);
            dH[2 * j] = h0; dH[2 * j + 1] = h1;
            dL[2 * j] = l0; dL[2 * j + 1] = l1;
        }
    }

    int nsub = gy ? 3 : 2;
    for (int s = 0; s < nsub; s++) {
        int widx, mode, sidx = 0;
        const float* bias;
        float* out;
        if (s == 0)      { widx = 0; bias = btg;  out = gy ? g_TgtX : g_TgtY; mode = 0; }
        else if (s == 1) { widx = 1; bias = g_bc; out = gy ? g_Hy   : g_Hx;   mode = 1; sidx = gy; }
        else             { widx = 2; bias = bon;  out = dout;                 mode = 2; }
        bool full = (mode == 2);

        __syncthreads();   // previous sub done reading B/bias
        {
            const uint4* src = (const uint4*)g_Bh[widx];
            uint32_t bdst = sb + (uint32_t)SM_B * 4;
            for (int i = tid; i < D * PA / 4; i += 256) cpa16(bdst + i * 16, src + i);
            CP_WAIT();
        }
        if (tid < 128) bias_s[tid] = bias[tid];
        __syncthreads();

        float c[4][4][4];
        #pragma unroll
        for (int mf = 0; mf < 4; mf++)
            #pragma unroll
            for (int nf = 0; nf < 4; nf++)
                #pragma unroll
                for (int q = 0; q < 4; q++) c[mf][nf][q] = 0.f;

        mma_pass(sb, wid, lane, c, true);        // Ah*Bh + Al*Bh
        if (full) {
            __syncthreads();
            const uint4* src = (const uint4*)g_Bl[widx];
            uint32_t bdst = sb + (uint32_t)SM_B * 4;
            for (int i = tid; i < D * PA / 4; i += 256) cpa16(bdst + i * 16, src + i);
            CP_WAIT();
            __syncthreads();
            mma_pass(sb, wid, lane, c, false);   // Ah*Bl
        }

        // epilogue
        float ls[8], lq[8];
        #pragma unroll
        for (int i = 0; i < 8; i++) { ls[i] = 0.f; lq[i] = 0.f; }

        #pragma unroll
        for (int mf = 0; mf < 4; mf++) {
            #pragma unroll
            for (int part = 0; part < 2; part++) {
                int n = row0 + warpM * 64 + mf * 16 + g + part * 8;
                #pragma unroll
                for (int nf = 0; nf < 4; nf++) {
                    int col = warpN * 32 + nf * 8 + 2 * tg;
                    float v0 = c[mf][nf][part * 2]     + bias_s[col];
                    float v1 = c[mf][nf][part * 2 + 1] + bias_s[col + 1];
                    if (mode == 2) {
                        if (n < N) {
                            float2 s2 = *(const float2*)(g_S + (size_t)n * 256 + 128 + col);
                            *(float2*)(dout + (size_t)n * D + col) =
                                make_float2(v0 + s2.x, v1 + s2.y);
                        }
                    } else {
                        *(float2*)(out + (size_t)n * D + col) = make_float2(v0, v1);
                        if (mode == 1 && n < N) {
                            ls[nf * 2]     += v0; lq[nf * 2]     += v0 * v0;
                            ls[nf * 2 + 1] += v1; lq[nf * 2 + 1] += v1 * v1;
                        }
                    }
                }
            }
        }
        if (mode == 1) {
            #pragma unroll
            for (int i = 0; i < 8; i++) {
                #pragma unroll
                for (int off = 4; off < 32; off <<= 1) {
                    ls[i] += __shfl_xor_sync(0xffffffffu, ls[i], off);
                    lq[i] += __shfl_xor_sync(0xffffffffu, lq[i], off);
                }
            }
            if (g == 0) {
                #pragma unroll
                for (int nf = 0; nf < 4; nf++) {
                    #pragma unroll
                    for (int j = 0; j < 2; j++) {
                        int col = warpN * 32 + nf * 8 + 2 * tg + j;
                        atomicAdd(&g_colsum[sidx][col], ls[nf * 2 + j]);
                        atomicAdd(&g_colsq[sidx][col],  lq[nf * 2 + j]);
                    }
                }
            }
        }
    }
}

__global__ void k_stats(const float* __restrict__ bng, const float* __restrict__ bnb, int N) {
    int t = threadIdx.x;
    int s = t >> 7, c = t & 127;
    float inv = 1.f / (float)N;
    float mu  = g_colsum[s][c] * inv;
    float var = g_colsq[s][c] * inv - mu * mu;
    float istd = rsqrtf(var + 1e-5f);
    float sc = bng[c] * istd;
    g_bnScale[s][c] = sc;
    g_bnShift[s][c] = bnb[c] - mu * sc;
}

// ---------------- stage-2: predictor + cosine loss (2-term, 2 CTAs/SM) --------
__global__ __launch_bounds__(256, 2) void k_pred_s2(
    const float* __restrict__ b2, const float* __restrict__ prelu_a, int N)
{
    extern __shared__ uint32_t sm[];
    float* bias_s = (float*)(sm + SM_BIAS);
    float* sred   = (float*)(sm + SM_RED);   // psq[128], dot[128], tsq[128]
    uint32_t sb = smem_u32(sm);

    int tag = blockIdx.y;
    int row0 = blockIdx.x * 128;
    int tid = threadIdx.x;
    int wid = tid >> 5, lane = tid & 31;
    int g = lane >> 2, tg = lane & 3;
    int warpM = wid & 1, warpN = wid >> 1;
    const float* H = tag ? g_Hy : g_Hx;
    const float* T = tag ? g_TgtY : g_TgtX;
    float slope = prelu_a[0];

    // fill A = PReLU(BN(H)) split
    {
        int m = tid >> 1, half = tid & 1;
        const float4* hrow = (const float4*)(H + (size_t)(row0 + m) * D + half * 64);
        const float4* scp = (const float4*)(g_bnScale[tag] + half * 64);
        const float4* shp = (const float4*)(g_bnShift[tag] + half * 64);
        uint32_t* dH = sm + SM_AH + m * PA + half * 32;
        uint32_t* dL = sm + SM_AL + m * PA + half * 32;
        #pragma unroll
        for (int j = 0; j < 16; j++) {
            float4 h  = hrow[j];
            float4 sc = scp[j];
            float4 sh = shp[j];
            float a0 = fmaf(h.x, sc.x, sh.x);
            float a1 = fmaf(h.y, sc.y, sh.y);
            float a2 = fmaf(h.z, sc.z, sh.z);
            float a3 = fmaf(h.w, sc.w, sh.w);
            a0 = a0 > 0.f ? a0 : slope * a0;
            a1 = a1 > 0.f ? a1 : slope * a1;
            a2 = a2 > 0.f ? a2 : slope * a2;
            a3 = a3 > 0.f ? a3 : slope * a3;
            uint32_t h0, l0, h1, l1;
            bsplit(a0, a1, h0, l0);
            bsplit(a2, a3, h1, l1);
            dH[2 * j] = h0; dH[2 * j + 1] = h1;
            dL[2 * j] = l0; dL[2 * j + 1] = l1;
        }
    }
    {
        const uint4* src = (const uint4*)g_Bh[3];
        uint32_t bdst = sb + (uint32_t)SM_B * 4;
        for (int i = tid; i < D * PA / 4; i += 256) cpa16(bdst + i * 16, src + i);
        CP_WAIT();
    }
    if (tid < 128) {
        bias_s[tid] = b2[tid];
        sred[tid] = 0.f; sred[128 + tid] = 0.f; sred[256 + tid] = 0.f;
    }
    __syncthreads();

    float c[4][4][4];
    #pragma unroll
    for (int mf = 0; mf < 4; mf++)
        #pragma unroll
        for (int nf = 0; nf < 4; nf++)
            #pragma unroll
            for (int q = 0; q < 4; q++) c[mf][nf][q] = 0.f;

    mma_pass(sb, wid, lane, c, true);    // 2-term: A @ Bh (cosine-normalized)

    #pragma unroll
    for (int mf = 0; mf < 4; mf++) {
        #pragma unroll
        for (int part = 0; part < 2; part++) {
            int r = warpM * 64 + mf * 16 + g + part * 8;
            int n = row0 + r;
            float psq = 0.f, dot = 0.f, tsq = 0.f;
            #pragma unroll
            for (int nf = 0; nf < 4; nf++) {
                int col = warpN * 32 + nf * 8 + 2 * tg;
                float v0 = c[mf][nf][part * 2]     + bias_s[col];
                float v1 = c[mf][nf][part * 2 + 1] + bias_s[col + 1];
                float2 t2 = *(const float2*)(T + (size_t)n * D + col);
                psq = fmaf(v0, v0, fmaf(v1, v1, psq));
                dot = fmaf(v0, t2.x, fmaf(v1, t2.y, dot));
                tsq = fmaf(t2.x, t2.x, fmaf(t2.y, t2.y, tsq));
            }
            atomicAdd(&sred[r], psq);
            atomicAdd(&sred[128 + r], dot);
            atomicAdd(&sred[256 + r], tsq);
        }
    }
    __syncthreads();

    if (tid < 128) {
        int n = row0 + tid;
        float lossv = 0.f;
        if (n < N) {
            float denom = fmaxf(sqrtf(sred[tid]), 1e-12f) *
                          fmaxf(sqrtf(sred[256 + tid]), 1e-12f);
            lossv = 2.f - 2.f * sred[128 + tid] / denom;
        }
        #pragma unroll
        for (int o = 16; o; o >>= 1) lossv += __shfl_xor_sync(0xffffffffu, lossv, o);
        if (lane == 0) atomicAdd(&g_lossSum, (double)lossv);
    }
}

__global__ void k_final(float* __restrict__ dout, int N) {
    dout[(size_t)N * D] = (float)(g_lossSum / (double)N);
}

// ---------------- launch ----------------
extern "C" void kernel_launch(void* const* d_in, const int* in_sizes, int n_in,
                              void* d_out, int out_size) {
    const float* x    = (const float*)d_in[0];
    const float* perb = (const float*)d_in[1];
    const int*   erow = (const int*)d_in[2];
    const int*   ecol = (const int*)d_in[3];
    const float* ew   = (const float*)d_in[4];
    const float* Won  = (const float*)d_in[5];
    const float* bon  = (const float*)d_in[6];
    const float* Wtg  = (const float*)d_in[7];
    const float* btg  = (const float*)d_in[8];
    const float* W1   = (const float*)d_in[9];
    const float* b1   = (const float*)d_in[10];
    const float* bng  = (const float*)d_in[11];
    const float* bnb  = (const float*)d_in[12];
    const float* pa   = (const float*)d_in[13];
    const float* W2   = (const float*)d_in[14];
    const float* b2   = (const float*)d_in[15];
    float* out = (float*)d_out;

    int N = in_sizes[0] / D;
    int E = in_sizes[2];
    if (N > NPAD) N = NPAD;
    if (E > EMAX) E = EMAX;

    cudaFuncSetAttribute(k_gemm_s1, cudaFuncAttributeMaxDynamicSharedMemorySize, DYN_SMEM);
    cudaFuncSetAttribute(k_pred_s2, cudaFuncAttributeMaxDynamicSharedMemorySize, DYN_SMEM);

    const int PREPB = NPAD * 64 / 256;       // 12512
    int EB = (E + 255) / 256;

    k_prep_count<<<PREPB + EB, 256>>>(x, perb, erow, N, E, PREPB);
    k_scan<<<1, 1024>>>();
    k_scatter_combine<<<EB + D + 1, 256>>>(erow, ecol, ew, Won, bon, W1, b1, E, EB);
    k_agg_wprep<<<16 + NPAD / 8, 256>>>(Wtg, Won, W2);
    dim3 g1(NBLK, 2);
    k_gemm_s1<<<g1, 256, DYN_SMEM>>>(bon, btg, out, N);
    k_stats<<<1, 256>>>(bng, bnb, N);
    dim3 g2(NBLK, 2);
    k_pred_s2<<<g2, 256, DYN_SMEM>>>(b2, pa, N);
    k_final<<<1, 1>>>(out, N);
}

// round 8
// speedup vs baseline: 2.5390x; 1.0776x over previous
#include <cuda_runtime.h>
#include <cuda_fp16.h>
#include <cstdint>

#define D 128
#define NPAD 50048          // 391 * 128
#define NBLK 391
#define PA 68               // packed (fp16x2) row pitch in u32: 64 data + 4 pad
#define EMAX 1000000

// ---------------- device scratch ----------------
__device__ float g_S2[(size_t)NPAD * D];      // x2 = x + perb
__device__ float g_Agg[(size_t)NPAD * 256];   // [n][0:128]=Zx, [128:256]=Z2
__device__ float g_TgtX[(size_t)NPAD * D];
__device__ float g_TgtY[(size_t)NPAD * D];
__device__ float g_Hx[(size_t)NPAD * D];
__device__ float g_Hy[(size_t)NPAD * D];
__device__ float g_Wc[D * D];
__device__ float g_bc[D];
__device__ __align__(16) uint32_t g_Bh[4][D * PA];  // Wtg, Wc, Won, W2 (fp16 hi)
__device__ __align__(16) uint32_t g_Bl[4][D * PA];  // fp16 lo residual
__device__ float g_colsum[2][D];
__device__ float g_colsq[2][D];
__device__ float g_bnScale[2][D];
__device__ float g_bnShift[2][D];
__device__ double g_lossSum;
// CSR (g_cur zero at load; every launch restores it to zero)
__device__ int   g_off[NPAD + 1];
__device__ int   g_cur[NPAD];
__device__ int   g_ecol2[EMAX];
__device__ float g_ew2[EMAX];

// ---------------- helpers ----------------
__device__ __forceinline__ uint32_t smem_u32(const void* p) {
    uint32_t a;
    asm("{ .reg .u64 t; cvta.to.shared.u64 t, %1; cvt.u32.u64 %0, t; }" : "=r"(a) : "l"(p));
    return a;
}
__device__ __forceinline__ void cpa16(uint32_t s, const void* g) {
    asm volatile("cp.async.ca.shared.global [%0], [%1], 16;" :: "r"(s), "l"(g));
}
#define CP_WAIT() \
    asm volatile("cp.async.commit_group;\n\tcp.async.wait_group 0;" ::: "memory")

// split fp32 pair -> packed fp16 hi pair + fp16 lo (residual) pair
__device__ __forceinline__ void hsplit(float x, float y, uint32_t& h, uint32_t& l) {
    __half2 hh = __floats2half2_rn(x, y);
    float2 hf = __half22float2(hh);
    __half2 ll = __floats2half2_rn(x - hf.x, y - hf.y);
    h = *reinterpret_cast<uint32_t*>(&hh);
    l = *reinterpret_cast<uint32_t*>(&ll);
}
__device__ __forceinline__ uint32_t hpack(float x, float y) {
    __half2 hh = __floats2half2_rn(x, y);
    return *reinterpret_cast<uint32_t*>(&hh);
}

// fp16 HMMA, fp32 accumulate (sm_80+ PTX)
#define MMA(cc, a, b0v, b1v) \
    asm("mma.sync.aligned.m16n8k16.row.col.f32.f16.f16.f32 " \
        "{%0,%1,%2,%3},{%4,%5,%6,%7},{%8,%9},{%0,%1,%2,%3};" \
        : "+f"((cc)[0]), "+f"((cc)[1]), "+f"((cc)[2]), "+f"((cc)[3]) \
        : "r"((a)[0]), "r"((a)[1]), "r"((a)[2]), "r"((a)[3]), \
          "r"(b0v), "r"(b1v))

#define LDSM4(r, addr) \
    asm volatile("ldmatrix.sync.aligned.m8n8.x4.shared.b16 {%0,%1,%2,%3}, [%4];" \
        : "=r"((r)[0]), "=r"((r)[1]), "=r"((r)[2]), "=r"((r)[3]) : "r"(addr))

// smem layout (u32 offsets): Ah, Al, single B, bias, reduction
#define SM_AH 0
#define SM_AL (D * PA)
#define SM_B  (2 * D * PA)
#define SM_BIAS (3 * D * PA)
#define SM_RED (SM_BIAS + 128)
#define DYN_SMEM ((SM_RED + 3 * 128) * 4)   // ~104.5KB -> 2 CTAs/SM

// ---------------- fused: prep (x2 only) || count ----------------
__global__ void k_prep_count(const float* __restrict__ x, const float* __restrict__ perb,
                             const int* __restrict__ erow, int N, int E, int PREPB) {
    int b = blockIdx.x;
    int t = threadIdx.x;
    if (b < PREPB) {
        int idx = b * 256 + t;                 // float4 index into g_S2
        if (idx >= NPAD * 32) return;
        int n = idx >> 5, k = idx & 31;
        float4 v = make_float4(0.f, 0.f, 0.f, 0.f);
        if (n < N) {
            float4 a = ((const float4*)x)[(size_t)n * 32 + k];
            float4 p = ((const float4*)perb)[(size_t)n * 32 + k];
            v = make_float4(a.x + p.x, a.y + p.y, a.z + p.z, a.w + p.w);
        }
        ((float4*)g_S2)[idx] = v;
    } else {
        int e = (b - PREPB) * 256 + t;
        if (e < E) atomicAdd(&g_cur[__ldg(erow + e)], 1);
    }
}

// single-block exclusive scan over g_cur -> g_off; reset g_cur for scatter
__global__ void k_scan() {
    __shared__ int part[1024];
    const int CH = (NPAD + 1023) / 1024;   // 49
    int t = threadIdx.x;
    int base = t * CH;
    int s = 0;
    for (int i = 0; i < CH; i++) {
        int idx = base + i;
        if (idx < NPAD) s += g_cur[idx];
    }
    part[t] = s;
    __syncthreads();
    for (int off = 1; off < 1024; off <<= 1) {
        int u = (t >= off) ? part[t - off] : 0;
        __syncthreads();
        part[t] += u;
        __syncthreads();
    }
    int run = part[t] - s;
    for (int i = 0; i < CH; i++) {
        int idx = base + i;
        if (idx < NPAD) {
            g_off[idx] = run;
            run += g_cur[idx];
            g_cur[idx] = 0;
        }
    }
    if (t == 1023) g_off[NPAD] = part[1023];
}

// ---------------- fused: scatter || combine (Wc = Won@W1, bc = bon@W1+b1) ------
__global__ void k_scatter_combine(
    const int* __restrict__ erow, const int* __restrict__ ecol,
    const float* __restrict__ ew,
    const float* __restrict__ Won, const float* __restrict__ bon,
    const float* __restrict__ W1,  const float* __restrict__ b1,
    int E, int SCATB)
{
    int b = blockIdx.x;
    int t = threadIdx.x;
    if (b < SCATB) {
        int e = b * 256 + t;
        if (e >= E) return;
        int r = __ldg(erow + e);
        int pos = g_off[r] + atomicAdd(&g_cur[r], 1);
        g_ecol2[pos] = __ldg(ecol + e);
        g_ew2[pos]   = __ldg(ew + e);
    } else {
        __shared__ float row[D];
        int i = b - SCATB;           // 0..128
        int j = t;
        if (j < D) row[j] = (i < D) ? Won[i * D + j] : bon[j];
        __syncthreads();
        if (j < D) {
            float acc = (i < D) ? 0.f : b1[j];
            #pragma unroll 8
            for (int k = 0; k < D; k++) acc = fmaf(row[k], W1[k * D + j], acc);
            if (i < D) g_Wc[i * D + j] = acc;
            else       g_bc[j] = acc;
        }
    }
}

// ---------------- fused: wprep (16 blocks) || CSR aggregation ----------------
// Agg[n][0:128] = sum w * x[col];  Agg[n][128:256] = sum w * x2[col]
__global__ __launch_bounds__(256) void k_agg_wprep(
    const float* __restrict__ x,
    const float* __restrict__ Wtg, const float* __restrict__ Won,
    const float* __restrict__ W2) {
    int b = blockIdx.x;
    int t = threadIdx.x;
    if (b < 16) {
        if (b == 0 && t >= 128) {
            int c = t - 128;
            g_colsum[0][c] = 0.f; g_colsum[1][c] = 0.f;
            g_colsq[0][c]  = 0.f; g_colsq[1][c]  = 0.f;
            if (c == 0) g_lossSum = 0.0;
        }
        int w = b >> 2, quad = b & 3;
        if (t < 64) {
            const float* W = (w == 0) ? Wtg : (w == 1) ? g_Wc : (w == 2) ? Won : W2;
            int n = quad * 32 + (t >> 1), half = t & 1;
            #pragma unroll
            for (int j = 0; j < 32; j++) {
                int k = half * 64 + 2 * j;
                float v0 = W[(size_t)k * D + n];
                float v1 = W[(size_t)(k + 1) * D + n];
                uint32_t h, l;
                hsplit(v0, v1, h, l);
                g_Bh[w][n * PA + half * 32 + j] = h;
                g_Bl[w][n * PA + half * 32 + j] = l;
            }
        }
        return;
    }
    // aggregation: one warp per node; lanes 0-15 read x, lanes 16-31 read x2
    int wid = t >> 5, lane = t & 31;
    int n = (b - 16) * 8 + wid;
    int start = g_off[n];
    int deg = g_off[n + 1] - start;
    if (lane == 0) g_cur[n] = 0;          // restore invariant for next launch
    const float4* base = (lane < 16) ? (const float4*)x : (const float4*)g_S2;
    int loff = (lane & 15) * 2;
    float4 a0 = make_float4(0.f, 0.f, 0.f, 0.f), a1 = a0;
    for (int bb = 0; bb < deg; bb += 32) {
        int j = bb + lane;
        int cc = 0; float ww = 0.f;
        if (j < deg) { cc = g_ecol2[start + j]; ww = g_ew2[start + j]; }
        int cnt = min(32, deg - bb);
        int i = 0;
        for (; i + 4 <= cnt; i += 4) {
            int   c0 = __shfl_sync(0xffffffffu, cc, i);
            int   c1 = __shfl_sync(0xffffffffu, cc, i + 1);
            int   c2 = __shfl_sync(0xffffffffu, cc, i + 2);
            int   c3 = __shfl_sync(0xffffffffu, cc, i + 3);
            float w0 = __shfl_sync(0xffffffffu, ww, i);
            float w1 = __shfl_sync(0xffffffffu, ww, i + 1);
            float w2 = __shfl_sync(0xffffffffu, ww, i + 2);
            float w3 = __shfl_sync(0xffffffffu, ww, i + 3);
            const float4* p0 = base + (size_t)c0 * 32 + loff;
            const float4* p1 = base + (size_t)c1 * 32 + loff;
            const float4* p2 = base + (size_t)c2 * 32 + loff;
            const float4* p3 = base + (size_t)c3 * 32 + loff;
            float4 v00 = __ldg(p0), v01 = __ldg(p0 + 1);
            float4 v10 = __ldg(p1), v11 = __ldg(p1 + 1);
            float4 v20 = __ldg(p2), v21 = __ldg(p2 + 1);
            float4 v30 = __ldg(p3), v31 = __ldg(p3 + 1);
            a0.x = fmaf(w0, v00.x, a0.x); a0.y = fmaf(w0, v00.y, a0.y);
            a0.z = fmaf(w0, v00.z, a0.z); a0.w = fmaf(w0, v00.w, a0.w);
            a1.x = fmaf(w0, v01.x, a1.x); a1.y = fmaf(w0, v01.y, a1.y);
            a1.z = fmaf(w0, v01.z, a1.z); a1.w = fmaf(w0, v01.w, a1.w);
            a0.x = fmaf(w1, v10.x, a0.x); a0.y = fmaf(w1, v10.y, a0.y);
            a0.z = fmaf(w1, v10.z, a0.z); a0.w = fmaf(w1, v10.w, a0.w);
            a1.x = fmaf(w1, v11.x, a1.x); a1.y = fmaf(w1, v11.y, a1.y);
            a1.z = fmaf(w1, v11.z, a1.z); a1.w = fmaf(w1, v11.w, a1.w);
            a0.x = fmaf(w2, v20.x, a0.x); a0.y = fmaf(w2, v20.y, a0.y);
            a0.z = fmaf(w2, v20.z, a0.z); a0.w = fmaf(w2, v20.w, a0.w);
            a1.x = fmaf(w2, v21.x, a1.x); a1.y = fmaf(w2, v21.y, a1.y);
            a1.z = fmaf(w2, v21.z, a1.z); a1.w = fmaf(w2, v21.w, a1.w);
            a0.x = fmaf(w3, v30.x, a0.x); a0.y = fmaf(w3, v30.y, a0.y);
            a0.z = fmaf(w3, v30.z, a0.z); a0.w = fmaf(w3, v30.w, a0.w);
            a1.x = fmaf(w3, v31.x, a1.x); a1.y = fmaf(w3, v31.y, a1.y);
            a1.z = fmaf(w3, v31.z, a1.z); a1.w = fmaf(w3, v31.w, a1.w);
        }
        for (; i < cnt; i++) {
            int cs = __shfl_sync(0xffffffffu, cc, i);
            float ws = __shfl_sync(0xffffffffu, ww, i);
            const float4* src = base + (size_t)cs * 32 + loff;
            float4 v = __ldg(src);
            float4 u = __ldg(src + 1);
            a0.x = fmaf(ws, v.x, a0.x); a0.y = fmaf(ws, v.y, a0.y);
            a0.z = fmaf(ws, v.z, a0.z); a0.w = fmaf(ws, v.w, a0.w);
            a1.x = fmaf(ws, u.x, a1.x); a1.y = fmaf(ws, u.y, a1.y);
            a1.z = fmaf(ws, u.z, a1.z); a1.w = fmaf(ws, u.w, a1.w);
        }
    }
    // lanes 0-15 wrote Zx part (cols 0-127), 16-31 wrote Z2 part (128-255)
    float4* dst = (float4*)g_Agg + (size_t)n * 64 + (lane < 16 ? 0 : 32) + loff;
    dst[0] = a0;
    dst[1] = a1;
}

// ---------------- MMA pass via ldmatrix ----------------
// dual=true: (Ah+Al)@B ; dual=false: Ah@B.  B slot holds whatever was copied.
__device__ __forceinline__ void mma_pass(uint32_t sb, int wid, int lane,
                                         float c[4][4][4], bool dual) {
    int warpM = wid & 1, warpN = wid >> 1;
    int arow = warpM * 64 + (lane & 15);
    uint32_t aA = sb + (uint32_t)(arow * PA + (lane >> 4) * 4) * 4;
    int brow = warpN * 32 + (lane & 7) + ((lane >> 4) & 1) * 8;
    uint32_t aB = sb + (uint32_t)(brow * PA + ((lane >> 3) & 1) * 4) * 4
                + (uint32_t)SM_B * 4;

    #pragma unroll
    for (int ks = 0; ks < 8; ks++) {
        uint32_t ah[4][4], b[2][4];
        #pragma unroll
        for (int mf = 0; mf < 4; mf++)
            LDSM4(ah[mf], aA + (uint32_t)(mf * 16 * PA) * 4 + ks * 32);
        #pragma unroll
        for (int p = 0; p < 2; p++)
            LDSM4(b[p], aB + (uint32_t)(p * 16 * PA) * 4 + ks * 32);
        #pragma unroll
        for (int mf = 0; mf < 4; mf++)
            #pragma unroll
            for (int p = 0; p < 2; p++) {
                MMA(c[mf][p * 2 + 0], ah[mf], b[p][0], b[p][1]);
                MMA(c[mf][p * 2 + 1], ah[mf], b[p][2], b[p][3]);
            }
        if (dual) {
            uint32_t al[4][4];
            #pragma unroll
            for (int mf = 0; mf < 4; mf++)
                LDSM4(al[mf], aA + (uint32_t)SM_AL * 4
                              + (uint32_t)(mf * 16 * PA) * 4 + ks * 32);
            #pragma unroll
            for (int mf = 0; mf < 4; mf++)
                #pragma unroll
                for (int p = 0; p < 2; p++) {
                    MMA(c[mf][p * 2 + 0], al[mf], b[p][0], b[p][1]);
                    MMA(c[mf][p * 2 + 1], al[mf], b[p][2], b[p][3]);
                }
        }
    }
}

// ---------------- stage-1 ----------------
// gy=0: A=Zx -> TgtY (1-term), Hx (1-term, stats 0)
// gy=1: A=Z2 -> TgtX (1-term), Hy (1-term, stats 1), embed (3-term fp16) -> dout
__global__ __launch_bounds__(256, 2) void k_gemm_s1(
    const float* __restrict__ bon, const float* __restrict__ btg,
    float* __restrict__ dout, int N)
{
    extern __shared__ uint32_t sm[];
    float* bias_s = (float*)(sm + SM_BIAS);
    uint32_t sb = smem_u32(sm);

    int gy = blockIdx.y;
    int row0 = blockIdx.x * 128;
    int tid = threadIdx.x;
    int wid = tid >> 5, lane = tid & 31;
    int g = lane >> 2, tg = lane & 3;
    int warpM = wid & 1, warpN = wid >> 1;
    int aoff = gy ? 32 : 0;   // float4 offset: Zx at 0, Z2 at 32

    // fill A (fp16 hi; lo only needed for embed on gy=1)
    {
        int m = tid >> 1, half = tid & 1;
        const float4* arow = (const float4*)g_Agg + (size_t)(row0 + m) * 64 + aoff + half * 16;
        uint32_t* dH = sm + SM_AH + m * PA + half * 32;
        uint32_t* dL = sm + SM_AL + m * PA + half * 32;
        if (gy) {
            #pragma unroll
            for (int j = 0; j < 16; j++) {
                float4 a = arow[j];
                uint32_t h0, l0, h1, l1;
                hsplit(a.x, a.y, h0, l0);
                hsplit(a.z, a.w, h1, l1);
                dH[2 * j] = h0; dH[2 * j + 1] = h1;
                dL[2 * j] = l0; dL[2 * j + 1] = l1;
            }
        } else {
            #pragma unroll
            for (int j = 0; j < 16; j++) {
                float4 a = arow[j];
                dH[2 * j]     = hpack(a.x, a.y);
                dH[2 * j + 1] = hpack(a.z, a.w);
            }
        }
    }

    int nsub = gy ? 3 : 2;
    for (int s = 0; s < nsub; s++) {
        int widx, mode, sidx = 0;
        const float* bias;
        float* out;
        if (s == 0)      { widx = 0; bias = btg;  out = gy ? g_TgtX : g_TgtY; mode = 0; }
        else if (s == 1) { widx = 1; bias = g_bc; out = gy ? g_Hy   : g_Hx;   mode = 1; sidx = gy; }
        else             { widx = 2; bias = bon;  out = dout;                 mode = 2; }
        bool full = (mode == 2);

        __syncthreads();
        {
            const uint4* src = (const uint4*)g_Bh[widx];
            uint32_t bdst = sb + (uint32_t)SM_B * 4;
            for (int i = tid; i < D * PA / 4; i += 256) cpa16(bdst + i * 16, src + i);
            CP_WAIT();
        }
        if (tid < 128) bias_s[tid] = bias[tid];
        __syncthreads();

        float c[4][4][4];
        #pragma unroll
        for (int mf = 0; mf < 4; mf++)
            #pragma unroll
            for (int nf = 0; nf < 4; nf++)
                #pragma unroll
                for (int q = 0; q < 4; q++) c[mf][nf][q] = 0.f;

        mma_pass(sb, wid, lane, c, full);        // loss paths: Ah@Bh; embed: (Ah+Al)@Bh
        if (full) {
            __syncthreads();
            const uint4* src = (const uint4*)g_Bl[widx];
            uint32_t bdst = sb + (uint32_t)SM_B * 4;
            for (int i = tid; i < D * PA / 4; i += 256) cpa16(bdst + i * 16, src + i);
            CP_WAIT();
            __syncthreads();
            mma_pass(sb, wid, lane, c, false);   // + Ah@Bl
        }

        // epilogue
        float ls[8], lq[8];
        #pragma unroll
        for (int i = 0; i < 8; i++) { ls[i] = 0.f; lq[i] = 0.f; }

        #pragma unroll
        for (int mf = 0; mf < 4; mf++) {
            #pragma unroll
            for (int part = 0; part < 2; part++) {
                int n = row0 + warpM * 64 + mf * 16 + g + part * 8;
                #pragma unroll
                for (int nf = 0; nf < 4; nf++) {
                    int col = warpN * 32 + nf * 8 + 2 * tg;
                    float v0 = c[mf][nf][part * 2]     + bias_s[col];
                    float v1 = c[mf][nf][part * 2 + 1] + bias_s[col + 1];
                    if (mode == 2) {
                        if (n < N) {
                            float2 s2 = *(const float2*)(g_S2 + (size_t)n * D + col);
                            *(float2*)(dout + (size_t)n * D + col) =
                                make_float2(v0 + s2.x, v1 + s2.y);
                        }
                    } else {
                        *(float2*)(out + (size_t)n * D + col) = make_float2(v0, v1);
                        if (mode == 1 && n < N) {
                            ls[nf * 2]     += v0; lq[nf * 2]     += v0 * v0;
                            ls[nf * 2 + 1] += v1; lq[nf * 2 + 1] += v1 * v1;
                        }
                    }
                }
            }
        }
        if (mode == 1) {
            #pragma unroll
            for (int i = 0; i < 8; i++) {
                #pragma unroll
                for (int off = 4; off < 32; off <<= 1) {
                    ls[i] += __shfl_xor_sync(0xffffffffu, ls[i], off);
                    lq[i] += __shfl_xor_sync(0xffffffffu, lq[i], off);
                }
            }
            if (g == 0) {
                #pragma unroll
                for (int nf = 0; nf < 4; nf++) {
                    #pragma unroll
                    for (int j = 0; j < 2; j++) {
                        int col = warpN * 32 + nf * 8 + 2 * tg + j;
                        atomicAdd(&g_colsum[sidx][col], ls[nf * 2 + j]);
                        atomicAdd(&g_colsq[sidx][col],  lq[nf * 2 + j]);
                    }
                }
            }
        }
    }
}

__global__ void k_stats(const float* __restrict__ bng, const float* __restrict__ bnb, int N) {
    int t = threadIdx.x;
    int s = t >> 7, c = t & 127;
    float inv = 1.f / (float)N;
    float mu  = g_colsum[s][c] * inv;
    float var = g_colsq[s][c] * inv - mu * mu;
    float istd = rsqrtf(var + 1e-5f);
    float sc = bng[c] * istd;
    g_bnScale[s][c] = sc;
    g_bnShift[s][c] = bnb[c] - mu * sc;
}

// ---------------- stage-2: predictor (1-term fp16) + cosine loss ----------------
__global__ __launch_bounds__(256, 2) void k_pred_s2(
    const float* __restrict__ b2, const float* __restrict__ prelu_a, int N)
{
    extern __shared__ uint32_t sm[];
    float* bias_s = (float*)(sm + SM_BIAS);
    float* sred   = (float*)(sm + SM_RED);   // psq[128], dot[128], tsq[128]
    uint32_t sb = smem_u32(sm);

    int tag = blockIdx.y;
    int row0 = blockIdx.x * 128;
    int tid = threadIdx.x;
    int wid = tid >> 5, lane = tid & 31;
    int g = lane >> 2, tg = lane & 3;
    int warpM = wid & 1, warpN = wid >> 1;
    const float* H = tag ? g_Hy : g_Hx;
    const float* T = tag ? g_TgtY : g_TgtX;
    float slope = prelu_a[0];

    // fill A = PReLU(BN(H)), fp16 hi only
    {
        int m = tid >> 1, half = tid & 1;
        const float4* hrow = (const float4*)(H + (size_t)(row0 + m) * D + half * 64);
        const float4* scp = (const float4*)(g_bnScale[tag] + half * 64);
        const float4* shp = (const float4*)(g_bnShift[tag] + half * 64);
        uint32_t* dH = sm + SM_AH + m * PA + half * 32;
        #pragma unroll
        for (int j = 0; j < 16; j++) {
            float4 h  = hrow[j];
            float4 sc = scp[j];
            float4 sh = shp[j];
            float a0 = fmaf(h.x, sc.x, sh.x);
            float a1 = fmaf(h.y, sc.y, sh.y);
            float a2 = fmaf(h.z, sc.z, sh.z);
            float a3 = fmaf(h.w, sc.w, sh.w);
            a0 = a0 > 0.f ? a0 : slope * a0;
            a1 = a1 > 0.f ? a1 : slope * a1;
            a2 = a2 > 0.f ? a2 : slope * a2;
            a3 = a3 > 0.f ? a3 : slope * a3;
            dH[2 * j]     = hpack(a0, a1);
            dH[2 * j + 1] = hpack(a2, a3);
        }
    }
    {
        const uint4* src = (const uint4*)g_Bh[3];
        uint32_t bdst = sb + (uint32_t)SM_B * 4;
        for (int i = tid; i < D * PA / 4; i += 256) cpa16(bdst + i * 16, src + i);
        CP_WAIT();
    }
    if (tid < 128) {
        bias_s[tid] = b2[tid];
        sred[tid] = 0.f; sred[128 + tid] = 0.f; sred[256 + tid] = 0.f;
    }
    __syncthreads();

    float c[4][4][4];
    #pragma unroll
    for (int mf = 0; mf < 4; mf++)
        #pragma unroll
        for (int nf = 0; nf < 4; nf++)
            #pragma unroll
            for (int q = 0; q < 4; q++) c[mf][nf][q] = 0.f;

    mma_pass(sb, wid, lane, c, false);   // 1-term fp16

    #pragma unroll
    for (int mf = 0; mf < 4; mf++) {
        #pragma unroll
        for (int part = 0; part < 2; part++) {
            int r = warpM * 64 + mf * 16 + g + part * 8;
            int n = row0 + r;
            float psq = 0.f, dot = 0.f, tsq = 0.f;
            #pragma unroll
            for (int nf = 0; nf < 4; nf++) {
                int col = warpN * 32 + nf * 8 + 2 * tg;
                float v0 = c[mf][nf][part * 2]     + bias_s[col];
                float v1 = c[mf][nf][part * 2 + 1] + bias_s[col + 1];
                float2 t2 = *(const float2*)(T + (size_t)n * D + col);
                psq = fmaf(v0, v0, fmaf(v1, v1, psq));
                dot = fmaf(v0, t2.x, fmaf(v1, t2.y, dot));
                tsq = fmaf(t2.x, t2.x, fmaf(t2.y, t2.y, tsq));
            }
            atomicAdd(&sred[r], psq);
            atomicAdd(&sred[128 + r], dot);
            atomicAdd(&sred[256 + r], tsq);
        }
    }
    __syncthreads();

    if (tid < 128) {
        int n = row0 + tid;
        float lossv = 0.f;
        if (n < N) {
            float denom = fmaxf(sqrtf(sred[tid]), 1e-12f) *
                          fmaxf(sqrtf(sred[256 + tid]), 1e-12f);
            lossv = 2.f - 2.f * sred[128 + tid] / denom;
        }
        #pragma unroll
        for (int o = 16; o; o >>= 1) lossv += __shfl_xor_sync(0xffffffffu, lossv, o);
        if (lane == 0) atomicAdd(&g_lossSum, (double)lossv);
    }
}

__global__ void k_final(float* __restrict__ dout, int N) {
    dout[(size_t)N * D] = (float)(g_lossSum / (double)N);
}

// ---------------- launch ----------------
extern "C" void kernel_launch(void* const* d_in, const int* in_sizes, int n_in,
                              void* d_out, int out_size) {
    const float* x    = (const float*)d_in[0];
    const float* perb = (const float*)d_in[1];
    const int*   erow = (const int*)d_in[2];
    const int*   ecol = (const int*)d_in[3];
    const float* ew   = (const float*)d_in[4];
    const float* Won  = (const float*)d_in[5];
    const float* bon  = (const float*)d_in[6];
    const float* Wtg  = (const float*)d_in[7];
    const float* btg  = (const float*)d_in[8];
    const float* W1   = (const float*)d_in[9];
    const float* b1   = (const float*)d_in[10];
    const float* bng  = (const float*)d_in[11];
    const float* bnb  = (const float*)d_in[12];
    const float* pa   = (const float*)d_in[13];
    const float* W2   = (const float*)d_in[14];
    const float* b2   = (const float*)d_in[15];
    float* out = (float*)d_out;

    int N = in_sizes[0] / D;
    int E = in_sizes[2];
    if (N > NPAD) N = NPAD;
    if (E > EMAX) E = EMAX;

    cudaFuncSetAttribute(k_gemm_s1, cudaFuncAttributeMaxDynamicSharedMemorySize, DYN_SMEM);
    cudaFuncSetAttribute(k_pred_s2, cudaFuncAttributeMaxDynamicSharedMemorySize, DYN_SMEM);

    const int PREPB = NPAD * 32 / 256;       // 6256
    int EB = (E + 255) / 256;

    k_prep_count<<<PREPB + EB, 256>>>(x, perb, erow, N, E, PREPB);
    k_scan<<<1, 1024>>>();
    k_scatter_combine<<<EB + D + 1, 256>>>(erow, ecol, ew, Won, bon, W1, b1, E, EB);
    k_agg_wprep<<<16 + NPAD / 8, 256>>>(x, Wtg, Won, W2);
    dim3 g1(NBLK, 2);
    k_gemm_s1<<<g1, 256, DYN_SMEM>>>(bon, btg, out, N);
    k_stats<<<1, 256>>>(bng, bnb, N);
    dim3 g2(NBLK, 2);
    k_pred_s2<<<g2, 256, DYN_SMEM>>>(b2, pa, N);
    k_final<<<1, 1>>>(out, N);
}

// round 10
// speedup vs baseline: 2.7305x; 1.0755x over previous
#include <cuda_runtime.h>
#include <cuda_fp16.h>
#include <cstdint>

#define D 128
#define NPAD 50048          // 391 * 128
#define NBLK 391
#define PA 68               // packed (fp16x2) row pitch in u32: 64 data + 4 pad
#define EMAX 1000000

// ---------------- device scratch ----------------
__device__ float g_S2[(size_t)NPAD * D];                  // x2 = x + perb (fp32)
__device__ __align__(16) uint32_t g_AggX[(size_t)NPAD * 64];  // Zx, packed half2
__device__ float g_AggZ2[(size_t)NPAD * D];               // Z2, fp32 (embed needs precision)
__device__ __align__(16) uint32_t g_TgtX[(size_t)NPAD * 64];  // packed half2
__device__ __align__(16) uint32_t g_TgtY[(size_t)NPAD * 64];
__device__ __align__(16) uint32_t g_Hx[(size_t)NPAD * 64];
__device__ __align__(16) uint32_t g_Hy[(size_t)NPAD * 64];
__device__ float g_Wc[D * D];
__device__ float g_bc[D];
__device__ __align__(16) uint32_t g_Bh[4][D * PA];  // Wtg, Wc, Won, W2 (fp16 hi)
__device__ __align__(16) uint32_t g_Bl[4][D * PA];  // fp16 lo residual
__device__ float g_colsum[2][D];
__device__ float g_colsq[2][D];
__device__ float g_bnScale[2][D];
__device__ float g_bnShift[2][D];
__device__ double g_lossSum;
// CSR (g_cur zero at load; every launch restores it to zero)
__device__ int   g_off[NPAD + 1];
__device__ int   g_cur[NPAD];
__device__ int   g_ecol2[EMAX];
__device__ float g_ew2[EMAX];

// ---------------- helpers ----------------
__device__ __forceinline__ uint32_t smem_u32(const void* p) {
    uint32_t a;
    asm("{ .reg .u64 t; cvta.to.shared.u64 t, %1; cvt.u32.u64 %0, t; }" : "=r"(a) : "l"(p));
    return a;
}
__device__ __forceinline__ void cpa16(uint32_t s, const void* g) {
    asm volatile("cp.async.ca.shared.global [%0], [%1], 16;" :: "r"(s), "l"(g));
}
#define CP_WAIT() \
    asm volatile("cp.async.commit_group;\n\tcp.async.wait_group 0;" ::: "memory")

__device__ __forceinline__ void hsplit(float x, float y, uint32_t& h, uint32_t& l) {
    __half2 hh = __floats2half2_rn(x, y);
    float2 hf = __half22float2(hh);
    __half2 ll = __floats2half2_rn(x - hf.x, y - hf.y);
    h = *reinterpret_cast<uint32_t*>(&hh);
    l = *reinterpret_cast<uint32_t*>(&ll);
}
__device__ __forceinline__ uint32_t hpack(float x, float y) {
    __half2 hh = __floats2half2_rn(x, y);
    return *reinterpret_cast<uint32_t*>(&hh);
}
__device__ __forceinline__ float2 hunpack(uint32_t v) {
    return __half22float2(*reinterpret_cast<__half2*>(&v));
}

// fp16 HMMA, fp32 accumulate (sm_80+ PTX)
#define MMA(cc, a, b0v, b1v) \
    asm("mma.sync.aligned.m16n8k16.row.col.f32.f16.f16.f32 " \
        "{%0,%1,%2,%3},{%4,%5,%6,%7},{%8,%9},{%0,%1,%2,%3};" \
        : "+f"((cc)[0]), "+f"((cc)[1]), "+f"((cc)[2]), "+f"((cc)[3]) \
        : "r"((a)[0]), "r"((a)[1]), "r"((a)[2]), "r"((a)[3]), \
          "r"(b0v), "r"(b1v))

#define LDSM4(r, addr) \
    asm volatile("ldmatrix.sync.aligned.m8n8.x4.shared.b16 {%0,%1,%2,%3}, [%4];" \
        : "=r"((r)[0]), "=r"((r)[1]), "=r"((r)[2]), "=r"((r)[3]) : "r"(addr))

// smem layout (u32 offsets): Ah, Al, single B, bias, reduction
#define SM_AH 0
#define SM_AL (D * PA)
#define SM_B  (2 * D * PA)
#define SM_BIAS (3 * D * PA)
#define SM_RED (SM_BIAS + 128)
#define DYN_SMEM ((SM_RED + 3 * 128) * 4)   // ~104.5KB -> 2 CTAs/SM

// ---------------- fused: prep (x2 only) || count ----------------
__global__ void k_prep_count(const float* __restrict__ x, const float* __restrict__ perb,
                             const int* __restrict__ erow, int N, int E, int PREPB) {
    int b = blockIdx.x;
    int t = threadIdx.x;
    if (b < PREPB) {
        int idx = b * 256 + t;                 // float4 index into g_S2
        if (idx >= NPAD * 32) return;
        int n = idx >> 5, k = idx & 31;
        float4 v = make_float4(0.f, 0.f, 0.f, 0.f);
        if (n < N) {
            float4 a = ((const float4*)x)[(size_t)n * 32 + k];
            float4 p = ((const float4*)perb)[(size_t)n * 32 + k];
            v = make_float4(a.x + p.x, a.y + p.y, a.z + p.z, a.w + p.w);
        }
        ((float4*)g_S2)[idx] = v;
    } else {
        int e = (b - PREPB) * 256 + t;
        if (e < E) atomicAdd(&g_cur[__ldg(erow + e)], 1);
    }
}

// single-block exclusive scan over g_cur -> g_off; reset g_cur for scatter
__global__ void k_scan() {
    __shared__ int part[1024];
    const int CH = (NPAD + 1023) / 1024;   // 49
    int t = threadIdx.x;
    int base = t * CH;
    int s = 0;
    for (int i = 0; i < CH; i++) {
        int idx = base + i;
        if (idx < NPAD) s += g_cur[idx];
    }
    part[t] = s;
    __syncthreads();
    for (int off = 1; off < 1024; off <<= 1) {
        int u = (t >= off) ? part[t - off] : 0;
        __syncthreads();
        part[t] += u;
        __syncthreads();
    }
    int run = part[t] - s;
    for (int i = 0; i < CH; i++) {
        int idx = base + i;
        if (idx < NPAD) {
            g_off[idx] = run;
            run += g_cur[idx];
            g_cur[idx] = 0;
        }
    }
    if (t == 1023) g_off[NPAD] = part[1023];
}

// ---------------- fused: scatter || combine (Wc = Won@W1, bc = bon@W1+b1) ------
__global__ void k_scatter_combine(
    const int* __restrict__ erow, const int* __restrict__ ecol,
    const float* __restrict__ ew,
    const float* __restrict__ Won, const float* __restrict__ bon,
    const float* __restrict__ W1,  const float* __restrict__ b1,
    int E, int SCATB)
{
    int b = blockIdx.x;
    int t = threadIdx.x;
    if (b < SCATB) {
        int e = b * 256 + t;
        if (e >= E) return;
        int r = __ldg(erow + e);
        int pos = g_off[r] + atomicAdd(&g_cur[r], 1);
        g_ecol2[pos] = __ldg(ecol + e);
        g_ew2[pos]   = __ldg(ew + e);
    } else {
        __shared__ float row[D];
        int i = b - SCATB;           // 0..128
        int j = t;
        if (j < D) row[j] = (i < D) ? Won[i * D + j] : bon[j];
        __syncthreads();
        if (j < D) {
            float acc = (i < D) ? 0.f : b1[j];
            #pragma unroll 8
            for (int k = 0; k < D; k++) acc = fmaf(row[k], W1[k * D + j], acc);
            if (i < D) g_Wc[i * D + j] = acc;
            else       g_bc[j] = acc;
        }
    }
}

// ---------------- fused: wprep (16 blocks) || CSR aggregation ----------------
// lanes 0-15: Zx = sum w*x[col]  -> g_AggX (packed half2)
// lanes 16-31: Z2 = sum w*x2[col] -> g_AggZ2 (fp32)
__global__ __launch_bounds__(256) void k_agg_wprep(
    const float* __restrict__ x,
    const float* __restrict__ Wtg, const float* __restrict__ Won,
    const float* __restrict__ W2) {
    int b = blockIdx.x;
    int t = threadIdx.x;
    if (b < 16) {
        if (b == 0 && t >= 128) {
            int c = t - 128;
            g_colsum[0][c] = 0.f; g_colsum[1][c] = 0.f;
            g_colsq[0][c]  = 0.f; g_colsq[1][c]  = 0.f;
            if (c == 0) g_lossSum = 0.0;
        }
        int w = b >> 2, quad = b & 3;
        if (t < 64) {
            const float* W = (w == 0) ? Wtg : (w == 1) ? g_Wc : (w == 2) ? Won : W2;
            int n = quad * 32 + (t >> 1), half = t & 1;
            #pragma unroll
            for (int j = 0; j < 32; j++) {
                int k = half * 64 + 2 * j;
                float v0 = W[(size_t)k * D + n];
                float v1 = W[(size_t)(k + 1) * D + n];
                uint32_t h, l;
                hsplit(v0, v1, h, l);
                g_Bh[w][n * PA + half * 32 + j] = h;
                g_Bl[w][n * PA + half * 32 + j] = l;
            }
        }
        return;
    }
    int wid = t >> 5, lane = t & 31;
    int n = (b - 16) * 8 + wid;
    int start = g_off[n];
    int deg = g_off[n + 1] - start;
    if (lane == 0) g_cur[n] = 0;          // restore invariant for next launch
    const float4* base = (lane < 16) ? (const float4*)x : (const float4*)g_S2;
    int loff = (lane & 15) * 2;
    float4 a0 = make_float4(0.f, 0.f, 0.f, 0.f), a1 = a0;
    for (int bb = 0; bb < deg; bb += 32) {
        int j = bb + lane;
        int cc = 0; float ww = 0.f;
        if (j < deg) { cc = g_ecol2[start + j]; ww = g_ew2[start + j]; }
        int cnt = min(32, deg - bb);
        int i = 0;
        for (; i + 4 <= cnt; i += 4) {
            int   c0 = __shfl_sync(0xffffffffu, cc, i);
            int   c1 = __shfl_sync(0xffffffffu, cc, i + 1);
            int   c2 = __shfl_sync(0xffffffffu, cc, i + 2);
            int   c3 = __shfl_sync(0xffffffffu, cc, i + 3);
            float w0 = __shfl_sync(0xffffffffu, ww, i);
            float w1 = __shfl_sync(0xffffffffu, ww, i + 1);
            float w2 = __shfl_sync(0xffffffffu, ww, i + 2);
            float w3 = __shfl_sync(0xffffffffu, ww, i + 3);
            const float4* p0 = base + (size_t)c0 * 32 + loff;
            const float4* p1 = base + (size_t)c1 * 32 + loff;
            const float4* p2 = base + (size_t)c2 * 32 + loff;
            const float4* p3 = base + (size_t)c3 * 32 + loff;
            float4 v00 = __ldg(p0), v01 = __ldg(p0 + 1);
            float4 v10 = __ldg(p1), v11 = __ldg(p1 + 1);
            float4 v20 = __ldg(p2), v21 = __ldg(p2 + 1);
            float4 v30 = __ldg(p3), v31 = __ldg(p3 + 1);
            a0.x = fmaf(w0, v00.x, a0.x); a0.y = fmaf(w0, v00.y, a0.y);
            a0.z = fmaf(w0, v00.z, a0.z); a0.w = fmaf(w0, v00.w, a0.w);
            a1.x = fmaf(w0, v01.x, a1.x); a1.y = fmaf(w0, v01.y, a1.y);
            a1.z = fmaf(w0, v01.z, a1.z); a1.w = fmaf(w0, v01.w, a1.w);
            a0.x = fmaf(w1, v10.x, a0.x); a0.y = fmaf(w1, v10.y, a0.y);
            a0.z = fmaf(w1, v10.z, a0.z); a0.w = fmaf(w1, v10.w, a0.w);
            a1.x = fmaf(w1, v11.x, a1.x); a1.y = fmaf(w1, v11.y, a1.y);
            a1.z = fmaf(w1, v11.z, a1.z); a1.w = fmaf(w1, v11.w, a1.w);
            a0.x = fmaf(w2, v20.x, a0.x); a0.y = fmaf(w2, v20.y, a0.y);
            a0.z = fmaf(w2, v20.z, a0.z); a0.w = fmaf(w2, v20.w, a0.w);
            a1.x = fmaf(w2, v21.x, a1.x); a1.y = fmaf(w2, v21.y, a1.y);
            a1.z = fmaf(w2, v21.z, a1.z); a1.w = fmaf(w2, v21.w, a1.w);
            a0.x = fmaf(w3, v30.x, a0.x); a0.y = fmaf(w3, v30.y, a0.y);
            a0.z = fmaf(w3, v30.z, a0.z); a0.w = fmaf(w3, v30.w, a0.w);
            a1.x = fmaf(w3, v31.x, a1.x); a1.y = fmaf(w3, v31.y, a1.y);
            a1.z = fmaf(w3, v31.z, a1.z); a1.w = fmaf(w3, v31.w, a1.w);
        }
        for (; i < cnt; i++) {
            int cs = __shfl_sync(0xffffffffu, cc, i);
            float ws = __shfl_sync(0xffffffffu, ww, i);
            const float4* src = base + (size_t)cs * 32 + loff;
            float4 v = __ldg(src);
            float4 u = __ldg(src + 1);
            a0.x = fmaf(ws, v.x, a0.x); a0.y = fmaf(ws, v.y, a0.y);
            a0.z = fmaf(ws, v.z, a0.z); a0.w = fmaf(ws, v.w, a0.w);
            a1.x = fmaf(ws, u.x, a1.x); a1.y = fmaf(ws, u.y, a1.y);
            a1.z = fmaf(ws, u.z, a1.z); a1.w = fmaf(ws, u.w, a1.w);
        }
    }
    if (lane < 16) {
        uint4 pk;
        pk.x = hpack(a0.x, a0.y);
        pk.y = hpack(a0.z, a0.w);
        pk.z = hpack(a1.x, a1.y);
        pk.w = hpack(a1.z, a1.w);
        *(uint4*)(g_AggX + (size_t)n * 64 + lane * 4) = pk;
    } else {
        float4* dst = (float4*)g_AggZ2 + (size_t)n * 32 + loff;
        dst[0] = a0;
        dst[1] = a1;
    }
}

// ---------------- MMA pass via ldmatrix ----------------
__device__ __forceinline__ void mma_pass(uint32_t sb, int wid, int lane,
                                         float c[4][4][4], bool dual) {
    int warpM = wid & 1, warpN = wid >> 1;
    int arow = warpM * 64 + (lane & 15);
    uint32_t aA = sb + (uint32_t)(arow * PA + (lane >> 4) * 4) * 4;
    int brow = warpN * 32 + (lane & 7) + ((lane >> 4) & 1) * 8;
    uint32_t aB = sb + (uint32_t)(brow * PA + ((lane >> 3) & 1) * 4) * 4
                + (uint32_t)SM_B * 4;

    #pragma unroll
    for (int ks = 0; ks < 8; ks++) {
        uint32_t ah[4][4], b[2][4];
        #pragma unroll
        for (int mf = 0; mf < 4; mf++)
            LDSM4(ah[mf], aA + (uint32_t)(mf * 16 * PA) * 4 + ks * 32);
        #pragma unroll
        for (int p = 0; p < 2; p++)
            LDSM4(b[p], aB + (uint32_t)(p * 16 * PA) * 4 + ks * 32);
        #pragma unroll
        for (int mf = 0; mf < 4; mf++)
            #pragma unroll
            for (int p = 0; p < 2; p++) {
                MMA(c[mf][p * 2 + 0], ah[mf], b[p][0], b[p][1]);
                MMA(c[mf][p * 2 + 1], ah[mf], b[p][2], b[p][3]);
            }
        if (dual) {
            uint32_t al[4][4];
            #pragma unroll
            for (int mf = 0; mf < 4; mf++)
                LDSM4(al[mf], aA + (uint32_t)SM_AL * 4
                              + (uint32_t)(mf * 16 * PA) * 4 + ks * 32);
            #pragma unroll
            for (int mf = 0; mf < 4; mf++)
                #pragma unroll
                for (int p = 0; p < 2; p++) {
                    MMA(c[mf][p * 2 + 0], al[mf], b[p][0], b[p][1]);
                    MMA(c[mf][p * 2 + 1], al[mf], b[p][2], b[p][3]);
                }
        }
    }
}

// ---------------- stage-1 ----------------
// gy=0: A=Zx (pre-packed fp16) -> TgtY, Hx (1-term, stats 0)
// gy=1: A=Z2 (fp32, split)     -> TgtX, Hy (1-term, stats 1), embed (3-term) -> dout
__global__ __launch_bounds__(256, 2) void k_gemm_s1(
    const float* __restrict__ bon, const float* __restrict__ btg,
    float* __restrict__ dout, int N)
{
    extern __shared__ uint32_t sm[];
    float* bias_s = (float*)(sm + SM_BIAS);
    uint32_t sb = smem_u32(sm);

    int gy = blockIdx.y;
    int row0 = blockIdx.x * 128;
    int tid = threadIdx.x;
    int wid = tid >> 5, lane = tid & 31;
    int g = lane >> 2, tg = lane & 3;
    int warpM = wid & 1, warpN = wid >> 1;

    // fill A
    {
        int m = tid >> 1, half = tid & 1;
        if (gy) {
            const float4* arow = (const float4*)g_AggZ2 + (size_t)(row0 + m) * 32 + half * 16;
            uint32_t* dH = sm + SM_AH + m * PA + half * 32;
            uint32_t* dL = sm + SM_AL + m * PA + half * 32;
            #pragma unroll
            for (int j = 0; j < 16; j++) {
                float4 a = arow[j];
                uint32_t h0, l0, h1, l1;
                hsplit(a.x, a.y, h0, l0);
                hsplit(a.z, a.w, h1, l1);
                dH[2 * j] = h0; dH[2 * j + 1] = h1;
                dL[2 * j] = l0; dL[2 * j + 1] = l1;
            }
        } else {
            // copy 32 u32 (= full half-row of 64 packed half2 split across halves)
            const uint4* srcp = (const uint4*)(g_AggX + (size_t)(row0 + m) * 64 + half * 32);
            uint4* dH4 = (uint4*)(sm + SM_AH + m * PA + half * 32);
            #pragma unroll
            for (int j = 0; j < 8; j++) dH4[j] = srcp[j];
        }
    }

    int nsub = gy ? 3 : 2;
    for (int s = 0; s < nsub; s++) {
        int widx, mode, sidx = 0;
        const float* bias;
        uint32_t* outh = nullptr;
        if (s == 0)      { widx = 0; bias = btg;  outh = gy ? g_TgtX : g_TgtY; mode = 0; }
        else if (s == 1) { widx = 1; bias = g_bc; outh = gy ? g_Hy   : g_Hx;   mode = 1; sidx = gy; }
        else             { widx = 2; bias = bon;  mode = 2; }
        bool full = (mode == 2);

        __syncthreads();
        {
            const uint4* src = (const uint4*)g_Bh[widx];
            uint32_t bdst = sb + (uint32_t)SM_B * 4;
            for (int i = tid; i < D * PA / 4; i += 256) cpa16(bdst + i * 16, src + i);
            CP_WAIT();
        }
        if (tid < 128) bias_s[tid] = bias[tid];
        __syncthreads();

        float c[4][4][4];
        #pragma unroll
        for (int mf = 0; mf < 4; mf++)
            #pragma unroll
            for (int nf = 0; nf < 4; nf++)
                #pragma unroll
                for (int q = 0; q < 4; q++) c[mf][nf][q] = 0.f;

        mma_pass(sb, wid, lane, c, full);
        if (full) {
            __syncthreads();
            const uint4* src = (const uint4*)g_Bl[widx];
            uint32_t bdst = sb + (uint32_t)SM_B * 4;
            for (int i = tid; i < D * PA / 4; i += 256) cpa16(bdst + i * 16, src + i);
            CP_WAIT();
            __syncthreads();
            mma_pass(sb, wid, lane, c, false);
        }

        // epilogue
        float ls[8], lq[8];
        #pragma unroll
        for (int i = 0; i < 8; i++) { ls[i] = 0.f; lq[i] = 0.f; }

        #pragma unroll
        for (int mf = 0; mf < 4; mf++) {
            #pragma unroll
            for (int part = 0; part < 2; part++) {
                int n = row0 + warpM * 64 + mf * 16 + g + part * 8;
                #pragma unroll
                for (int nf = 0; nf < 4; nf++) {
                    int col = warpN * 32 + nf * 8 + 2 * tg;
                    float v0 = c[mf][nf][part * 2]     + bias_s[col];
                    float v1 = c[mf][nf][part * 2 + 1] + bias_s[col + 1];
                    if (mode == 2) {
                        if (n < N) {
                            float2 s2 = *(const float2*)(g_S2 + (size_t)n * D + col);
                            *(float2*)(dout + (size_t)n * D + col) =
                                make_float2(v0 + s2.x, v1 + s2.y);
                        }
                    } else {
                        outh[(size_t)n * 64 + (col >> 1)] = hpack(v0, v1);
                        if (mode == 1 && n < N) {
                            ls[nf * 2]     += v0; lq[nf * 2]     += v0 * v0;
                            ls[nf * 2 + 1] += v1; lq[nf * 2 + 1] += v1 * v1;
                        }
                    }
                }
            }
        }
        if (mode == 1) {
            #pragma unroll
            for (int i = 0; i < 8; i++) {
                #pragma unroll
                for (int off = 4; off < 32; off <<= 1) {
                    ls[i] += __shfl_xor_sync(0xffffffffu, ls[i], off);
                    lq[i] += __shfl_xor_sync(0xffffffffu, lq[i], off);
                }
            }
            if (g == 0) {
                #pragma unroll
                for (int nf = 0; nf < 4; nf++) {
                    #pragma unroll
                    for (int j = 0; j < 2; j++) {
                        int col = warpN * 32 + nf * 8 + 2 * tg + j;
                        atomicAdd(&g_colsum[sidx][col], ls[nf * 2 + j]);
                        atomicAdd(&g_colsq[sidx][col],  lq[nf * 2 + j]);
                    }
                }
            }
        }
    }
}

__global__ void k_stats(const float* __restrict__ bng, const float* __restrict__ bnb, int N) {
    int t = threadIdx.x;
    int s = t >> 7, c = t & 127;
    float inv = 1.f / (float)N;
    float mu  = g_colsum[s][c] * inv;
    float var = g_colsq[s][c] * inv - mu * mu;
    float istd = rsqrtf(var + 1e-5f);
    float sc = bng[c] * istd;
    g_bnScale[s][c] = sc;
    g_bnShift[s][c] = bnb[c] - mu * sc;
}

// ---------------- stage-2: predictor (1-term fp16) + cosine loss ----------------
__global__ __launch_bounds__(256, 2) void k_pred_s2(
    const float* __restrict__ b2, const float* __restrict__ prelu_a, int N)
{
    extern __shared__ uint32_t sm[];
    float* bias_s = (float*)(sm + SM_BIAS);
    float* sred   = (float*)(sm + SM_RED);   // psq[128], dot[128], tsq[128]
    uint32_t sb = smem_u32(sm);

    int tag = blockIdx.y;
    int row0 = blockIdx.x * 128;
    int tid = threadIdx.x;
    int wid = tid >> 5, lane = tid & 31;
    int g = lane >> 2, tg = lane & 3;
    int warpM = wid & 1, warpN = wid >> 1;
    const uint32_t* H = tag ? g_Hy : g_Hx;
    const uint32_t* T = tag ? g_TgtY : g_TgtX;
    float slope = prelu_a[0];

    // fill A = PReLU(BN(H)) from packed-half2 H
    {
        int m = tid >> 1, half = tid & 1;
        const uint4* hrow = (const uint4*)(H + (size_t)(row0 + m) * 64 + half * 32);
        const float2* scp = (const float2*)g_bnScale[tag] + half * 32;
        const float2* shp = (const float2*)g_bnShift[tag] + half * 32;
        uint32_t* dH = sm + SM_AH + m * PA + half * 32;
        #pragma unroll
        for (int j = 0; j < 8; j++) {
            uint4 hv = hrow[j];
            uint32_t comps[4] = {hv.x, hv.y, hv.z, hv.w};
            #pragma unroll
            for (int q = 0; q < 4; q++) {
                float2 f  = hunpack(comps[q]);
                float2 sc = scp[j * 4 + q];
                float2 sh = shp[j * 4 + q];
                float a0 = fmaf(f.x, sc.x, sh.x);
                float a1 = fmaf(f.y, sc.y, sh.y);
                a0 = a0 > 0.f ? a0 : slope * a0;
                a1 = a1 > 0.f ? a1 : slope * a1;
                dH[j * 4 + q] = hpack(a0, a1);
            }
        }
    }
    {
        const uint4* src = (const uint4*)g_Bh[3];
        uint32_t bdst = sb + (uint32_t)SM_B * 4;
        for (int i = tid; i < D * PA / 4; i += 256) cpa16(bdst + i * 16, src + i);
        CP_WAIT();
    }
    if (tid < 128) {
        bias_s[tid] = b2[tid];
        sred[tid] = 0.f; sred[128 + tid] = 0.f; sred[256 + tid] = 0.f;
    }
    __syncthreads();

    float c[4][4][4];
    #pragma unroll
    for (int mf = 0; mf < 4; mf++)
        #pragma unroll
        for (int nf = 0; nf < 4; nf++)
            #pragma unroll
            for (int q = 0; q < 4; q++) c[mf][nf][q] = 0.f;

    mma_pass(sb, wid, lane, c, false);   // 1-term fp16

    #pragma unroll
    for (int mf = 0; mf < 4; mf++) {
        #pragma unroll
        for (int part = 0; part < 2; part++) {
            int r = warpM * 64 + mf * 16 + g + part * 8;
            int n = row0 + r;
            float psq = 0.f, dot = 0.f, tsq = 0.f;
            #pragma unroll
            for (int nf = 0; nf < 4; nf++) {
                int col = warpN * 32 + nf * 8 + 2 * tg;
                float v0 = c[mf][nf][part * 2]     + bias_s[col];
                float v1 = c[mf][nf][part * 2 + 1] + bias_s[col + 1];
                float2 t2 = hunpack(T[(size_t)n * 64 + (col >> 1)]);
                psq = fmaf(v0, v0, fmaf(v1, v1, psq));
                dot = fmaf(v0, t2.x, fmaf(v1, t2.y, dot));
                tsq = fmaf(t2.x, t2.x, fmaf(t2.y, t2.y, tsq));
            }
            atomicAdd(&sred[r], psq);
            atomicAdd(&sred[128 + r], dot);
            atomicAdd(&sred[256 + r], tsq);
        }
    }
    __syncthreads();

    if (tid < 128) {
        int n = row0 + tid;
        float lossv = 0.f;
        if (n < N) {
            float denom = fmaxf(sqrtf(sred[tid]), 1e-12f) *
                          fmaxf(sqrtf(sred[256 + tid]), 1e-12f);
            lossv = 2.f - 2.f * sred[128 + tid] / denom;
        }
        #pragma unroll
        for (int o = 16; o; o >>= 1) lossv += __shfl_xor_sync(0xffffffffu, lossv, o);
        if (lane == 0) atomicAdd(&g_lossSum, (double)lossv);
    }
}

__global__ void k_final(float* __restrict__ dout, int N) {
    dout[(size_t)N * D] = (float)(g_lossSum / (double)N);
}

// ---------------- launch ----------------
extern "C" void kernel_launch(void* const* d_in, const int* in_sizes, int n_in,
                              void* d_out, int out_size) {
    const float* x    = (const float*)d_in[0];
    const float* perb = (const float*)d_in[1];
    const int*   erow = (const int*)d_in[2];
    const int*   ecol = (const int*)d_in[3];
    const float* ew   = (const float*)d_in[4];
    const float* Won  = (const float*)d_in[5];
    const float* bon  = (const float*)d_in[6];
    const float* Wtg  = (const float*)d_in[7];
    const float* btg  = (const float*)d_in[8];
    const float* W1   = (const float*)d_in[9];
    const float* b1   = (const float*)d_in[10];
    const float* bng  = (const float*)d_in[11];
    const float* bnb  = (const float*)d_in[12];
    const float* pa   = (const float*)d_in[13];
    const float* W2   = (const float*)d_in[14];
    const float* b2   = (const float*)d_in[15];
    float* out = (float*)d_out;

    int N = in_sizes[0] / D;
    int E = in_sizes[2];
    if (N > NPAD) N = NPAD;
    if (E > EMAX) E = EMAX;

    cudaFuncSetAttribute(k_gemm_s1, cudaFuncAttributeMaxDynamicSharedMemorySize, DYN_SMEM);
    cudaFuncSetAttribute(k_pred_s2, cudaFuncAttributeMaxDynamicSharedMemorySize, DYN_SMEM);

    const int PREPB = NPAD * 32 / 256;       // 6256
    int EB = (E + 255) / 256;

    k_prep_count<<<PREPB + EB, 256>>>(x, perb, erow, N, E, PREPB);
    k_scan<<<1, 1024>>>();
    k_scatter_combine<<<EB + D + 1, 256>>>(erow, ecol, ew, Won, bon, W1, b1, E, EB);
    k_agg_wprep<<<16 + NPAD / 8, 256>>>(x, Wtg, Won, W2);
    dim3 g1(NBLK, 2);
    k_gemm_s1<<<g1, 256, DYN_SMEM>>>(bon, btg, out, N);
    k_stats<<<1, 256>>>(bng, bnb, N);
    dim3 g2(NBLK, 2);
    k_pred_s2<<<g2, 256, DYN_SMEM>>>(b2, pa, N);
    k_final<<<1, 1>>>(out, N);
}

// round 11
// speedup vs baseline: 2.7954x; 1.0238x over previous
#include <cuda_runtime.h>
#include <cuda_fp16.h>
#include <cstdint>

#define D 128
#define NPAD 50048          // 391 * 128
#define NBLK 391
#define PA 68               // packed (fp16x2) row pitch in u32: 64 data + 4 pad
#define EMAX 1000000

// ---------------- device scratch ----------------
__device__ float g_S2[(size_t)NPAD * D];                      // x2 = x + perb (fp32)
__device__ __align__(16) uint32_t g_AggX[(size_t)NPAD * 64];  // Zx, packed half2
__device__ __align__(16) uint32_t g_AggZ2h[(size_t)NPAD * 64];// Z2 hi, packed half2
__device__ __align__(16) uint32_t g_AggZ2l[(size_t)NPAD * 64];// Z2 lo residual
__device__ __align__(16) uint32_t g_TgtX[(size_t)NPAD * 64];  // packed half2
__device__ __align__(16) uint32_t g_TgtY[(size_t)NPAD * 64];
__device__ __align__(16) uint32_t g_Hx[(size_t)NPAD * 64];
__device__ __align__(16) uint32_t g_Hy[(size_t)NPAD * 64];
__device__ float g_Wc[D * D];
__device__ float g_bc[D];
__device__ __align__(16) uint32_t g_Bh[4][D * PA];  // Wtg, Wc, Won, W2 (fp16 hi)
__device__ __align__(16) uint32_t g_Bl[4][D * PA];  // fp16 lo residual
__device__ float g_colsum[2][D];
__device__ float g_colsq[2][D];
__device__ double g_lossSum;
// CSR (g_cur zero at load; every launch restores it to zero)
__device__ int   g_off[NPAD + 1];
__device__ int   g_cur[NPAD];
__device__ int   g_ecol2[EMAX];
__device__ float g_ew2[EMAX];

// ---------------- helpers ----------------
__device__ __forceinline__ uint32_t smem_u32(const void* p) {
    uint32_t a;
    asm("{ .reg .u64 t; cvta.to.shared.u64 t, %1; cvt.u32.u64 %0, t; }" : "=r"(a) : "l"(p));
    return a;
}
__device__ __forceinline__ void cpa16(uint32_t s, const void* g) {
    asm volatile("cp.async.ca.shared.global [%0], [%1], 16;" :: "r"(s), "l"(g));
}
#define CP_WAIT() \
    asm volatile("cp.async.commit_group;\n\tcp.async.wait_group 0;" ::: "memory")

__device__ __forceinline__ void hsplit(float x, float y, uint32_t& h, uint32_t& l) {
    __half2 hh = __floats2half2_rn(x, y);
    float2 hf = __half22float2(hh);
    __half2 ll = __floats2half2_rn(x - hf.x, y - hf.y);
    h = *reinterpret_cast<uint32_t*>(&hh);
    l = *reinterpret_cast<uint32_t*>(&ll);
}
__device__ __forceinline__ uint32_t hpack(float x, float y) {
    __half2 hh = __floats2half2_rn(x, y);
    return *reinterpret_cast<uint32_t*>(&hh);
}
__device__ __forceinline__ float2 hunpack(uint32_t v) {
    return __half22float2(*reinterpret_cast<__half2*>(&v));
}

// fp16 HMMA, fp32 accumulate (sm_80+ PTX)
#define MMA(cc, a, b0v, b1v) \
    asm("mma.sync.aligned.m16n8k16.row.col.f32.f16.f16.f32 " \
        "{%0,%1,%2,%3},{%4,%5,%6,%7},{%8,%9},{%0,%1,%2,%3};" \
        : "+f"((cc)[0]), "+f"((cc)[1]), "+f"((cc)[2]), "+f"((cc)[3]) \
        : "r"((a)[0]), "r"((a)[1]), "r"((a)[2]), "r"((a)[3]), \
          "r"(b0v), "r"(b1v))

#define LDSM4(r, addr) \
    asm volatile("ldmatrix.sync.aligned.m8n8.x4.shared.b16 {%0,%1,%2,%3}, [%4];" \
        : "=r"((r)[0]), "=r"((r)[1]), "=r"((r)[2]), "=r"((r)[3]) : "r"(addr))

// smem layout (u32 offsets): Ah, Al, single B, double bias, reduction, bn affine
#define SM_AH 0
#define SM_AL (D * PA)
#define SM_B  (2 * D * PA)
#define SM_BIAS (3 * D * PA)          // 2 x 128 floats (double-buffered)
#define SM_RED (SM_BIAS + 256)        // psq/dot/tsq  3 x 128
#define SM_BN  (SM_RED + 384)         // bn scale[128], shift[128]
#define DYN_SMEM ((SM_BN + 256) * 4)  // 108032 B -> 2 CTAs/SM

// ---------------- fused: prep (x2 only) || count ----------------
__global__ void k_prep_count(const float* __restrict__ x, const float* __restrict__ perb,
                             const int* __restrict__ erow, int N, int E, int PREPB) {
    int b = blockIdx.x;
    int t = threadIdx.x;
    if (b < PREPB) {
        int idx = b * 256 + t;                 // float4 index into g_S2
        if (idx >= NPAD * 32) return;
        int n = idx >> 5, k = idx & 31;
        float4 v = make_float4(0.f, 0.f, 0.f, 0.f);
        if (n < N) {
            float4 a = ((const float4*)x)[(size_t)n * 32 + k];
            float4 p = ((const float4*)perb)[(size_t)n * 32 + k];
            v = make_float4(a.x + p.x, a.y + p.y, a.z + p.z, a.w + p.w);
        }
        ((float4*)g_S2)[idx] = v;
    } else {
        int e = (b - PREPB) * 256 + t;
        if (e < E) atomicAdd(&g_cur[__ldg(erow + e)], 1);
    }
}

// single-block exclusive scan over g_cur -> g_off; reset g_cur for scatter
__global__ void k_scan() {
    __shared__ int part[1024];
    const int CH = (NPAD + 1023) / 1024;   // 49
    int t = threadIdx.x;
    int base = t * CH;
    int s = 0;
    for (int i = 0; i < CH; i++) {
        int idx = base + i;
        if (idx < NPAD) s += g_cur[idx];
    }
    part[t] = s;
    __syncthreads();
    for (int off = 1; off < 1024; off <<= 1) {
        int u = (t >= off) ? part[t - off] : 0;
        __syncthreads();
        part[t] += u;
        __syncthreads();
    }
    int run = part[t] - s;
    for (int i = 0; i < CH; i++) {
        int idx = base + i;
        if (idx < NPAD) {
            g_off[idx] = run;
            run += g_cur[idx];
            g_cur[idx] = 0;
        }
    }
    if (t == 1023) g_off[NPAD] = part[1023];
}

// ---------------- fused: scatter || combine (Wc = Won@W1, bc = bon@W1+b1) ------
__global__ void k_scatter_combine(
    const int* __restrict__ erow, const int* __restrict__ ecol,
    const float* __restrict__ ew,
    const float* __restrict__ Won, const float* __restrict__ bon,
    const float* __restrict__ W1,  const float* __restrict__ b1,
    int E, int SCATB)
{
    int b = blockIdx.x;
    int t = threadIdx.x;
    if (b < SCATB) {
        int e = b * 256 + t;
        if (e >= E) return;
        int r = __ldg(erow + e);
        int pos = g_off[r] + atomicAdd(&g_cur[r], 1);
        g_ecol2[pos] = __ldg(ecol + e);
        g_ew2[pos]   = __ldg(ew + e);
    } else {
        __shared__ float row[D];
        int i = b - SCATB;           // 0..128
        int j = t;
        if (j < D) row[j] = (i < D) ? Won[i * D + j] : bon[j];
        __syncthreads();
        if (j < D) {
            float acc = (i < D) ? 0.f : b1[j];
            #pragma unroll 8
            for (int k = 0; k < D; k++) acc = fmaf(row[k], W1[k * D + j], acc);
            if (i < D) g_Wc[i * D + j] = acc;
            else       g_bc[j] = acc;
        }
    }
}

// ---------------- fused: wprep (16 blocks) || CSR aggregation ----------------
// lanes 0-15:  Zx = sum w*x[col]   -> g_AggX   (packed half2)
// lanes 16-31: Z2 = sum w*x2[col]  -> g_AggZ2h/g_AggZ2l (hi/lo packed half2)
__global__ __launch_bounds__(256) void k_agg_wprep(
    const float* __restrict__ x,
    const float* __restrict__ Wtg, const float* __restrict__ Won,
    const float* __restrict__ W2) {
    int b = blockIdx.x;
    int t = threadIdx.x;
    if (b < 16) {
        if (b == 0 && t >= 128) {
            int c = t - 128;
            g_colsum[0][c] = 0.f; g_colsum[1][c] = 0.f;
            g_colsq[0][c]  = 0.f; g_colsq[1][c]  = 0.f;
            if (c == 0) g_lossSum = 0.0;
        }
        int w = b >> 2, quad = b & 3;
        if (t < 64) {
            const float* W = (w == 0) ? Wtg : (w == 1) ? g_Wc : (w == 2) ? Won : W2;
            int n = quad * 32 + (t >> 1), half = t & 1;
            #pragma unroll
            for (int j = 0; j < 32; j++) {
                int k = half * 64 + 2 * j;
                float v0 = W[(size_t)k * D + n];
                float v1 = W[(size_t)(k + 1) * D + n];
                uint32_t h, l;
                hsplit(v0, v1, h, l);
                g_Bh[w][n * PA + half * 32 + j] = h;
                g_Bl[w][n * PA + half * 32 + j] = l;
            }
        }
        return;
    }
    int wid = t >> 5, lane = t & 31;
    int n = (b - 16) * 8 + wid;
    int start = g_off[n];
    int deg = g_off[n + 1] - start;
    if (lane == 0) g_cur[n] = 0;          // restore invariant for next launch
    const float4* base = (lane < 16) ? (const float4*)x : (const float4*)g_S2;
    int loff = (lane & 15) * 2;
    float4 a0 = make_float4(0.f, 0.f, 0.f, 0.f), a1 = a0;
    for (int bb = 0; bb < deg; bb += 32) {
        int j = bb + lane;
        int cc = 0; float ww = 0.f;
        if (j < deg) { cc = g_ecol2[start + j]; ww = g_ew2[start + j]; }
        int cnt = min(32, deg - bb);
        int i = 0;
        for (; i + 4 <= cnt; i += 4) {
            int   c0 = __shfl_sync(0xffffffffu, cc, i);
            int   c1 = __shfl_sync(0xffffffffu, cc, i + 1);
            int   c2 = __shfl_sync(0xffffffffu, cc, i + 2);
            int   c3 = __shfl_sync(0xffffffffu, cc, i + 3);
            float w0 = __shfl_sync(0xffffffffu, ww, i);
            float w1 = __shfl_sync(0xffffffffu, ww, i + 1);
            float w2 = __shfl_sync(0xffffffffu, ww, i + 2);
            float w3 = __shfl_sync(0xffffffffu, ww, i + 3);
            const float4* p0 = base + (size_t)c0 * 32 + loff;
            const float4* p1 = base + (size_t)c1 * 32 + loff;
            const float4* p2 = base + (size_t)c2 * 32 + loff;
            const float4* p3 = base + (size_t)c3 * 32 + loff;
            float4 v00 = __ldg(p0), v01 = __ldg(p0 + 1);
            float4 v10 = __ldg(p1), v11 = __ldg(p1 + 1);
            float4 v20 = __ldg(p2), v21 = __ldg(p2 + 1);
            float4 v30 = __ldg(p3), v31 = __ldg(p3 + 1);
            a0.x = fmaf(w0, v00.x, a0.x); a0.y = fmaf(w0, v00.y, a0.y);
            a0.z = fmaf(w0, v00.z, a0.z); a0.w = fmaf(w0, v00.w, a0.w);
            a1.x = fmaf(w0, v01.x, a1.x); a1.y = fmaf(w0, v01.y, a1.y);
            a1.z = fmaf(w0, v01.z, a1.z); a1.w = fmaf(w0, v01.w, a1.w);
            a0.x = fmaf(w1, v10.x, a0.x); a0.y = fmaf(w1, v10.y, a0.y);
            a0.z = fmaf(w1, v10.z, a0.z); a0.w = fmaf(w1, v10.w, a0.w);
            a1.x = fmaf(w1, v11.x, a1.x); a1.y = fmaf(w1, v11.y, a1.y);
            a1.z = fmaf(w1, v11.z, a1.z); a1.w = fmaf(w1, v11.w, a1.w);
            a0.x = fmaf(w2, v20.x, a0.x); a0.y = fmaf(w2, v20.y, a0.y);
            a0.z = fmaf(w2, v20.z, a0.z); a0.w = fmaf(w2, v20.w, a0.w);
            a1.x = fmaf(w2, v21.x, a1.x); a1.y = fmaf(w2, v21.y, a1.y);
            a1.z = fmaf(w2, v21.z, a1.z); a1.w = fmaf(w2, v21.w, a1.w);
            a0.x = fmaf(w3, v30.x, a0.x); a0.y = fmaf(w3, v30.y, a0.y);
            a0.z = fmaf(w3, v30.z, a0.z); a0.w = fmaf(w3, v30.w, a0.w);
            a1.x = fmaf(w3, v31.x, a1.x); a1.y = fmaf(w3, v31.y, a1.y);
            a1.z = fmaf(w3, v31.z, a1.z); a1.w = fmaf(w3, v31.w, a1.w);
        }
        for (; i < cnt; i++) {
            int cs = __shfl_sync(0xffffffffu, cc, i);
            float ws = __shfl_sync(0xffffffffu, ww, i);
            const float4* src = base + (size_t)cs * 32 + loff;
            float4 v = __ldg(src);
            float4 u = __ldg(src + 1);
            a0.x = fmaf(ws, v.x, a0.x); a0.y = fmaf(ws, v.y, a0.y);
            a0.z = fmaf(ws, v.z, a0.z); a0.w = fmaf(ws, v.w, a0.w);
            a1.x = fmaf(ws, u.x, a1.x); a1.y = fmaf(ws, u.y, a1.y);
            a1.z = fmaf(ws, u.z, a1.z); a1.w = fmaf(ws, u.w, a1.w);
        }
    }
    if (lane < 16) {
        uint4 pk;
        pk.x = hpack(a0.x, a0.y);
        pk.y = hpack(a0.z, a0.w);
        pk.z = hpack(a1.x, a1.y);
        pk.w = hpack(a1.z, a1.w);
        *(uint4*)(g_AggX + (size_t)n * 64 + lane * 4) = pk;
    } else {
        uint4 hi, lo;
        hsplit(a0.x, a0.y, hi.x, lo.x);
        hsplit(a0.z, a0.w, hi.y, lo.y);
        hsplit(a1.x, a1.y, hi.z, lo.z);
        hsplit(a1.z, a1.w, hi.w, lo.w);
        *(uint4*)(g_AggZ2h + (size_t)n * 64 + (lane & 15) * 4) = hi;
        *(uint4*)(g_AggZ2l + (size_t)n * 64 + (lane & 15) * 4) = lo;
    }
}

// ---------------- MMA pass via ldmatrix ----------------
__device__ __forceinline__ void mma_pass(uint32_t sb, int wid, int lane,
                                         float c[4][4][4], bool dual) {
    int warpM = wid & 1, warpN = wid >> 1;
    int arow = warpM * 64 + (lane & 15);
    uint32_t aA = sb + (uint32_t)(arow * PA + (lane >> 4) * 4) * 4;
    int brow = warpN * 32 + (lane & 7) + ((lane >> 4) & 1) * 8;
    uint32_t aB = sb + (uint32_t)(brow * PA + ((lane >> 3) & 1) * 4) * 4
                + (uint32_t)SM_B * 4;

    #pragma unroll
    for (int ks = 0; ks < 8; ks++) {
        uint32_t ah[4][4], b[2][4];
        #pragma unroll
        for (int mf = 0; mf < 4; mf++)
            LDSM4(ah[mf], aA + (uint32_t)(mf * 16 * PA) * 4 + ks * 32);
        #pragma unroll
        for (int p = 0; p < 2; p++)
            LDSM4(b[p], aB + (uint32_t)(p * 16 * PA) * 4 + ks * 32);
        #pragma unroll
        for (int mf = 0; mf < 4; mf++)
            #pragma unroll
            for (int p = 0; p < 2; p++) {
                MMA(c[mf][p * 2 + 0], ah[mf], b[p][0], b[p][1]);
                MMA(c[mf][p * 2 + 1], ah[mf], b[p][2], b[p][3]);
            }
        if (dual) {
            uint32_t al[4][4];
            #pragma unroll
            for (int mf = 0; mf < 4; mf++)
                LDSM4(al[mf], aA + (uint32_t)SM_AL * 4
                              + (uint32_t)(mf * 16 * PA) * 4 + ks * 32);
            #pragma unroll
            for (int mf = 0; mf < 4; mf++)
                #pragma unroll
                for (int p = 0; p < 2; p++) {
                    MMA(c[mf][p * 2 + 0], al[mf], b[p][0], b[p][1]);
                    MMA(c[mf][p * 2 + 1], al[mf], b[p][2], b[p][3]);
                }
        }
    }
}

__device__ __forceinline__ void copyB(uint32_t sb, int tid, const uint32_t* src) {
    uint32_t bdst = sb + (uint32_t)SM_B * 4;
    const uint4* s4 = (const uint4*)src;
    for (int i = tid; i < D * PA / 4; i += 256) cpa16(bdst + i * 16, s4 + i);
}

// ---------------- stage-1 ----------------
// gy=0: A=Zx (pre-packed fp16)  -> TgtY (s0), Hx (s1, stats 0)
// gy=1: A=Z2 (pre-split hi/lo)  -> TgtX (s0), Hy (s1, stats 1), embed (s2) -> dout
__global__ __launch_bounds__(256, 2) void k_gemm_s1(
    const float* __restrict__ bon, const float* __restrict__ btg,
    float* __restrict__ dout, int N)
{
    extern __shared__ uint32_t sm[];
    float (*bias2)[128] = (float(*)[128])(sm + SM_BIAS);
    uint32_t sb = smem_u32(sm);

    int gy = blockIdx.y;
    int row0 = blockIdx.x * 128;
    int tid = threadIdx.x;
    int wid = tid >> 5, lane = tid & 31;
    int g = lane >> 2, tg = lane & 3;
    int warpM = wid & 1, warpN = wid >> 1;

    // async A copies (pre-packed/pre-split in global)
    {
        int m = tid >> 1, half = tid & 1;
        uint32_t dA = sb + (uint32_t)(SM_AH + m * PA + half * 32) * 4;
        if (gy) {
            const uint4* sh = (const uint4*)(g_AggZ2h + (size_t)(row0 + m) * 64 + half * 32);
            const uint4* sl = (const uint4*)(g_AggZ2l + (size_t)(row0 + m) * 64 + half * 32);
            uint32_t dL = sb + (uint32_t)(SM_AL + m * PA + half * 32) * 4;
            #pragma unroll
            for (int j = 0; j < 8; j++) {
                cpa16(dA + j * 16, sh + j);
                cpa16(dL + j * 16, sl + j);
            }
        } else {
            const uint4* sh = (const uint4*)(g_AggX + (size_t)(row0 + m) * 64 + half * 32);
            #pragma unroll
            for (int j = 0; j < 8; j++) cpa16(dA + j * 16, sh + j);
        }
    }
    copyB(sb, tid, g_Bh[0]);                 // first B = Wtg
    if (tid < 128) bias2[0][tid] = btg[tid];
    CP_WAIT();
    __syncthreads();

    int nsub = gy ? 3 : 2;
    for (int s = 0; s < nsub; s++) {
        int mode;                             // 0=Tgt, 1=H+stats, 2=embed
        uint32_t* outh = nullptr;
        int sidx = gy;
        if (s == 0)      { outh = gy ? g_TgtX : g_TgtY; mode = 0; }
        else if (s == 1) { outh = gy ? g_Hy   : g_Hx;   mode = 1; }
        else             { mode = 2; }
        bool full = (mode == 2);

        float c[4][4][4];
        #pragma unroll
        for (int mf = 0; mf < 4; mf++)
            #pragma unroll
            for (int nf = 0; nf < 4; nf++)
                #pragma unroll
                for (int q = 0; q < 4; q++) c[mf][nf][q] = 0.f;

        mma_pass(sb, wid, lane, c, full);     // loss: Ah@Bh; embed: (Ah+Al)@Bh
        if (full) {
            __syncthreads();
            copyB(sb, tid, g_Bl[2]);
            CP_WAIT();
            __syncthreads();
            mma_pass(sb, wid, lane, c, false);   // + Ah@Bl
        }

        __syncthreads();                      // all warps done reading B(s)
        if (s + 1 < nsub) {                   // prefetch next B under epilogue
            copyB(sb, tid, g_Bh[s + 1]);
            if (tid < 128)
                bias2[(s + 1) & 1][tid] = (s + 1 == 1) ? g_bc[tid] : bon[tid];
        }
        const float* bias_s = bias2[s & 1];

        // epilogue
        float ls[8], lq[8];
        #pragma unroll
        for (int i = 0; i < 8; i++) { ls[i] = 0.f; lq[i] = 0.f; }

        #pragma unroll
        for (int mf = 0; mf < 4; mf++) {
            #pragma unroll
            for (int part = 0; part < 2; part++) {
                int n = row0 + warpM * 64 + mf * 16 + g + part * 8;
                #pragma unroll
                for (int nf = 0; nf < 4; nf++) {
                    int col = warpN * 32 + nf * 8 + 2 * tg;
                    float v0 = c[mf][nf][part * 2]     + bias_s[col];
                    float v1 = c[mf][nf][part * 2 + 1] + bias_s[col + 1];
                    if (mode == 2) {
                        if (n < N) {
                            float2 s2 = *(const float2*)(g_S2 + (size_t)n * D + col);
                            *(float2*)(dout + (size_t)n * D + col) =
                                make_float2(v0 + s2.x, v1 + s2.y);
                        }
                    } else {
                        outh[(size_t)n * 64 + (col >> 1)] = hpack(v0, v1);
                        if (mode == 1 && n < N) {
                            ls[nf * 2]     += v0; lq[nf * 2]     += v0 * v0;
                            ls[nf * 2 + 1] += v1; lq[nf * 2 + 1] += v1 * v1;
                        }
                    }
                }
            }
        }
        if (mode == 1) {
            #pragma unroll
            for (int i = 0; i < 8; i++) {
                #pragma unroll
                for (int off = 4; off < 32; off <<= 1) {
                    ls[i] += __shfl_xor_sync(0xffffffffu, ls[i], off);
                    lq[i] += __shfl_xor_sync(0xffffffffu, lq[i], off);
                }
            }
            if (g == 0) {
                #pragma unroll
                for (int nf = 0; nf < 4; nf++) {
                    #pragma unroll
                    for (int j = 0; j < 2; j++) {
                        int col = warpN * 32 + nf * 8 + 2 * tg + j;
                        atomicAdd(&g_colsum[sidx][col], ls[nf * 2 + j]);
                        atomicAdd(&g_colsq[sidx][col],  lq[nf * 2 + j]);
                    }
                }
            }
        }
        if (s + 1 < nsub) {
            CP_WAIT();
            __syncthreads();
        }
    }
}

// ---------------- stage-2: predictor (1-term fp16) + cosine loss ----------------
// BN affine computed in-CTA from g_colsum/g_colsq (k_stats eliminated).
__global__ __launch_bounds__(256, 2) void k_pred_s2(
    const float* __restrict__ bng, const float* __restrict__ bnb,
    const float* __restrict__ b2, const float* __restrict__ prelu_a, int N)
{
    extern __shared__ uint32_t sm[];
    float* bias_s = (float*)(sm + SM_BIAS);
    float* sred   = (float*)(sm + SM_RED);   // psq[128], dot[128], tsq[128]
    float* bnsc   = (float*)(sm + SM_BN);
    float* bnsh   = bnsc + 128;
    uint32_t sb = smem_u32(sm);

    int tag = blockIdx.y;
    int row0 = blockIdx.x * 128;
    int tid = threadIdx.x;
    int wid = tid >> 5, lane = tid & 31;
    int g = lane >> 2, tg = lane & 3;
    int warpM = wid & 1, warpN = wid >> 1;
    const uint32_t* H = tag ? g_Hy : g_Hx;
    const uint32_t* T = tag ? g_TgtY : g_TgtX;
    float slope = prelu_a[0];

    copyB(sb, tid, g_Bh[3]);                  // W2, async under BN compute
    if (tid < 128) {
        float inv = 1.f / (float)N;
        float mu  = g_colsum[tag][tid] * inv;
        float var = g_colsq[tag][tid] * inv - mu * mu;
        float istd = rsqrtf(var + 1e-5f);
        float sc = bng[tid] * istd;
        bnsc[tid] = sc;
        bnsh[tid] = bnb[tid] - mu * sc;
        bias_s[tid] = b2[tid];
        sred[tid] = 0.f; sred[128 + tid] = 0.f; sred[256 + tid] = 0.f;
    }
    __syncthreads();

    // fill A = PReLU(BN(H)) from packed-half2 H
    {
        int m = tid >> 1, half = tid & 1;
        const uint4* hrow = (const uint4*)(H + (size_t)(row0 + m) * 64 + half * 32);
        const float2* scp = (const float2*)bnsc + half * 32;
        const float2* shp = (const float2*)bnsh + half * 32;
        uint32_t* dH = sm + SM_AH + m * PA + half * 32;
        #pragma unroll
        for (int j = 0; j < 8; j++) {
            uint4 hv = hrow[j];
            uint32_t comps[4] = {hv.x, hv.y, hv.z, hv.w};
            #pragma unroll
            for (int q = 0; q < 4; q++) {
                float2 f  = hunpack(comps[q]);
                float2 sc = scp[j * 4 + q];
                float2 sh = shp[j * 4 + q];
                float a0 = fmaf(f.x, sc.x, sh.x);
                float a1 = fmaf(f.y, sc.y, sh.y);
                a0 = a0 > 0.f ? a0 : slope * a0;
                a1 = a1 > 0.f ? a1 : slope * a1;
                dH[j * 4 + q] = hpack(a0, a1);
            }
        }
    }
    CP_WAIT();
    __syncthreads();

    float c[4][4][4];
    #pragma unroll
    for (int mf = 0; mf < 4; mf++)
        #pragma unroll
        for (int nf = 0; nf < 4; nf++)
            #pragma unroll
            for (int q = 0; q < 4; q++) c[mf][nf][q] = 0.f;

    mma_pass(sb, wid, lane, c, false);   // 1-term fp16

    #pragma unroll
    for (int mf = 0; mf < 4; mf++) {
        #pragma unroll
        for (int part = 0; part < 2; part++) {
            int r = warpM * 64 + mf * 16 + g + part * 8;
            int n = row0 + r;
            float psq = 0.f, dot = 0.f, tsq = 0.f;
            #pragma unroll
            for (int nf = 0; nf < 4; nf++) {
                int col = warpN * 32 + nf * 8 + 2 * tg;
                float v0 = c[mf][nf][part * 2]     + bias_s[col];
                float v1 = c[mf][nf][part * 2 + 1] + bias_s[col + 1];
                float2 t2 = hunpack(T[(size_t)n * 64 + (col >> 1)]);
                psq = fmaf(v0, v0, fmaf(v1, v1, psq));
                dot = fmaf(v0, t2.x, fmaf(v1, t2.y, dot));
                tsq = fmaf(t2.x, t2.x, fmaf(t2.y, t2.y, tsq));
            }
            atomicAdd(&sred[r], psq);
            atomicAdd(&sred[128 + r], dot);
            atomicAdd(&sred[256 + r], tsq);
        }
    }
    __syncthreads();

    if (tid < 128) {
        int n = row0 + tid;
        float lossv = 0.f;
        if (n < N) {
            float denom = fmaxf(sqrtf(sred[tid]), 1e-12f) *
                          fmaxf(sqrtf(sred[256 + tid]), 1e-12f);
            lossv = 2.f - 2.f * sred[128 + tid] / denom;
        }
        #pragma unroll
        for (int o = 16; o; o >>= 1) lossv += __shfl_xor_sync(0xffffffffu, lossv, o);
        if (lane == 0) atomicAdd(&g_lossSum, (double)lossv);
    }
}

__global__ void k_final(float* __restrict__ dout, int N) {
    dout[(size_t)N * D] = (float)(g_lossSum / (double)N);
}

// ---------------- launch ----------------
extern "C" void kernel_launch(void* const* d_in, const int* in_sizes, int n_in,
                              void* d_out, int out_size) {
    const float* x    = (const float*)d_in[0];
    const float* perb = (const float*)d_in[1];
    const int*   erow = (const int*)d_in[2];
    const int*   ecol = (const int*)d_in[3];
    const float* ew   = (const float*)d_in[4];
    const float* Won  = (const float*)d_in[5];
    const float* bon  = (const float*)d_in[6];
    const float* Wtg  = (const float*)d_in[7];
    const float* btg  = (const float*)d_in[8];
    const float* W1   = (const float*)d_in[9];
    const float* b1   = (const float*)d_in[10];
    const float* bng  = (const float*)d_in[11];
    const float* bnb  = (const float*)d_in[12];
    const float* pa   = (const float*)d_in[13];
    const float* W2   = (const float*)d_in[14];
    const float* b2   = (const float*)d_in[15];
    float* out = (float*)d_out;

    int N = in_sizes[0] / D;
    int E = in_sizes[2];
    if (N > NPAD) N = NPAD;
    if (E > EMAX) E = EMAX;

    cudaFuncSetAttribute(k_gemm_s1, cudaFuncAttributeMaxDynamicSharedMemorySize, DYN_SMEM);
    cudaFuncSetAttribute(k_pred_s2, cudaFuncAttributeMaxDynamicSharedMemorySize, DYN_SMEM);

    const int PREPB = NPAD * 32 / 256;       // 6256
    int EB = (E + 255) / 256;

    k_prep_count<<<PREPB + EB, 256>>>(x, perb, erow, N, E, PREPB);
    k_scan<<<1, 1024>>>();
    k_scatter_combine<<<EB + D + 1, 256>>>(erow, ecol, ew, Won, bon, W1, b1, E, EB);
    k_agg_wprep<<<16 + NPAD / 8, 256>>>(x, Wtg, Won, W2);
    dim3 g1(NBLK, 2);
    k_gemm_s1<<<g1, 256, DYN_SMEM>>>(bon, btg, out, N);
    dim3 g2(NBLK, 2);
    k_pred_s2<<<g2, 256, DYN_SMEM>>>(bng, bnb, b2, pa, N);
    k_final<<<1, 1>>>(out, N);
}